// round 4
// baseline (speedup 1.0000x reference)
#include <cuda_runtime.h>
#include <cstdint>
#include <cstddef>

// ---------------- problem constants ----------------
#define BB    2
#define NSEQ  4096
#define DMOD  1024
#define HH    16
#define HKV   4
#define DHD   64
#define MROWS (BB*NSEQ)          // 8192
#define NBK   32
#define BUCK  128

// ---------------- scratch layout (floats) ----------------
#define OFF_ZFULL 0ull                          // 8192*2048
#define OFF_ZM    (OFF_ZFULL + 16777216ull)     // 8192*1024
#define OFF_Q     (OFF_ZM    + 8388608ull)      // 8192*1024
#define OFF_KRAW  (OFF_Q     + 8388608ull)      // 8192*256
#define OFF_KH    (OFF_KRAW  + 2097152ull)      // 8192*256
#define OFF_V     (OFF_KH    + 2097152ull)      // 8192*256
#define OFF_ATT   (OFF_V     + 2097152ull)      // 8192*1024
#define OFF_QWP   (OFF_ATT   + 8388608ull)      // 1024*1024
#define OFF_KWP   (OFF_QWP   + 1048576ull)      // 1024*256
#define OFF_FQ    (OFF_KWP   + 262144ull)       // 1024*1024
#define OFF_FK    (OFF_FQ    + 1048576ull)      // 1024*256
#define OFF_FBASE (OFF_FK    + 262144ull)       // 1024*8
#define OFF_WQ    (OFF_FBASE + 8192ull)         // 64*64
#define OFF_WK    (OFF_WQ    + 4096ull)         // 64*64
#define SCRATCH_TOTAL (OFF_WK + 4096ull)

__device__ __align__(256) float g_scratch[SCRATCH_TOTAL];
__device__ int g_bucket[MROWS];
__device__ int g_order[MROWS];

// =====================================================================
// tf32 tensor-core GEMM v2 (fragment-ordered smem, double buffered).
// C[M,N] = A[M,K] @ B[K,N], fp32 in/out, M%128==0, N%128==0, K%32==0.
// SPLIT=true: 3xtf32 emulated-fp32 (hi/lo split, 3 MMAs per frag pair).
// Block tile 128x128x32, 8 warps (2x4), warp tile 64x32, mma m16n8k8.
//
// smem fragment layout (units: uint32):
//  A: ((kb*8 + mb)*32 + lane)*4 + slot   kb=k/8, mb=m/16,
//     lane = (m%16&7)*4 + (k%8&3), slot = (m%16>>3) + 2*(k%8>>2)
//  B: ((kb*16 + nb)*32 + lane)*2 + khi   nb=n/8,
//     lane = (n%8)*4 + (k%8&3), khi = (k%8)>>2
// Reader: A-frag = one LDS.128, B-frag = one LDS.64, conflict-free.
// =====================================================================
#define ASZ 4096
#define BSZ 4096

__device__ __forceinline__ uint32_t f2tf32(float f) {
    uint32_t r;
    asm("cvt.rna.tf32.f32 %0, %1;" : "=r"(r) : "f"(f));
    return r;
}

__device__ __forceinline__ void mma_tf32(float* c, const uint32_t* a, const uint32_t* b) {
    asm volatile(
        "mma.sync.aligned.m16n8k8.row.col.f32.tf32.tf32.f32 "
        "{%0,%1,%2,%3}, {%4,%5,%6,%7}, {%8,%9}, {%0,%1,%2,%3};"
        : "+f"(c[0]), "+f"(c[1]), "+f"(c[2]), "+f"(c[3])
        : "r"(a[0]), "r"(a[1]), "r"(a[2]), "r"(a[3]), "r"(b[0]), "r"(b[1]));
}

template<bool SPLIT>
__global__ __launch_bounds__(256, 1)
void gemm_tc(const float* __restrict__ A, int lda,
             const float* __restrict__ Bm, int ldb,
             float* __restrict__ C, int ldc, int K)
{
    extern __shared__ uint32_t smu[];
    const int STAGE = SPLIT ? (2 * ASZ + 2 * BSZ) : (ASZ + BSZ);

    const int tid = threadIdx.x;
    const int warp = tid >> 5, lane = tid & 31;
    const int bm = blockIdx.y * 128;
    const int bn = blockIdx.x * 128;

    // loader decomposition (precomputed)
    // A: id = tid + u*256 ; r = id>>3 ; kc = (id&7)<<2
    // B: r = id>>5 ; nc = (id&31)<<2
    int a_r[4], a_sl[4], a_ad[4];   // smem base offset (within A region)
    int b_kb[4], b_ad[4];
#pragma unroll
    for (int u = 0; u < 4; u++) {
        int id = tid + u * 256;
        {   // A
            int r = id >> 3, kc = (id & 7) << 2;
            int mb = r >> 4, rm = r & 15, lq = rm & 7, hi8 = rm >> 3;
            int kb = kc >> 3, khi = (kc & 7) >> 2;
            a_r[u] = r;
            a_sl[u] = kc;           // global k offset within tile
            a_ad[u] = ((kb * 8 + mb) * 32 + lq * 4) * 4 + (hi8 + 2 * khi);
        }
        {   // B
            int r = id >> 5, nc = (id & 31) << 2;
            int kb = r >> 3, lr = r & 3, khi = (r & 7) >> 2;
            int nb = nc >> 3, lql = (nc & 4);
            b_kb[u] = r;
            b_ad[u] = ((kb * 16 + nb) * 32 + lql * 4 + lr) * 2 + khi;
        }
    }

    float acc[4][4][4];
#pragma unroll
    for (int i = 0; i < 4; i++)
#pragma unroll
        for (int j = 0; j < 4; j++)
#pragma unroll
            for (int k = 0; k < 4; k++) acc[i][j][k] = 0.f;

    const int aoff = lane * 4 + (warp >> 2) * 512;   // + kb*1024 + mt*128
    const int boff = lane * 2 + (warp & 3) * 256;    // + kb*1024 + nt*64

    const int nk = K >> 5;
    float4 ra[4], rb[4];

    // prologue: load tile 0
#pragma unroll
    for (int u = 0; u < 4; u++) {
        ra[u] = *(const float4*)(A + (size_t)(bm + a_r[u]) * lda + a_sl[u]);
        rb[u] = *(const float4*)(Bm + (size_t)b_kb[u] * ldb + bn + ((tid + u * 256) & 31) * 4);
    }

    for (int kt = 0; kt < nk; kt++) {
        // STS current regs into stage kt&1
        {
            uint32_t* st = smu + (kt & 1) * STAGE;
            uint32_t* Ah = st;
            uint32_t* Al = st + ASZ;
            uint32_t* Bh = SPLIT ? (st + 2 * ASZ) : (st + ASZ);
            uint32_t* Bl = SPLIT ? (st + 2 * ASZ + BSZ) : nullptr;
#pragma unroll
            for (int u = 0; u < 4; u++) {
                float v[4] = {ra[u].x, ra[u].y, ra[u].z, ra[u].w};
#pragma unroll
                for (int i = 0; i < 4; i++) {
                    uint32_t hi = f2tf32(v[i]);
                    Ah[a_ad[u] + i * 4] = hi;
                    if (SPLIT) {
                        float lo = v[i] - __uint_as_float(hi);
                        Al[a_ad[u] + i * 4] = f2tf32(lo);
                    }
                }
                float w[4] = {rb[u].x, rb[u].y, rb[u].z, rb[u].w};
#pragma unroll
                for (int i = 0; i < 4; i++) {
                    uint32_t hi = f2tf32(w[i]);
                    Bh[b_ad[u] + i * 8] = hi;
                    if (SPLIT) {
                        float lo = w[i] - __uint_as_float(hi);
                        Bl[b_ad[u] + i * 8] = f2tf32(lo);
                    }
                }
            }
        }
        __syncthreads();

        // prefetch next tile
        if (kt + 1 < nk) {
            int kg = (kt + 1) << 5;
#pragma unroll
            for (int u = 0; u < 4; u++) {
                ra[u] = *(const float4*)(A + (size_t)(bm + a_r[u]) * lda + kg + a_sl[u]);
                rb[u] = *(const float4*)(Bm + (size_t)(kg + b_kb[u]) * ldb + bn + ((tid + u * 256) & 31) * 4);
            }
        }

        // compute from stage kt&1
        {
            const uint32_t* st = smu + (kt & 1) * STAGE;
            const uint32_t* Ah = st;
            const uint32_t* Al = st + ASZ;
            const uint32_t* Bh = SPLIT ? (st + 2 * ASZ) : (st + ASZ);
            const uint32_t* Bl = SPLIT ? (st + 2 * ASZ + BSZ) : nullptr;
#pragma unroll
            for (int kb = 0; kb < 4; kb++) {
                uint32_t ah[4][4], bh[4][2];
#pragma unroll
                for (int mt = 0; mt < 4; mt++)
                    *(uint4*)ah[mt] = *(const uint4*)(Ah + kb * 1024 + mt * 128 + aoff);
#pragma unroll
                for (int nt = 0; nt < 4; nt++)
                    *(uint2*)bh[nt] = *(const uint2*)(Bh + kb * 1024 + nt * 64 + boff);
                if (SPLIT) {
                    uint32_t al[4][4], bl[4][2];
#pragma unroll
                    for (int mt = 0; mt < 4; mt++)
                        *(uint4*)al[mt] = *(const uint4*)(Al + kb * 1024 + mt * 128 + aoff);
#pragma unroll
                    for (int nt = 0; nt < 4; nt++)
                        *(uint2*)bl[nt] = *(const uint2*)(Bl + kb * 1024 + nt * 64 + boff);
#pragma unroll
                    for (int mt = 0; mt < 4; mt++)
#pragma unroll
                        for (int nt = 0; nt < 4; nt++) {
                            mma_tf32(acc[mt][nt], al[mt], bh[nt]);
                            mma_tf32(acc[mt][nt], ah[mt], bl[nt]);
                            mma_tf32(acc[mt][nt], ah[mt], bh[nt]);
                        }
                } else {
#pragma unroll
                    for (int mt = 0; mt < 4; mt++)
#pragma unroll
                        for (int nt = 0; nt < 4; nt++)
                            mma_tf32(acc[mt][nt], ah[mt], bh[nt]);
                }
            }
        }
        __syncthreads();
    }

    // epilogue
    const int wm = (warp >> 2) * 64, wn = (warp & 3) * 32;
    const int lq = lane >> 2, lr = lane & 3;
#pragma unroll
    for (int mt = 0; mt < 4; mt++) {
#pragma unroll
        for (int nt = 0; nt < 4; nt++) {
            int row = bm + wm + mt * 16 + lq;
            int col = bn + wn + nt * 8 + 2 * lr;
            *(float2*)(C + (size_t)row * ldc + col) =
                make_float2(acc[mt][nt][0], acc[mt][nt][1]);
            *(float2*)(C + (size_t)(row + 8) * ldc + col) =
                make_float2(acc[mt][nt][2], acc[mt][nt][3]);
        }
    }
}

#define SMEM_TC1 ((ASZ + BSZ) * 2 * 4)
#define SMEM_TC3 ((2*ASZ + 2*BSZ) * 2 * 4)

// =====================================================================
// Weight folds
// =====================================================================
__global__ void fold_small(const float* __restrict__ Aq, const float* __restrict__ Bq,
                           const float* __restrict__ Ak, const float* __restrict__ Bk)
{
    int ij = blockIdx.x * blockDim.x + threadIdx.x;
    int i = ij >> 6, j = ij & 63;
    float sq = 0.f, sk = 0.f;
#pragma unroll
    for (int r = 0; r < 16; r++) {
        sq += Aq[i * 16 + r] * Bq[r * 64 + j];
        sk += Ak[i * 16 + r] * Bk[r * 64 + j];
    }
    g_scratch[OFF_WQ + ij] = sq;
    g_scratch[OFF_WK + ij] = sk;
}

__global__ void fold_qw(const float* __restrict__ qw, const float* __restrict__ kw,
                        const float* __restrict__ rand_gate)
{
    __shared__ float qr[1024];
    __shared__ float kr[256];
    __shared__ float wq_s[4096];
    __shared__ float wk_s[4096];
    int d = blockIdx.x;
    int tid = threadIdx.x;
    for (int i = tid; i < 4096; i += 256) { wq_s[i] = g_scratch[OFF_WQ + i]; wk_s[i] = g_scratch[OFF_WK + i]; }
    for (int i = tid; i < 1024; i += 256) qr[i] = qw[(size_t)d * 1024 + i];
    if (tid < 256) kr[tid] = kw[(size_t)d * 256 + tid];
    __syncthreads();
    for (int c = tid; c < 1024; c += 256) {
        int h = c >> 6, j = c & 63;
        float s = 0.f;
#pragma unroll
        for (int i = 0; i < 64; i++) s += qr[h * 64 + i] * wq_s[i * 64 + j];
        g_scratch[OFF_QWP + (size_t)d * 1024 + c] = s;
    }
    {
        int c = tid;
        int g = c >> 6, j = c & 63;
        float s = 0.f;
#pragma unroll
        for (int i = 0; i < 64; i++) s += kr[g * 64 + i] * wk_s[i * 64 + j];
        g_scratch[OFF_KWP + (size_t)d * 256 + c] = s * tanhf(1.f + rand_gate[j]);
    }
}

// FBASE = GEq @ base_w  ([1024,1024] x [1024,8]); fp32 exact (sign-critical)
__global__ void fold_base(const float* __restrict__ ge_out_w,
                          const float* __restrict__ base_w)
{
    int i = blockIdx.x;
    int tid = threadIdx.x;
    __shared__ float red[256];
    const float* a = ge_out_w + (size_t)i * 2048;
    int h = tid & 7, ck = tid >> 3;
    float p = 0.f;
#pragma unroll
    for (int dd = 0; dd < 32; dd++)
        p += a[ck * 32 + dd] * base_w[(ck * 32 + dd) * 8 + h];
    red[tid] = p;
    __syncthreads();
    if (tid < 8) {
        float s = 0.f;
        for (int c2 = 0; c2 < 32; c2++) s += red[c2 * 8 + tid];
        g_scratch[OFF_FBASE + (size_t)i * 8 + tid] = s;
    }
}

// =====================================================================
// conv + SiLU*SiLU gating (precision-critical -> expf)
// =====================================================================
__global__ void conv_silu(const float* __restrict__ dw_w, const float* __restrict__ dw_b)
{
    int gid = blockIdx.x * 256 + threadIdx.x;
    int d   = gid & 1023;
    int row = gid >> 10;
    int n   = row & (NSEQ - 1);
    const float* zr = g_scratch + OFF_ZFULL + (size_t)row * 2048;
    float z0 = (n > 0)        ? zr[-2048 + d] : 0.f;
    float z1 = zr[d];
    float z2 = (n < NSEQ - 1) ? zr[2048 + d] : 0.f;
    float c = z0 * dw_w[d * 3 + 0] + z1 * dw_w[d * 3 + 1] + z2 * dw_w[d * 3 + 2] + dw_b[d];
    float g = zr[1024 + d];
    float sc = c / (1.f + expf(-c));
    float sg = g / (1.f + expf(-g));
    g_scratch[OFF_ZM + (size_t)row * 1024 + d] = sc * sg;
}

// =====================================================================
// Haar mix over sequence pairs
// =====================================================================
__global__ void haar_kernel()
{
    int gid = blockIdx.x * 256 + threadIdx.x;
    int ch = gid & 255;
    int t  = gid >> 8;
    int c  = t & 2047;
    int b  = t >> 11;
    const float* kr = g_scratch + OFF_KRAW;
    float x0 = kr[((size_t)(b * NSEQ + 2 * c)) * 256 + ch];
    float x1 = kr[((size_t)(b * NSEQ + 2 * c + 1)) * 256 + ch];
    float* kh = g_scratch + OFF_KH;
    kh[((size_t)(b * NSEQ + c)) * 256 + ch]        = 0.5f * (x0 + x1);
    kh[((size_t)(b * NSEQ + 2048 + c)) * 256 + ch] = 0.5f * (x0 - x1);
}

// =====================================================================
// LSH hash: base = zm @ FBASE, sign->salt XOR. fp32 exact.
// =====================================================================
__global__ void hash_kernel(const float* __restrict__ rot,
                            const int* __restrict__ salts)
{
    int m = blockIdx.x;
    int tid = threadIdx.x;
    __shared__ float red[256];
    __shared__ float base_s[8];
    const float* zm = g_scratch + OFF_ZM + (size_t)m * 1024;
    const float* fb = g_scratch + OFF_FBASE;
    int h = tid & 7, ck = tid >> 3;
    float p = 0.f;
    const float* zp = zm + ck * 32;
#pragma unroll
    for (int dd = 0; dd < 32; dd++) p += zp[dd] * fb[(ck * 32 + dd) * 8 + h];
    red[tid] = p;
    __syncthreads();
    if (tid < 8) {
        float s = 0.f;
        for (int c2 = 0; c2 < 32; c2++) s += red[c2 * 8 + tid];
        base_s[tid] = s;
    }
    __syncthreads();
    if (tid == 0) {
        int code = 0;
#pragma unroll
        for (int r = 0; r < 4; r++) {
            int ph = 0;
#pragma unroll
            for (int kk = 0; kk < 8; kk++) {
                float sim = 0.f;
#pragma unroll
                for (int hh = 0; hh < 8; hh++) sim += base_s[hh] * rot[r * 64 + hh * 8 + kk];
                if (sim >= 0.f) ph ^= salts[r * 8 + kk];
            }
            code ^= ph;
        }
        g_bucket[m] = code & (NBK - 1);
    }
}

// =====================================================================
// Stable counting sort per batch
// =====================================================================
__global__ void sort_kernel()
{
    int b = blockIdx.x;
    __shared__ int hist[NBK];
    __shared__ int offs[NBK];
    int tid = threadIdx.x;
    if (tid < NBK) hist[tid] = 0;
    __syncthreads();
    const int* bk = g_bucket + b * NSEQ;
    for (int n = tid; n < NSEQ; n += 256) atomicAdd(&hist[bk[n]], 1);
    __syncthreads();
    if (tid == 0) {
        int s = 0;
        for (int i = 0; i < NBK; i++) { offs[i] = s; s += hist[i]; }
    }
    __syncthreads();
    if (tid < NBK) {
        int pos = offs[tid];
        for (int n = 0; n < NSEQ; n++) {
            if (bk[n] == tid) { g_order[b * NSEQ + pos] = n; pos++; }
        }
    }
}

// =====================================================================
// Bucketed attention (SIMT fp32)
// =====================================================================
#define QKPAD 132
#define PPAD  129
#define VPAD  68
#define ATTN_SMEM ((2*64*QKPAD + 128*VPAD) * 4)

__global__ __launch_bounds__(256, 2)
void attn_kernel()
{
    extern __shared__ float smf[];
    float* qT  = smf;
    float* kT  = smf + 64 * QKPAD;
    float* p_s = smf;
    float* v_s = smf + 2 * 64 * QKPAD;
    __shared__ int idx_s[128];

    const int c = blockIdx.x, h = blockIdx.y, b = blockIdx.z;
    const int kvh = h >> 2;
    const int tid = threadIdx.x;
    const int ty = tid >> 4, tx = tid & 15;

    if (tid < 128) idx_s[tid] = g_order[b * NSEQ + c * BUCK + tid];
    __syncthreads();

    const float* gq = g_scratch + OFF_Q;
    const float* gk = g_scratch + OFF_KH;
    const float* gv = g_scratch + OFF_V;

    for (int e = tid; e < 128 * 16; e += 256) {
        int row = e >> 4;
        int c4  = (e & 15) << 2;
        size_t grow = (size_t)(b * NSEQ + idx_s[row]);
        float4 qv = *(const float4*)(gq + grow * 1024 + h * 64 + c4);
        qT[(c4 + 0) * QKPAD + row] = qv.x;
        qT[(c4 + 1) * QKPAD + row] = qv.y;
        qT[(c4 + 2) * QKPAD + row] = qv.z;
        qT[(c4 + 3) * QKPAD + row] = qv.w;
        float4 kv = *(const float4*)(gk + grow * 256 + kvh * 64 + c4);
        kT[(c4 + 0) * QKPAD + row] = kv.x;
        kT[(c4 + 1) * QKPAD + row] = kv.y;
        kT[(c4 + 2) * QKPAD + row] = kv.z;
        kT[(c4 + 3) * QKPAD + row] = kv.w;
        *(float4*)(v_s + row * VPAD + c4) = *(const float4*)(gv + grow * 256 + kvh * 64 + c4);
    }
    __syncthreads();

    float acc[8][8];
#pragma unroll
    for (int i = 0; i < 8; i++)
#pragma unroll
        for (int j = 0; j < 8; j++) acc[i][j] = 0.f;

#pragma unroll 8
    for (int d = 0; d < 64; d++) {
        float a[8], bf[8];
        *(float4*)(a)      = *(const float4*)(qT + d * QKPAD + ty * 8);
        *(float4*)(a + 4)  = *(const float4*)(qT + d * QKPAD + ty * 8 + 4);
        *(float4*)(bf)     = *(const float4*)(kT + d * QKPAD + tx * 8);
        *(float4*)(bf + 4) = *(const float4*)(kT + d * QKPAD + tx * 8 + 4);
#pragma unroll
        for (int i = 0; i < 8; i++)
#pragma unroll
            for (int j = 0; j < 8; j++)
                acc[i][j] += a[i] * bf[j];
    }
    __syncthreads();

    float rowmax[8], rinv[8];
#pragma unroll
    for (int i = 0; i < 8; i++) {
        float m = acc[i][0];
#pragma unroll
        for (int j = 1; j < 8; j++) m = fmaxf(m, acc[i][j]);
#pragma unroll
        for (int off = 8; off >= 1; off >>= 1)
            m = fmaxf(m, __shfl_xor_sync(0xffffffffu, m, off));
        rowmax[i] = m;
    }
#pragma unroll
    for (int i = 0; i < 8; i++) {
        float s = 0.f;
#pragma unroll
        for (int j = 0; j < 8; j++) {
            float e = __expf((acc[i][j] - rowmax[i]) * 0.125f);
            acc[i][j] = e;
            s += e;
        }
#pragma unroll
        for (int off = 8; off >= 1; off >>= 1)
            s += __shfl_xor_sync(0xffffffffu, s, off);
        rinv[i] = 1.f / s;
    }
#pragma unroll
    for (int i = 0; i < 8; i++)
#pragma unroll
        for (int j = 0; j < 8; j++)
            p_s[(ty * 8 + i) * PPAD + tx * 8 + j] = acc[i][j] * rinv[i];
    __syncthreads();

    float o[8][4];
#pragma unroll
    for (int i = 0; i < 8; i++)
#pragma unroll
        for (int k2 = 0; k2 < 4; k2++) o[i][k2] = 0.f;

#pragma unroll 4
    for (int j = 0; j < 128; j++) {
        float4 vv = *(const float4*)(v_s + j * VPAD + tx * 4);
#pragma unroll
        for (int i = 0; i < 8; i++) {
            float p = p_s[(ty * 8 + i) * PPAD + j];
            o[i][0] += p * vv.x;
            o[i][1] += p * vv.y;
            o[i][2] += p * vv.z;
            o[i][3] += p * vv.w;
        }
    }
    float* ga = g_scratch + OFF_ATT;
#pragma unroll
    for (int i = 0; i < 8; i++) {
        int row = ty * 8 + i;
        size_t grow = (size_t)(b * NSEQ + idx_s[row]);
        *(float4*)(ga + grow * 1024 + h * 64 + tx * 4) =
            make_float4(o[i][0], o[i][1], o[i][2], o[i][3]);
    }
}

// =====================================================================
// Host launcher
// =====================================================================
extern "C" void kernel_launch(void* const* d_in, const int* in_sizes, int n_in,
                              void* d_out, int out_size)
{
    const float* x         = (const float*)d_in[0];
    const float* ge_inp_w  = (const float*)d_in[1];
    const float* dw_w      = (const float*)d_in[2];
    const float* dw_b      = (const float*)d_in[3];
    const float* ge_out_w  = (const float*)d_in[4];
    const float* q_w       = (const float*)d_in[5];
    const float* k_w       = (const float*)d_in[6];
    const float* v_w       = (const float*)d_in[7];
    const float* Aq        = (const float*)d_in[8];
    const float* Bq        = (const float*)d_in[9];
    const float* Ak        = (const float*)d_in[10];
    const float* Bk        = (const float*)d_in[11];
    const float* rand_gate = (const float*)d_in[12];
    const float* base_w    = (const float*)d_in[13];
    const float* rot       = (const float*)d_in[14];
    const float* o_w       = (const float*)d_in[16];
    const int*   salts     = (const int*)d_in[17];
    float* out = (float*)d_out;

    float* sc = nullptr;
    cudaGetSymbolAddress((void**)&sc, g_scratch);

    cudaFuncSetAttribute(attn_kernel, cudaFuncAttributeMaxDynamicSharedMemorySize, ATTN_SMEM);
    cudaFuncSetAttribute(gemm_tc<false>, cudaFuncAttributeMaxDynamicSharedMemorySize, SMEM_TC1);
    cudaFuncSetAttribute(gemm_tc<true>,  cudaFuncAttributeMaxDynamicSharedMemorySize, SMEM_TC3);

    // ---- weight folds ----
    fold_small<<<16, 256>>>(Aq, Bq, Ak, Bk);
    fold_qw<<<1024, 256>>>(q_w, k_w, rand_gate);
    // FQ = GEq @ QWP, FK = GEk @ KWP   (tf32 -> smooth path only)
    gemm_tc<false><<<dim3(8, 8), 256, SMEM_TC1>>>(ge_out_w, 2048, sc + OFF_QWP, 1024, sc + OFF_FQ, 1024, 1024);
    gemm_tc<false><<<dim3(2, 8), 256, SMEM_TC1>>>(ge_out_w + 1024, 2048, sc + OFF_KWP, 256, sc + OFF_FK, 256, 1024);
    // FBASE fp32 exact (sign-critical)
    fold_base<<<1024, 256>>>(ge_out_w, base_w);

    // ---- activations ----
    // zfull = x @ ge_inp_w  (3xtf32 emulated fp32 — feeds sign path via conv/silu)
    gemm_tc<true><<<dim3(16, 64), 256, SMEM_TC3>>>(x, 1024, ge_inp_w, 2048, sc + OFF_ZFULL, 2048, 1024);
    conv_silu<<<(MROWS * 1024) / 256, 256>>>(dw_w, dw_b);

    hash_kernel<<<MROWS, 256>>>(rot, salts);
    sort_kernel<<<BB, 256>>>();

    // smooth projections (tf32)
    gemm_tc<false><<<dim3(8, 64), 256, SMEM_TC1>>>(sc + OFF_ZM, 1024, sc + OFF_FQ, 1024, sc + OFF_Q, 1024, 1024);
    gemm_tc<false><<<dim3(2, 64), 256, SMEM_TC1>>>(sc + OFF_ZM, 1024, sc + OFF_FK, 256, sc + OFF_KRAW, 256, 1024);
    gemm_tc<false><<<dim3(2, 64), 256, SMEM_TC1>>>(x, 1024, v_w, 256, sc + OFF_V, 256, 1024);

    haar_kernel<<<(BB * 2048 * 256) / 256, 256>>>();

    attn_kernel<<<dim3(NBK, HH, BB), 256, ATTN_SMEM>>>();

    // out = att @ o_w (tf32)
    gemm_tc<false><<<dim3(8, 64), 256, SMEM_TC1>>>(sc + OFF_ATT, 1024, o_w, 1024, out, 1024, 1024);
}

// round 5
// speedup vs baseline: 2.1962x; 2.1962x over previous
#include <cuda_runtime.h>
#include <cstdint>
#include <cstddef>

// ---------------- problem constants ----------------
#define BB    2
#define NSEQ  4096
#define DMOD  1024
#define HH    16
#define HKV   4
#define DHD   64
#define MROWS (BB*NSEQ)          // 8192
#define NBK   32
#define BUCK  128

// ---------------- scratch layout (floats) ----------------
#define OFF_ZFULL 0ull                          // 8192*2048
#define OFF_ZM    (OFF_ZFULL + 16777216ull)     // 8192*1024
#define OFF_Q     (OFF_ZM    + 8388608ull)      // 8192*1024
#define OFF_KRAW  (OFF_Q     + 8388608ull)      // 8192*256
#define OFF_KH    (OFF_KRAW  + 2097152ull)      // 8192*256
#define OFF_V     (OFF_KH    + 2097152ull)      // 8192*256
#define OFF_ATT   (OFF_V     + 2097152ull)      // 8192*1024
#define OFF_QWP   (OFF_ATT   + 8388608ull)      // 1024*1024
#define OFF_KWP   (OFF_QWP   + 1048576ull)      // 1024*256
#define OFF_FQ    (OFF_KWP   + 262144ull)       // 1024*1024
#define OFF_FK    (OFF_FQ    + 1048576ull)      // 1024*256
#define OFF_FBASE (OFF_FK    + 262144ull)       // 1024*8
#define OFF_WQ    (OFF_FBASE + 8192ull)         // 64*64
#define OFF_WK    (OFF_WQ    + 4096ull)         // 64*64
#define SCRATCH_TOTAL (OFF_WK + 4096ull)

__device__ __align__(256) float g_scratch[SCRATCH_TOTAL];
__device__ int g_bucket[MROWS];
__device__ int g_order[MROWS];

// =====================================================================
// tf32 tensor-core GEMM (R3-proven skeleton): C = A @ B, fp32 in/out,
// tf32 MMA m16n8k8, 128x128x32 tiles, 8 warps of 64x32.
// =====================================================================
#define TBM 128
#define TBN 128
#define TBK 32
#define TAPAD 36
#define TBPAD 132

__device__ __forceinline__ uint32_t f2tf32(float f) {
    uint32_t r;
    asm("cvt.rna.tf32.f32 %0, %1;" : "=r"(r) : "f"(f));
    return r;
}

__device__ __forceinline__ void mma_tf32(float* c, const uint32_t* a, const uint32_t* b) {
    asm volatile(
        "mma.sync.aligned.m16n8k8.row.col.f32.tf32.tf32.f32 "
        "{%0,%1,%2,%3}, {%4,%5,%6,%7}, {%8,%9}, {%0,%1,%2,%3};"
        : "+f"(c[0]), "+f"(c[1]), "+f"(c[2]), "+f"(c[3])
        : "r"(a[0]), "r"(a[1]), "r"(a[2]), "r"(a[3]), "r"(b[0]), "r"(b[1]));
}

__global__ __launch_bounds__(256, 2)
void gemm_tf32(const float* __restrict__ A, int lda,
               const float* __restrict__ Bm, int ldb,
               float* __restrict__ C, int ldc, int K)
{
    __shared__ __align__(16) uint32_t a_s[TBM * TAPAD];   // [m][k]
    __shared__ __align__(16) uint32_t b_s[TBK * TBPAD];   // [k][n]

    const int tid = threadIdx.x;
    const int warp = tid >> 5, lane = tid & 31;
    const int wm = (warp >> 2) * 64;
    const int wn = (warp & 3) * 32;
    const int bm = blockIdx.y * TBM;
    const int bn = blockIdx.x * TBN;

    float acc[4][4][4];
#pragma unroll
    for (int i = 0; i < 4; i++)
#pragma unroll
        for (int j = 0; j < 4; j++)
#pragma unroll
            for (int k = 0; k < 4; k++) acc[i][j][k] = 0.f;

    const int lq = lane >> 2;
    const int lr = lane & 3;

    for (int kt = 0; kt < K; kt += TBK) {
#pragma unroll
        for (int u = 0; u < 4; u++) {
            int id = tid + u * 256;
            int r  = id >> 3;
            int kc = (id & 7) << 2;
            float4 v = *(const float4*)(A + (size_t)(bm + r) * lda + kt + kc);
            a_s[r * TAPAD + kc + 0] = f2tf32(v.x);
            a_s[r * TAPAD + kc + 1] = f2tf32(v.y);
            a_s[r * TAPAD + kc + 2] = f2tf32(v.z);
            a_s[r * TAPAD + kc + 3] = f2tf32(v.w);
        }
#pragma unroll
        for (int u = 0; u < 4; u++) {
            int id = tid + u * 256;
            int r  = id >> 5;
            int nc = (id & 31) << 2;
            float4 v = *(const float4*)(Bm + (size_t)(kt + r) * ldb + bn + nc);
            b_s[r * TBPAD + nc + 0] = f2tf32(v.x);
            b_s[r * TBPAD + nc + 1] = f2tf32(v.y);
            b_s[r * TBPAD + nc + 2] = f2tf32(v.z);
            b_s[r * TBPAD + nc + 3] = f2tf32(v.w);
        }
        __syncthreads();

#pragma unroll
        for (int kk = 0; kk < TBK; kk += 8) {
            uint32_t a[4][4], b[4][2];
#pragma unroll
            for (int mt = 0; mt < 4; mt++) {
                int r = wm + mt * 16 + lq;
                a[mt][0] = a_s[r * TAPAD + kk + lr];
                a[mt][1] = a_s[(r + 8) * TAPAD + kk + lr];
                a[mt][2] = a_s[r * TAPAD + kk + lr + 4];
                a[mt][3] = a_s[(r + 8) * TAPAD + kk + lr + 4];
            }
#pragma unroll
            for (int nt = 0; nt < 4; nt++) {
                int cc = wn + nt * 8 + lq;
                b[nt][0] = b_s[(kk + lr) * TBPAD + cc];
                b[nt][1] = b_s[(kk + lr + 4) * TBPAD + cc];
            }
#pragma unroll
            for (int mt = 0; mt < 4; mt++)
#pragma unroll
                for (int nt = 0; nt < 4; nt++)
                    mma_tf32(acc[mt][nt], a[mt], b[nt]);
        }
        __syncthreads();
    }

#pragma unroll
    for (int mt = 0; mt < 4; mt++) {
#pragma unroll
        for (int nt = 0; nt < 4; nt++) {
            int row = bm + wm + mt * 16 + lq;
            int col = bn + wn + nt * 8 + 2 * lr;
            *(float2*)(C + (size_t)row * ldc + col) =
                make_float2(acc[mt][nt][0], acc[mt][nt][1]);
            *(float2*)(C + (size_t)(row + 8) * ldc + col) =
                make_float2(acc[mt][nt][2], acc[mt][nt][3]);
        }
    }
}

// =====================================================================
// 3xtf32 split GEMM (fp32-class accuracy) on the SAME skeleton.
// hi = rna_tf32(x), lo = rna_tf32(x - hi); C += Al*Bh + Ah*Bl + Ah*Bh.
// Dynamic smem: Ah, Al, Bh, Bl.
// =====================================================================
#define X3_ASZ (TBM * TAPAD)
#define X3_BSZ (TBK * TBPAD)
#define SMEM_X3 ((2 * X3_ASZ + 2 * X3_BSZ) * 4)

__global__ __launch_bounds__(256)
void gemm_tf32x3(const float* __restrict__ A, int lda,
                 const float* __restrict__ Bm, int ldb,
                 float* __restrict__ C, int ldc, int K)
{
    extern __shared__ uint32_t smu[];
    uint32_t* Ah = smu;
    uint32_t* Al = smu + X3_ASZ;
    uint32_t* Bh = smu + 2 * X3_ASZ;
    uint32_t* Bl = smu + 2 * X3_ASZ + X3_BSZ;

    const int tid = threadIdx.x;
    const int warp = tid >> 5, lane = tid & 31;
    const int wm = (warp >> 2) * 64;
    const int wn = (warp & 3) * 32;
    const int bm = blockIdx.y * TBM;
    const int bn = blockIdx.x * TBN;

    float acc[4][4][4];
#pragma unroll
    for (int i = 0; i < 4; i++)
#pragma unroll
        for (int j = 0; j < 4; j++)
#pragma unroll
            for (int k = 0; k < 4; k++) acc[i][j][k] = 0.f;

    const int lq = lane >> 2;
    const int lr = lane & 3;

    for (int kt = 0; kt < K; kt += TBK) {
#pragma unroll
        for (int u = 0; u < 4; u++) {
            int id = tid + u * 256;
            int r  = id >> 3;
            int kc = (id & 7) << 2;
            float4 v = *(const float4*)(A + (size_t)(bm + r) * lda + kt + kc);
            float vv[4] = {v.x, v.y, v.z, v.w};
#pragma unroll
            for (int i = 0; i < 4; i++) {
                uint32_t hi = f2tf32(vv[i]);
                Ah[r * TAPAD + kc + i] = hi;
                Al[r * TAPAD + kc + i] = f2tf32(vv[i] - __uint_as_float(hi));
            }
        }
#pragma unroll
        for (int u = 0; u < 4; u++) {
            int id = tid + u * 256;
            int r  = id >> 5;
            int nc = (id & 31) << 2;
            float4 v = *(const float4*)(Bm + (size_t)(kt + r) * ldb + bn + nc);
            float vv[4] = {v.x, v.y, v.z, v.w};
#pragma unroll
            for (int i = 0; i < 4; i++) {
                uint32_t hi = f2tf32(vv[i]);
                Bh[r * TBPAD + nc + i] = hi;
                Bl[r * TBPAD + nc + i] = f2tf32(vv[i] - __uint_as_float(hi));
            }
        }
        __syncthreads();

#pragma unroll
        for (int kk = 0; kk < TBK; kk += 8) {
            uint32_t ah[4][4], al[4][4], bh[4][2], bl[4][2];
#pragma unroll
            for (int mt = 0; mt < 4; mt++) {
                int r = wm + mt * 16 + lq;
                ah[mt][0] = Ah[r * TAPAD + kk + lr];
                ah[mt][1] = Ah[(r + 8) * TAPAD + kk + lr];
                ah[mt][2] = Ah[r * TAPAD + kk + lr + 4];
                ah[mt][3] = Ah[(r + 8) * TAPAD + kk + lr + 4];
                al[mt][0] = Al[r * TAPAD + kk + lr];
                al[mt][1] = Al[(r + 8) * TAPAD + kk + lr];
                al[mt][2] = Al[r * TAPAD + kk + lr + 4];
                al[mt][3] = Al[(r + 8) * TAPAD + kk + lr + 4];
            }
#pragma unroll
            for (int nt = 0; nt < 4; nt++) {
                int cc = wn + nt * 8 + lq;
                bh[nt][0] = Bh[(kk + lr) * TBPAD + cc];
                bh[nt][1] = Bh[(kk + lr + 4) * TBPAD + cc];
                bl[nt][0] = Bl[(kk + lr) * TBPAD + cc];
                bl[nt][1] = Bl[(kk + lr + 4) * TBPAD + cc];
            }
#pragma unroll
            for (int mt = 0; mt < 4; mt++)
#pragma unroll
                for (int nt = 0; nt < 4; nt++) {
                    mma_tf32(acc[mt][nt], al[mt], bh[nt]);
                    mma_tf32(acc[mt][nt], ah[mt], bl[nt]);
                    mma_tf32(acc[mt][nt], ah[mt], bh[nt]);
                }
        }
        __syncthreads();
    }

#pragma unroll
    for (int mt = 0; mt < 4; mt++) {
#pragma unroll
        for (int nt = 0; nt < 4; nt++) {
            int row = bm + wm + mt * 16 + lq;
            int col = bn + wn + nt * 8 + 2 * lr;
            *(float2*)(C + (size_t)row * ldc + col) =
                make_float2(acc[mt][nt][0], acc[mt][nt][1]);
            *(float2*)(C + (size_t)(row + 8) * ldc + col) =
                make_float2(acc[mt][nt][2], acc[mt][nt][3]);
        }
    }
}

// =====================================================================
// Weight folds
// =====================================================================
__global__ void fold_small(const float* __restrict__ Aq, const float* __restrict__ Bq,
                           const float* __restrict__ Ak, const float* __restrict__ Bk)
{
    int ij = blockIdx.x * blockDim.x + threadIdx.x;
    int i = ij >> 6, j = ij & 63;
    float sq = 0.f, sk = 0.f;
#pragma unroll
    for (int r = 0; r < 16; r++) {
        sq += Aq[i * 16 + r] * Bq[r * 64 + j];
        sk += Ak[i * 16 + r] * Bk[r * 64 + j];
    }
    g_scratch[OFF_WQ + ij] = sq;
    g_scratch[OFF_WK + ij] = sk;
}

__global__ void fold_qw(const float* __restrict__ qw, const float* __restrict__ kw,
                        const float* __restrict__ rand_gate)
{
    __shared__ float qr[1024];
    __shared__ float kr[256];
    __shared__ float wq_s[4096];
    __shared__ float wk_s[4096];
    int d = blockIdx.x;
    int tid = threadIdx.x;
    for (int i = tid; i < 4096; i += 256) { wq_s[i] = g_scratch[OFF_WQ + i]; wk_s[i] = g_scratch[OFF_WK + i]; }
    for (int i = tid; i < 1024; i += 256) qr[i] = qw[(size_t)d * 1024 + i];
    if (tid < 256) kr[tid] = kw[(size_t)d * 256 + tid];
    __syncthreads();
    for (int c = tid; c < 1024; c += 256) {
        int h = c >> 6, j = c & 63;
        float s = 0.f;
#pragma unroll
        for (int i = 0; i < 64; i++) s += qr[h * 64 + i] * wq_s[i * 64 + j];
        g_scratch[OFF_QWP + (size_t)d * 1024 + c] = s;
    }
    {
        int c = tid;
        int g = c >> 6, j = c & 63;
        float s = 0.f;
#pragma unroll
        for (int i = 0; i < 64; i++) s += kr[g * 64 + i] * wk_s[i * 64 + j];
        g_scratch[OFF_KWP + (size_t)d * 256 + c] = s * tanhf(1.f + rand_gate[j]);
    }
}

// FBASE = GEq @ base_w (fp32 exact — sign-critical)
__global__ void fold_base(const float* __restrict__ ge_out_w,
                          const float* __restrict__ base_w)
{
    int i = blockIdx.x;
    int tid = threadIdx.x;
    __shared__ float red[256];
    const float* a = ge_out_w + (size_t)i * 2048;
    int h = tid & 7, ck = tid >> 3;
    float p = 0.f;
#pragma unroll
    for (int dd = 0; dd < 32; dd++)
        p += a[ck * 32 + dd] * base_w[(ck * 32 + dd) * 8 + h];
    red[tid] = p;
    __syncthreads();
    if (tid < 8) {
        float s = 0.f;
        for (int c2 = 0; c2 < 32; c2++) s += red[c2 * 8 + tid];
        g_scratch[OFF_FBASE + (size_t)i * 8 + tid] = s;
    }
}

// =====================================================================
// conv + SiLU*SiLU gating (precision-critical -> expf)
// =====================================================================
__global__ void conv_silu(const float* __restrict__ dw_w, const float* __restrict__ dw_b)
{
    int gid = blockIdx.x * 256 + threadIdx.x;
    int d   = gid & 1023;
    int row = gid >> 10;
    int n   = row & (NSEQ - 1);
    const float* zr = g_scratch + OFF_ZFULL + (size_t)row * 2048;
    float z0 = (n > 0)        ? zr[-2048 + d] : 0.f;
    float z1 = zr[d];
    float z2 = (n < NSEQ - 1) ? zr[2048 + d] : 0.f;
    float c = z0 * dw_w[d * 3 + 0] + z1 * dw_w[d * 3 + 1] + z2 * dw_w[d * 3 + 2] + dw_b[d];
    float g = zr[1024 + d];
    float sc = c / (1.f + expf(-c));
    float sg = g / (1.f + expf(-g));
    g_scratch[OFF_ZM + (size_t)row * 1024 + d] = sc * sg;
}

// =====================================================================
// Haar mix over sequence pairs
// =====================================================================
__global__ void haar_kernel()
{
    int gid = blockIdx.x * 256 + threadIdx.x;
    int ch = gid & 255;
    int t  = gid >> 8;
    int c  = t & 2047;
    int b  = t >> 11;
    const float* kr = g_scratch + OFF_KRAW;
    float x0 = kr[((size_t)(b * NSEQ + 2 * c)) * 256 + ch];
    float x1 = kr[((size_t)(b * NSEQ + 2 * c + 1)) * 256 + ch];
    float* kh = g_scratch + OFF_KH;
    kh[((size_t)(b * NSEQ + c)) * 256 + ch]        = 0.5f * (x0 + x1);
    kh[((size_t)(b * NSEQ + 2048 + c)) * 256 + ch] = 0.5f * (x0 - x1);
}

// =====================================================================
// LSH hash: base = zm @ FBASE, sign->salt XOR. fp32 exact.
// =====================================================================
__global__ void hash_kernel(const float* __restrict__ rot,
                            const int* __restrict__ salts)
{
    int m = blockIdx.x;
    int tid = threadIdx.x;
    __shared__ float red[256];
    __shared__ float base_s[8];
    const float* zm = g_scratch + OFF_ZM + (size_t)m * 1024;
    const float* fb = g_scratch + OFF_FBASE;
    int h = tid & 7, ck = tid >> 3;
    float p = 0.f;
    const float* zp = zm + ck * 32;
#pragma unroll
    for (int dd = 0; dd < 32; dd++) p += zp[dd] * fb[(ck * 32 + dd) * 8 + h];
    red[tid] = p;
    __syncthreads();
    if (tid < 8) {
        float s = 0.f;
        for (int c2 = 0; c2 < 32; c2++) s += red[c2 * 8 + tid];
        base_s[tid] = s;
    }
    __syncthreads();
    if (tid == 0) {
        int code = 0;
#pragma unroll
        for (int r = 0; r < 4; r++) {
            int ph = 0;
#pragma unroll
            for (int kk = 0; kk < 8; kk++) {
                float sim = 0.f;
#pragma unroll
                for (int hh = 0; hh < 8; hh++) sim += base_s[hh] * rot[r * 64 + hh * 8 + kk];
                if (sim >= 0.f) ph ^= salts[r * 8 + kk];
            }
            code ^= ph;
        }
        g_bucket[m] = code & (NBK - 1);
    }
}

// =====================================================================
// Stable counting sort per batch
// =====================================================================
__global__ void sort_kernel()
{
    int b = blockIdx.x;
    __shared__ int hist[NBK];
    __shared__ int offs[NBK];
    int tid = threadIdx.x;
    if (tid < NBK) hist[tid] = 0;
    __syncthreads();
    const int* bk = g_bucket + b * NSEQ;
    for (int n = tid; n < NSEQ; n += 256) atomicAdd(&hist[bk[n]], 1);
    __syncthreads();
    if (tid == 0) {
        int s = 0;
        for (int i = 0; i < NBK; i++) { offs[i] = s; s += hist[i]; }
    }
    __syncthreads();
    if (tid < NBK) {
        int pos = offs[tid];
        for (int n = 0; n < NSEQ; n++) {
            if (bk[n] == tid) { g_order[b * NSEQ + pos] = n; pos++; }
        }
    }
}

// =====================================================================
// Bucketed attention (SIMT fp32)
// =====================================================================
#define QKPAD 132
#define PPAD  129
#define VPAD  68
#define ATTN_SMEM ((2*64*QKPAD + 128*VPAD) * 4)

__global__ __launch_bounds__(256, 2)
void attn_kernel()
{
    extern __shared__ float smf[];
    float* qT  = smf;
    float* kT  = smf + 64 * QKPAD;
    float* p_s = smf;
    float* v_s = smf + 2 * 64 * QKPAD;
    __shared__ int idx_s[128];

    const int c = blockIdx.x, h = blockIdx.y, b = blockIdx.z;
    const int kvh = h >> 2;
    const int tid = threadIdx.x;
    const int ty = tid >> 4, tx = tid & 15;

    if (tid < 128) idx_s[tid] = g_order[b * NSEQ + c * BUCK + tid];
    __syncthreads();

    const float* gq = g_scratch + OFF_Q;
    const float* gk = g_scratch + OFF_KH;
    const float* gv = g_scratch + OFF_V;

    for (int e = tid; e < 128 * 16; e += 256) {
        int row = e >> 4;
        int c4  = (e & 15) << 2;
        size_t grow = (size_t)(b * NSEQ + idx_s[row]);
        float4 qv = *(const float4*)(gq + grow * 1024 + h * 64 + c4);
        qT[(c4 + 0) * QKPAD + row] = qv.x;
        qT[(c4 + 1) * QKPAD + row] = qv.y;
        qT[(c4 + 2) * QKPAD + row] = qv.z;
        qT[(c4 + 3) * QKPAD + row] = qv.w;
        float4 kv = *(const float4*)(gk + grow * 256 + kvh * 64 + c4);
        kT[(c4 + 0) * QKPAD + row] = kv.x;
        kT[(c4 + 1) * QKPAD + row] = kv.y;
        kT[(c4 + 2) * QKPAD + row] = kv.z;
        kT[(c4 + 3) * QKPAD + row] = kv.w;
        *(float4*)(v_s + row * VPAD + c4) = *(const float4*)(gv + grow * 256 + kvh * 64 + c4);
    }
    __syncthreads();

    float acc[8][8];
#pragma unroll
    for (int i = 0; i < 8; i++)
#pragma unroll
        for (int j = 0; j < 8; j++) acc[i][j] = 0.f;

#pragma unroll 8
    for (int d = 0; d < 64; d++) {
        float a[8], bf[8];
        *(float4*)(a)      = *(const float4*)(qT + d * QKPAD + ty * 8);
        *(float4*)(a + 4)  = *(const float4*)(qT + d * QKPAD + ty * 8 + 4);
        *(float4*)(bf)     = *(const float4*)(kT + d * QKPAD + tx * 8);
        *(float4*)(bf + 4) = *(const float4*)(kT + d * QKPAD + tx * 8 + 4);
#pragma unroll
        for (int i = 0; i < 8; i++)
#pragma unroll
            for (int j = 0; j < 8; j++)
                acc[i][j] += a[i] * bf[j];
    }
    __syncthreads();

    float rowmax[8], rinv[8];
#pragma unroll
    for (int i = 0; i < 8; i++) {
        float m = acc[i][0];
#pragma unroll
        for (int j = 1; j < 8; j++) m = fmaxf(m, acc[i][j]);
#pragma unroll
        for (int off = 8; off >= 1; off >>= 1)
            m = fmaxf(m, __shfl_xor_sync(0xffffffffu, m, off));
        rowmax[i] = m;
    }
#pragma unroll
    for (int i = 0; i < 8; i++) {
        float s = 0.f;
#pragma unroll
        for (int j = 0; j < 8; j++) {
            float e = __expf((acc[i][j] - rowmax[i]) * 0.125f);
            acc[i][j] = e;
            s += e;
        }
#pragma unroll
        for (int off = 8; off >= 1; off >>= 1)
            s += __shfl_xor_sync(0xffffffffu, s, off);
        rinv[i] = 1.f / s;
    }
#pragma unroll
    for (int i = 0; i < 8; i++)
#pragma unroll
        for (int j = 0; j < 8; j++)
            p_s[(ty * 8 + i) * PPAD + tx * 8 + j] = acc[i][j] * rinv[i];
    __syncthreads();

    float o[8][4];
#pragma unroll
    for (int i = 0; i < 8; i++)
#pragma unroll
        for (int k2 = 0; k2 < 4; k2++) o[i][k2] = 0.f;

#pragma unroll 4
    for (int j = 0; j < 128; j++) {
        float4 vv = *(const float4*)(v_s + j * VPAD + tx * 4);
#pragma unroll
        for (int i = 0; i < 8; i++) {
            float p = p_s[(ty * 8 + i) * PPAD + j];
            o[i][0] += p * vv.x;
            o[i][1] += p * vv.y;
            o[i][2] += p * vv.z;
            o[i][3] += p * vv.w;
        }
    }
    float* ga = g_scratch + OFF_ATT;
#pragma unroll
    for (int i = 0; i < 8; i++) {
        int row = ty * 8 + i;
        size_t grow = (size_t)(b * NSEQ + idx_s[row]);
        *(float4*)(ga + grow * 1024 + h * 64 + tx * 4) =
            make_float4(o[i][0], o[i][1], o[i][2], o[i][3]);
    }
}

// =====================================================================
// Host launcher
// =====================================================================
extern "C" void kernel_launch(void* const* d_in, const int* in_sizes, int n_in,
                              void* d_out, int out_size)
{
    const float* x         = (const float*)d_in[0];
    const float* ge_inp_w  = (const float*)d_in[1];
    const float* dw_w      = (const float*)d_in[2];
    const float* dw_b      = (const float*)d_in[3];
    const float* ge_out_w  = (const float*)d_in[4];
    const float* q_w       = (const float*)d_in[5];
    const float* k_w       = (const float*)d_in[6];
    const float* v_w       = (const float*)d_in[7];
    const float* Aq        = (const float*)d_in[8];
    const float* Bq        = (const float*)d_in[9];
    const float* Ak        = (const float*)d_in[10];
    const float* Bk        = (const float*)d_in[11];
    const float* rand_gate = (const float*)d_in[12];
    const float* base_w    = (const float*)d_in[13];
    const float* rot       = (const float*)d_in[14];
    const float* o_w       = (const float*)d_in[16];
    const int*   salts     = (const int*)d_in[17];
    float* out = (float*)d_out;

    float* sc = nullptr;
    cudaGetSymbolAddress((void**)&sc, g_scratch);

    cudaFuncSetAttribute(attn_kernel, cudaFuncAttributeMaxDynamicSharedMemorySize, ATTN_SMEM);
    cudaFuncSetAttribute(gemm_tf32x3, cudaFuncAttributeMaxDynamicSharedMemorySize, SMEM_X3);

    // ---- weight folds ----
    fold_small<<<16, 256>>>(Aq, Bq, Ak, Bk);
    fold_qw<<<1024, 256>>>(q_w, k_w, rand_gate);
    // FQ = GEq @ QWP, FK = GEk @ KWP  (tf32 — smooth path only)
    gemm_tf32<<<dim3(8, 8), 256>>>(ge_out_w, 2048, sc + OFF_QWP, 1024, sc + OFF_FQ, 1024, 1024);
    gemm_tf32<<<dim3(2, 8), 256>>>(ge_out_w + 1024, 2048, sc + OFF_KWP, 256, sc + OFF_FK, 256, 1024);
    // FBASE fp32 exact (sign-critical)
    fold_base<<<1024, 256>>>(ge_out_w, base_w);

    // ---- activations ----
    // zfull = x @ ge_inp_w  (3xtf32 split — fp32-class accuracy for sign path)
    gemm_tf32x3<<<dim3(16, 64), 256, SMEM_X3>>>(x, 1024, ge_inp_w, 2048, sc + OFF_ZFULL, 2048, 1024);
    conv_silu<<<(MROWS * 1024) / 256, 256>>>(dw_w, dw_b);

    hash_kernel<<<MROWS, 256>>>(rot, salts);
    sort_kernel<<<BB, 256>>>();

    // smooth projections (tf32)
    gemm_tf32<<<dim3(8, 64), 256>>>(sc + OFF_ZM, 1024, sc + OFF_FQ, 1024, sc + OFF_Q, 1024, 1024);
    gemm_tf32<<<dim3(2, 64), 256>>>(sc + OFF_ZM, 1024, sc + OFF_FK, 256, sc + OFF_KRAW, 256, 1024);
    gemm_tf32<<<dim3(2, 64), 256>>>(x, 1024, v_w, 256, sc + OFF_V, 256, 1024);

    haar_kernel<<<(BB * 2048 * 256) / 256, 256>>>();

    attn_kernel<<<dim3(NBK, HH, BB), 256, ATTN_SMEM>>>();

    // out = att @ o_w (tf32)
    gemm_tf32<<<dim3(8, 64), 256>>>(sc + OFF_ATT, 1024, o_w, 1024, out, 1024, 1024);
}

// round 6
// speedup vs baseline: 2.3853x; 1.0861x over previous
#include <cuda_runtime.h>
#include <cstdint>
#include <cstddef>

// ---------------- problem constants ----------------
#define BB    2
#define NSEQ  4096
#define DMOD  1024
#define HH    16
#define HKV   4
#define DHD   64
#define MROWS (BB*NSEQ)          // 8192
#define NBK   32
#define BUCK  128

// ---------------- scratch layout (floats) ----------------
#define OFF_ZFULL 0ull                          // 8192*2048
#define OFF_ZM    (OFF_ZFULL + 16777216ull)     // 8192*1024
#define OFF_Q     (OFF_ZM    + 8388608ull)      // 8192*1024
#define OFF_KRAW  (OFF_Q     + 8388608ull)      // 8192*256
#define OFF_KH    (OFF_KRAW  + 2097152ull)      // 8192*256
#define OFF_V     (OFF_KH    + 2097152ull)      // 8192*256
#define OFF_ATT   (OFF_V     + 2097152ull)      // 8192*1024
#define OFF_QWP   (OFF_ATT   + 8388608ull)      // 1024*1024
#define OFF_KWP   (OFF_QWP   + 1048576ull)      // 1024*256
#define OFF_FQ    (OFF_KWP   + 262144ull)       // 1024*1024
#define OFF_FK    (OFF_FQ    + 1048576ull)      // 1024*256
#define OFF_FBASE (OFF_FK    + 262144ull)       // 1024*8
#define OFF_WQ    (OFF_FBASE + 8192ull)         // 64*64
#define OFF_WK    (OFF_WQ    + 4096ull)         // 64*64
#define SCRATCH_TOTAL (OFF_WK + 4096ull)

__device__ __align__(256) float g_scratch[SCRATCH_TOTAL];
__device__ int g_bucket[MROWS];
__device__ int g_order[MROWS];

// =====================================================================
// tf32 tensor-core GEMM core. Same layout/writers as R5 (proven);
// A-fragment reads now via ldmatrix.x4 (conflict-free with TAPAD=36:
// row stride 144B = 9*16B -> 8-row group covers all 32 banks).
// =====================================================================
#define TBM 128
#define TBN 128
#define TBK 32
#define TAPAD 36
#define TBPAD 132

__device__ __forceinline__ uint32_t f2tf32(float f) {
    uint32_t r;
    asm("cvt.rna.tf32.f32 %0, %1;" : "=r"(r) : "f"(f));
    return r;
}

__device__ __forceinline__ void mma_tf32(float* c, const uint32_t* a, const uint32_t* b) {
    asm volatile(
        "mma.sync.aligned.m16n8k8.row.col.f32.tf32.tf32.f32 "
        "{%0,%1,%2,%3}, {%4,%5,%6,%7}, {%8,%9}, {%0,%1,%2,%3};"
        : "+f"(c[0]), "+f"(c[1]), "+f"(c[2]), "+f"(c[3])
        : "r"(a[0]), "r"(a[1]), "r"(a[2]), "r"(a[3]), "r"(b[0]), "r"(b[1]));
}

__device__ __forceinline__ void ldsm_x4(uint32_t* r, uint32_t addr) {
    asm volatile("ldmatrix.sync.aligned.m8n8.x4.shared.b16 {%0,%1,%2,%3}, [%4];"
                 : "=r"(r[0]), "=r"(r[1]), "=r"(r[2]), "=r"(r[3])
                 : "r"(addr));
}

__device__ __forceinline__
void gemm_tf32_tile(const float* __restrict__ A, int lda,
                    const float* __restrict__ Bm, int ldb,
                    float* __restrict__ C, int ldc, int K,
                    int bm, int bn)
{
    __shared__ __align__(16) uint32_t a_s[TBM * TAPAD];   // [m][k]
    __shared__ __align__(16) uint32_t b_s[TBK * TBPAD];   // [k][n]

    const int tid = threadIdx.x;
    const int warp = tid >> 5, lane = tid & 31;
    const int wm = (warp >> 2) * 64;
    const int wn = (warp & 3) * 32;

    float acc[4][4][4];
#pragma unroll
    for (int i = 0; i < 4; i++)
#pragma unroll
        for (int j = 0; j < 4; j++)
#pragma unroll
            for (int k = 0; k < 4; k++) acc[i][j][k] = 0.f;

    const int lq = lane >> 2;
    const int lr = lane & 3;

    // ldmatrix per-thread row address: lanes 0-7 -> rows wm..wm+7 @k0,
    // 8-15 -> +8 @k0, 16-23 -> rows @k0+4, 24-31 -> +8 @k0+4.
    const uint32_t s_a0 = (uint32_t)__cvta_generic_to_shared(a_s);
    const uint32_t a_lm_base =
        s_a0 + (((wm + (lane & 7) + ((lane >> 3) & 1) * 8) * TAPAD + (lane >> 4) * 4) << 2);

    for (int kt = 0; kt < K; kt += TBK) {
#pragma unroll
        for (int u = 0; u < 4; u++) {
            int id = tid + u * 256;
            int r  = id >> 3;
            int kc = (id & 7) << 2;
            float4 v = *(const float4*)(A + (size_t)(bm + r) * lda + kt + kc);
            a_s[r * TAPAD + kc + 0] = f2tf32(v.x);
            a_s[r * TAPAD + kc + 1] = f2tf32(v.y);
            a_s[r * TAPAD + kc + 2] = f2tf32(v.z);
            a_s[r * TAPAD + kc + 3] = f2tf32(v.w);
        }
#pragma unroll
        for (int u = 0; u < 4; u++) {
            int id = tid + u * 256;
            int r  = id >> 5;
            int nc = (id & 31) << 2;
            float4 v = *(const float4*)(Bm + (size_t)(kt + r) * ldb + bn + nc);
            b_s[r * TBPAD + nc + 0] = f2tf32(v.x);
            b_s[r * TBPAD + nc + 1] = f2tf32(v.y);
            b_s[r * TBPAD + nc + 2] = f2tf32(v.z);
            b_s[r * TBPAD + nc + 3] = f2tf32(v.w);
        }
        __syncthreads();

#pragma unroll
        for (int kk = 0; kk < TBK; kk += 8) {
            uint32_t a[4][4], b[4][2];
#pragma unroll
            for (int mt = 0; mt < 4; mt++)
                ldsm_x4(a[mt], a_lm_base + ((mt * 16 * TAPAD + kk) << 2));
#pragma unroll
            for (int nt = 0; nt < 4; nt++) {
                int cc = wn + nt * 8 + lq;
                b[nt][0] = b_s[(kk + lr) * TBPAD + cc];
                b[nt][1] = b_s[(kk + lr + 4) * TBPAD + cc];
            }
#pragma unroll
            for (int mt = 0; mt < 4; mt++)
#pragma unroll
                for (int nt = 0; nt < 4; nt++)
                    mma_tf32(acc[mt][nt], a[mt], b[nt]);
        }
        __syncthreads();
    }

#pragma unroll
    for (int mt = 0; mt < 4; mt++) {
#pragma unroll
        for (int nt = 0; nt < 4; nt++) {
            int row = bm + wm + mt * 16 + lq;
            int col = bn + wn + nt * 8 + 2 * lr;
            *(float2*)(C + (size_t)row * ldc + col) =
                make_float2(acc[mt][nt][0], acc[mt][nt][1]);
            *(float2*)(C + (size_t)(row + 8) * ldc + col) =
                make_float2(acc[mt][nt][2], acc[mt][nt][3]);
        }
    }
}

__global__ __launch_bounds__(256, 2)
void gemm_tf32(const float* __restrict__ A, int lda,
               const float* __restrict__ Bm, int ldb,
               float* __restrict__ C, int ldc, int K)
{
    gemm_tf32_tile(A, lda, Bm, ldb, C, ldc, K, blockIdx.y * TBM, blockIdx.x * TBN);
}

// Fused fold GEMMs in one launch: x<8 -> FQ = GEq@QWP, x>=8 -> FK = GEk@KWP.
__global__ __launch_bounds__(256, 2)
void fold_fused(const float* __restrict__ geo)
{
    const float* A;
    const float* Bm;
    float* C;
    int ldb, ldc, bn;
    if (blockIdx.x < 8) {
        A = geo;            Bm = g_scratch + OFF_QWP; C = g_scratch + OFF_FQ;
        ldb = 1024; ldc = 1024; bn = blockIdx.x * TBN;
    } else {
        A = geo + 1024;     Bm = g_scratch + OFF_KWP; C = g_scratch + OFF_FK;
        ldb = 256;  ldc = 256;  bn = (blockIdx.x - 8) * TBN;
    }
    gemm_tf32_tile(A, 2048, Bm, ldb, C, ldc, 1024, blockIdx.y * TBM, bn);
}

// =====================================================================
// 3xtf32 split GEMM (fp32-class accuracy), ldmatrix A-reads.
// =====================================================================
#define X3_ASZ (TBM * TAPAD)
#define X3_BSZ (TBK * TBPAD)
#define SMEM_X3 ((2 * X3_ASZ + 2 * X3_BSZ) * 4)

__global__ __launch_bounds__(256)
void gemm_tf32x3(const float* __restrict__ A, int lda,
                 const float* __restrict__ Bm, int ldb,
                 float* __restrict__ C, int ldc, int K)
{
    extern __shared__ uint32_t smu[];
    uint32_t* Ah = smu;
    uint32_t* Al = smu + X3_ASZ;
    uint32_t* Bh = smu + 2 * X3_ASZ;
    uint32_t* Bl = smu + 2 * X3_ASZ + X3_BSZ;

    const int tid = threadIdx.x;
    const int warp = tid >> 5, lane = tid & 31;
    const int wm = (warp >> 2) * 64;
    const int wn = (warp & 3) * 32;
    const int bm = blockIdx.y * TBM;
    const int bn = blockIdx.x * TBN;

    float acc[4][4][4];
#pragma unroll
    for (int i = 0; i < 4; i++)
#pragma unroll
        for (int j = 0; j < 4; j++)
#pragma unroll
            for (int k = 0; k < 4; k++) acc[i][j][k] = 0.f;

    const int lq = lane >> 2;
    const int lr = lane & 3;

    const uint32_t s_ah0 = (uint32_t)__cvta_generic_to_shared(Ah);
    const uint32_t lm_off =
        (((wm + (lane & 7) + ((lane >> 3) & 1) * 8) * TAPAD + (lane >> 4) * 4) << 2);
    const uint32_t ah_base = s_ah0 + lm_off;
    const uint32_t al_base = ah_base + (X3_ASZ << 2);

    for (int kt = 0; kt < K; kt += TBK) {
#pragma unroll
        for (int u = 0; u < 4; u++) {
            int id = tid + u * 256;
            int r  = id >> 3;
            int kc = (id & 7) << 2;
            float4 v = *(const float4*)(A + (size_t)(bm + r) * lda + kt + kc);
            float vv[4] = {v.x, v.y, v.z, v.w};
#pragma unroll
            for (int i = 0; i < 4; i++) {
                uint32_t hi = f2tf32(vv[i]);
                Ah[r * TAPAD + kc + i] = hi;
                Al[r * TAPAD + kc + i] = f2tf32(vv[i] - __uint_as_float(hi));
            }
        }
#pragma unroll
        for (int u = 0; u < 4; u++) {
            int id = tid + u * 256;
            int r  = id >> 5;
            int nc = (id & 31) << 2;
            float4 v = *(const float4*)(Bm + (size_t)(kt + r) * ldb + bn + nc);
            float vv[4] = {v.x, v.y, v.z, v.w};
#pragma unroll
            for (int i = 0; i < 4; i++) {
                uint32_t hi = f2tf32(vv[i]);
                Bh[r * TBPAD + nc + i] = hi;
                Bl[r * TBPAD + nc + i] = f2tf32(vv[i] - __uint_as_float(hi));
            }
        }
        __syncthreads();

#pragma unroll
        for (int kk = 0; kk < TBK; kk += 8) {
            uint32_t ah[4][4], al[4][4], bh[4][2], bl[4][2];
#pragma unroll
            for (int mt = 0; mt < 4; mt++) {
                uint32_t off = (mt * 16 * TAPAD + kk) << 2;
                ldsm_x4(ah[mt], ah_base + off);
                ldsm_x4(al[mt], al_base + off);
            }
#pragma unroll
            for (int nt = 0; nt < 4; nt++) {
                int cc = wn + nt * 8 + lq;
                bh[nt][0] = Bh[(kk + lr) * TBPAD + cc];
                bh[nt][1] = Bh[(kk + lr + 4) * TBPAD + cc];
                bl[nt][0] = Bl[(kk + lr) * TBPAD + cc];
                bl[nt][1] = Bl[(kk + lr + 4) * TBPAD + cc];
            }
#pragma unroll
            for (int mt = 0; mt < 4; mt++)
#pragma unroll
                for (int nt = 0; nt < 4; nt++) {
                    mma_tf32(acc[mt][nt], al[mt], bh[nt]);
                    mma_tf32(acc[mt][nt], ah[mt], bl[nt]);
                    mma_tf32(acc[mt][nt], ah[mt], bh[nt]);
                }
        }
        __syncthreads();
    }

#pragma unroll
    for (int mt = 0; mt < 4; mt++) {
#pragma unroll
        for (int nt = 0; nt < 4; nt++) {
            int row = bm + wm + mt * 16 + lq;
            int col = bn + wn + nt * 8 + 2 * lr;
            *(float2*)(C + (size_t)row * ldc + col) =
                make_float2(acc[mt][nt][0], acc[mt][nt][1]);
            *(float2*)(C + (size_t)(row + 8) * ldc + col) =
                make_float2(acc[mt][nt][2], acc[mt][nt][3]);
        }
    }
}

// =====================================================================
// Weight folds (small)
// =====================================================================
__global__ void fold_small(const float* __restrict__ Aq, const float* __restrict__ Bq,
                           const float* __restrict__ Ak, const float* __restrict__ Bk)
{
    int ij = blockIdx.x * blockDim.x + threadIdx.x;
    int i = ij >> 6, j = ij & 63;
    float sq = 0.f, sk = 0.f;
#pragma unroll
    for (int r = 0; r < 16; r++) {
        sq += Aq[i * 16 + r] * Bq[r * 64 + j];
        sk += Ak[i * 16 + r] * Bk[r * 64 + j];
    }
    g_scratch[OFF_WQ + ij] = sq;
    g_scratch[OFF_WK + ij] = sk;
}

__global__ void fold_qw(const float* __restrict__ qw, const float* __restrict__ kw,
                        const float* __restrict__ rand_gate)
{
    __shared__ float qr[1024];
    __shared__ float kr[256];
    __shared__ float wq_s[4096];
    __shared__ float wk_s[4096];
    int d = blockIdx.x;
    int tid = threadIdx.x;
    for (int i = tid; i < 4096; i += 256) { wq_s[i] = g_scratch[OFF_WQ + i]; wk_s[i] = g_scratch[OFF_WK + i]; }
    for (int i = tid; i < 1024; i += 256) qr[i] = qw[(size_t)d * 1024 + i];
    if (tid < 256) kr[tid] = kw[(size_t)d * 256 + tid];
    __syncthreads();
    for (int c = tid; c < 1024; c += 256) {
        int h = c >> 6, j = c & 63;
        float s = 0.f;
#pragma unroll
        for (int i = 0; i < 64; i++) s += qr[h * 64 + i] * wq_s[i * 64 + j];
        g_scratch[OFF_QWP + (size_t)d * 1024 + c] = s;
    }
    {
        int c = tid;
        int g = c >> 6, j = c & 63;
        float s = 0.f;
#pragma unroll
        for (int i = 0; i < 64; i++) s += kr[g * 64 + i] * wk_s[i * 64 + j];
        g_scratch[OFF_KWP + (size_t)d * 256 + c] = s * tanhf(1.f + rand_gate[j]);
    }
}

// FBASE = GEq @ base_w (fp32 exact — sign-critical)
__global__ void fold_base(const float* __restrict__ ge_out_w,
                          const float* __restrict__ base_w)
{
    int i = blockIdx.x;
    int tid = threadIdx.x;
    __shared__ float red[256];
    const float* a = ge_out_w + (size_t)i * 2048;
    int h = tid & 7, ck = tid >> 3;
    float p = 0.f;
#pragma unroll
    for (int dd = 0; dd < 32; dd++)
        p += a[ck * 32 + dd] * base_w[(ck * 32 + dd) * 8 + h];
    red[tid] = p;
    __syncthreads();
    if (tid < 8) {
        float s = 0.f;
        for (int c2 = 0; c2 < 32; c2++) s += red[c2 * 8 + tid];
        g_scratch[OFF_FBASE + (size_t)i * 8 + tid] = s;
    }
}

// =====================================================================
// conv + SiLU*SiLU gating (precision-critical -> expf)
// =====================================================================
__global__ void conv_silu(const float* __restrict__ dw_w, const float* __restrict__ dw_b)
{
    int gid = blockIdx.x * 256 + threadIdx.x;
    int d   = gid & 1023;
    int row = gid >> 10;
    int n   = row & (NSEQ - 1);
    const float* zr = g_scratch + OFF_ZFULL + (size_t)row * 2048;
    float z0 = (n > 0)        ? zr[-2048 + d] : 0.f;
    float z1 = zr[d];
    float z2 = (n < NSEQ - 1) ? zr[2048 + d] : 0.f;
    float c = z0 * dw_w[d * 3 + 0] + z1 * dw_w[d * 3 + 1] + z2 * dw_w[d * 3 + 2] + dw_b[d];
    float g = zr[1024 + d];
    float sc = c / (1.f + expf(-c));
    float sg = g / (1.f + expf(-g));
    g_scratch[OFF_ZM + (size_t)row * 1024 + d] = sc * sg;
}

// =====================================================================
// Haar mix over sequence pairs
// =====================================================================
__global__ void haar_kernel()
{
    int gid = blockIdx.x * 256 + threadIdx.x;
    int ch = gid & 255;
    int t  = gid >> 8;
    int c  = t & 2047;
    int b  = t >> 11;
    const float* kr = g_scratch + OFF_KRAW;
    float x0 = kr[((size_t)(b * NSEQ + 2 * c)) * 256 + ch];
    float x1 = kr[((size_t)(b * NSEQ + 2 * c + 1)) * 256 + ch];
    float* kh = g_scratch + OFF_KH;
    kh[((size_t)(b * NSEQ + c)) * 256 + ch]        = 0.5f * (x0 + x1);
    kh[((size_t)(b * NSEQ + 2048 + c)) * 256 + ch] = 0.5f * (x0 - x1);
}

// =====================================================================
// LSH hash: base = zm @ FBASE, sign->salt XOR. fp32 exact.
// =====================================================================
__global__ void hash_kernel(const float* __restrict__ rot,
                            const int* __restrict__ salts)
{
    int m = blockIdx.x;
    int tid = threadIdx.x;
    __shared__ float red[256];
    __shared__ float base_s[8];
    const float* zm = g_scratch + OFF_ZM + (size_t)m * 1024;
    const float* fb = g_scratch + OFF_FBASE;
    int h = tid & 7, ck = tid >> 3;
    float p = 0.f;
    const float* zp = zm + ck * 32;
#pragma unroll
    for (int dd = 0; dd < 32; dd++) p += zp[dd] * fb[(ck * 32 + dd) * 8 + h];
    red[tid] = p;
    __syncthreads();
    if (tid < 8) {
        float s = 0.f;
        for (int c2 = 0; c2 < 32; c2++) s += red[c2 * 8 + tid];
        base_s[tid] = s;
    }
    __syncthreads();
    if (tid == 0) {
        int code = 0;
#pragma unroll
        for (int r = 0; r < 4; r++) {
            int ph = 0;
#pragma unroll
            for (int kk = 0; kk < 8; kk++) {
                float sim = 0.f;
#pragma unroll
                for (int hh = 0; hh < 8; hh++) sim += base_s[hh] * rot[r * 64 + hh * 8 + kk];
                if (sim >= 0.f) ph ^= salts[r * 8 + kk];
            }
            code ^= ph;
        }
        g_bucket[m] = code & (NBK - 1);
    }
}

// =====================================================================
// Stable counting sort per batch
// =====================================================================
__global__ void sort_kernel()
{
    int b = blockIdx.x;
    __shared__ int hist[NBK];
    __shared__ int offs[NBK];
    int tid = threadIdx.x;
    if (tid < NBK) hist[tid] = 0;
    __syncthreads();
    const int* bk = g_bucket + b * NSEQ;
    for (int n = tid; n < NSEQ; n += 256) atomicAdd(&hist[bk[n]], 1);
    __syncthreads();
    if (tid == 0) {
        int s = 0;
        for (int i = 0; i < NBK; i++) { offs[i] = s; s += hist[i]; }
    }
    __syncthreads();
    if (tid < NBK) {
        int pos = offs[tid];
        for (int n = 0; n < NSEQ; n++) {
            if (bk[n] == tid) { g_order[b * NSEQ + pos] = n; pos++; }
        }
    }
}

// =====================================================================
// Bucketed attention (SIMT fp32)
// =====================================================================
#define QKPAD 132
#define PPAD  129
#define VPAD  68
#define ATTN_SMEM ((2*64*QKPAD + 128*VPAD) * 4)

__global__ __launch_bounds__(256, 2)
void attn_kernel()
{
    extern __shared__ float smf[];
    float* qT  = smf;
    float* kT  = smf + 64 * QKPAD;
    float* p_s = smf;
    float* v_s = smf + 2 * 64 * QKPAD;
    __shared__ int idx_s[128];

    const int c = blockIdx.x, h = blockIdx.y, b = blockIdx.z;
    const int kvh = h >> 2;
    const int tid = threadIdx.x;
    const int ty = tid >> 4, tx = tid & 15;

    if (tid < 128) idx_s[tid] = g_order[b * NSEQ + c * BUCK + tid];
    __syncthreads();

    const float* gq = g_scratch + OFF_Q;
    const float* gk = g_scratch + OFF_KH;
    const float* gv = g_scratch + OFF_V;

    for (int e = tid; e < 128 * 16; e += 256) {
        int row = e >> 4;
        int c4  = (e & 15) << 2;
        size_t grow = (size_t)(b * NSEQ + idx_s[row]);
        float4 qv = *(const float4*)(gq + grow * 1024 + h * 64 + c4);
        qT[(c4 + 0) * QKPAD + row] = qv.x;
        qT[(c4 + 1) * QKPAD + row] = qv.y;
        qT[(c4 + 2) * QKPAD + row] = qv.z;
        qT[(c4 + 3) * QKPAD + row] = qv.w;
        float4 kv = *(const float4*)(gk + grow * 256 + kvh * 64 + c4);
        kT[(c4 + 0) * QKPAD + row] = kv.x;
        kT[(c4 + 1) * QKPAD + row] = kv.y;
        kT[(c4 + 2) * QKPAD + row] = kv.z;
        kT[(c4 + 3) * QKPAD + row] = kv.w;
        *(float4*)(v_s + row * VPAD + c4) = *(const float4*)(gv + grow * 256 + kvh * 64 + c4);
    }
    __syncthreads();

    float acc[8][8];
#pragma unroll
    for (int i = 0; i < 8; i++)
#pragma unroll
        for (int j = 0; j < 8; j++) acc[i][j] = 0.f;

#pragma unroll 8
    for (int d = 0; d < 64; d++) {
        float a[8], bf[8];
        *(float4*)(a)      = *(const float4*)(qT + d * QKPAD + ty * 8);
        *(float4*)(a + 4)  = *(const float4*)(qT + d * QKPAD + ty * 8 + 4);
        *(float4*)(bf)     = *(const float4*)(kT + d * QKPAD + tx * 8);
        *(float4*)(bf + 4) = *(const float4*)(kT + d * QKPAD + tx * 8 + 4);
#pragma unroll
        for (int i = 0; i < 8; i++)
#pragma unroll
            for (int j = 0; j < 8; j++)
                acc[i][j] += a[i] * bf[j];
    }
    __syncthreads();

    float rowmax[8], rinv[8];
#pragma unroll
    for (int i = 0; i < 8; i++) {
        float m = acc[i][0];
#pragma unroll
        for (int j = 1; j < 8; j++) m = fmaxf(m, acc[i][j]);
#pragma unroll
        for (int off = 8; off >= 1; off >>= 1)
            m = fmaxf(m, __shfl_xor_sync(0xffffffffu, m, off));
        rowmax[i] = m;
    }
#pragma unroll
    for (int i = 0; i < 8; i++) {
        float s = 0.f;
#pragma unroll
        for (int j = 0; j < 8; j++) {
            float e = __expf((acc[i][j] - rowmax[i]) * 0.125f);
            acc[i][j] = e;
            s += e;
        }
#pragma unroll
        for (int off = 8; off >= 1; off >>= 1)
            s += __shfl_xor_sync(0xffffffffu, s, off);
        rinv[i] = 1.f / s;
    }
#pragma unroll
    for (int i = 0; i < 8; i++)
#pragma unroll
        for (int j = 0; j < 8; j++)
            p_s[(ty * 8 + i) * PPAD + tx * 8 + j] = acc[i][j] * rinv[i];
    __syncthreads();

    float o[8][4];
#pragma unroll
    for (int i = 0; i < 8; i++)
#pragma unroll
        for (int k2 = 0; k2 < 4; k2++) o[i][k2] = 0.f;

#pragma unroll 4
    for (int j = 0; j < 128; j++) {
        float4 vv = *(const float4*)(v_s + j * VPAD + tx * 4);
#pragma unroll
        for (int i = 0; i < 8; i++) {
            float p = p_s[(ty * 8 + i) * PPAD + j];
            o[i][0] += p * vv.x;
            o[i][1] += p * vv.y;
            o[i][2] += p * vv.z;
            o[i][3] += p * vv.w;
        }
    }
    float* ga = g_scratch + OFF_ATT;
#pragma unroll
    for (int i = 0; i < 8; i++) {
        int row = ty * 8 + i;
        size_t grow = (size_t)(b * NSEQ + idx_s[row]);
        *(float4*)(ga + grow * 1024 + h * 64 + tx * 4) =
            make_float4(o[i][0], o[i][1], o[i][2], o[i][3]);
    }
}

// =====================================================================
// Host launcher
// =====================================================================
extern "C" void kernel_launch(void* const* d_in, const int* in_sizes, int n_in,
                              void* d_out, int out_size)
{
    const float* x         = (const float*)d_in[0];
    const float* ge_inp_w  = (const float*)d_in[1];
    const float* dw_w      = (const float*)d_in[2];
    const float* dw_b      = (const float*)d_in[3];
    const float* ge_out_w  = (const float*)d_in[4];
    const float* q_w       = (const float*)d_in[5];
    const float* k_w       = (const float*)d_in[6];
    const float* v_w       = (const float*)d_in[7];
    const float* Aq        = (const float*)d_in[8];
    const float* Bq        = (const float*)d_in[9];
    const float* Ak        = (const float*)d_in[10];
    const float* Bk        = (const float*)d_in[11];
    const float* rand_gate = (const float*)d_in[12];
    const float* base_w    = (const float*)d_in[13];
    const float* rot       = (const float*)d_in[14];
    const float* o_w       = (const float*)d_in[16];
    const int*   salts     = (const int*)d_in[17];
    float* out = (float*)d_out;

    float* sc = nullptr;
    cudaGetSymbolAddress((void**)&sc, g_scratch);

    cudaFuncSetAttribute(attn_kernel, cudaFuncAttributeMaxDynamicSharedMemorySize, ATTN_SMEM);
    cudaFuncSetAttribute(gemm_tf32x3, cudaFuncAttributeMaxDynamicSharedMemorySize, SMEM_X3);

    // ---- weight folds ----
    fold_small<<<16, 256>>>(Aq, Bq, Ak, Bk);
    fold_qw<<<1024, 256>>>(q_w, k_w, rand_gate);
    // FQ + FK folds fused in one launch (tf32, smooth path only)
    fold_fused<<<dim3(10, 8), 256>>>(ge_out_w);
    // FBASE fp32 exact (sign-critical)
    fold_base<<<1024, 256>>>(ge_out_w, base_w);

    // ---- activations ----
    // zfull = x @ ge_inp_w  (3xtf32 split — fp32-class accuracy for sign path)
    gemm_tf32x3<<<dim3(16, 64), 256, SMEM_X3>>>(x, 1024, ge_inp_w, 2048, sc + OFF_ZFULL, 2048, 1024);
    conv_silu<<<(MROWS * 1024) / 256, 256>>>(dw_w, dw_b);

    hash_kernel<<<MROWS, 256>>>(rot, salts);
    sort_kernel<<<BB, 256>>>();

    // smooth projections (tf32)
    gemm_tf32<<<dim3(8, 64), 256>>>(sc + OFF_ZM, 1024, sc + OFF_FQ, 1024, sc + OFF_Q, 1024, 1024);
    gemm_tf32<<<dim3(2, 64), 256>>>(sc + OFF_ZM, 1024, sc + OFF_FK, 256, sc + OFF_KRAW, 256, 1024);
    gemm_tf32<<<dim3(2, 64), 256>>>(x, 1024, v_w, 256, sc + OFF_V, 256, 1024);

    haar_kernel<<<(BB * 2048 * 256) / 256, 256>>>();

    attn_kernel<<<dim3(NBK, HH, BB), 256, ATTN_SMEM>>>();

    // out = att @ o_w (tf32)
    gemm_tf32<<<dim3(8, 64), 256>>>(sc + OFF_ATT, 1024, o_w, 1024, out, 1024, 1024);
}

// round 7
// speedup vs baseline: 2.8137x; 1.1796x over previous
#include <cuda_runtime.h>
#include <cstdint>
#include <cstddef>

// ---------------- problem constants ----------------
#define BB    2
#define NSEQ  4096
#define DMOD  1024
#define HH    16
#define HKV   4
#define DHD   64
#define MROWS (BB*NSEQ)          // 8192
#define NBK   32
#define BUCK  128

// ---------------- scratch layout (floats) ----------------
#define OFF_ZFULL 0ull                          // 8192*2048
#define OFF_ZM    (OFF_ZFULL + 16777216ull)     // 8192*1024
#define OFF_Q     (OFF_ZM    + 8388608ull)      // 8192*1024
#define OFF_KRAW  (OFF_Q     + 8388608ull)      // 8192*256
#define OFF_KH    (OFF_KRAW  + 2097152ull)      // 8192*256
#define OFF_V     (OFF_KH    + 2097152ull)      // 8192*256
#define OFF_ATT   (OFF_V     + 2097152ull)      // 8192*1024
#define OFF_QWP   (OFF_ATT   + 8388608ull)      // 1024*1024
#define OFF_KWP   (OFF_QWP   + 1048576ull)      // 1024*256
#define OFF_FQ    (OFF_KWP   + 262144ull)       // 1024*1024
#define OFF_FK    (OFF_FQ    + 1048576ull)      // 1024*256
#define OFF_FBASE (OFF_FK    + 262144ull)       // 1024*8
#define OFF_WQ    (OFF_FBASE + 8192ull)         // 64*64
#define OFF_WK    (OFF_WQ    + 4096ull)         // 64*64
#define SCRATCH_TOTAL (OFF_WK + 4096ull)

__device__ __align__(256) float g_scratch[SCRATCH_TOTAL];
__device__ int g_bucket[MROWS];
__device__ int g_order[MROWS];

// =====================================================================
// tf32 tensor-core GEMM core (proven layout; ldmatrix A-reads;
// vectorized STS.128 writers).
// =====================================================================
#define TBM 128
#define TBN 128
#define TBK 32
#define TAPAD 36
#define TBPAD 132

__device__ __forceinline__ uint32_t f2tf32(float f) {
    uint32_t r;
    asm("cvt.rna.tf32.f32 %0, %1;" : "=r"(r) : "f"(f));
    return r;
}

__device__ __forceinline__ void mma_tf32(float* c, const uint32_t* a, const uint32_t* b) {
    asm volatile(
        "mma.sync.aligned.m16n8k8.row.col.f32.tf32.tf32.f32 "
        "{%0,%1,%2,%3}, {%4,%5,%6,%7}, {%8,%9}, {%0,%1,%2,%3};"
        : "+f"(c[0]), "+f"(c[1]), "+f"(c[2]), "+f"(c[3])
        : "r"(a[0]), "r"(a[1]), "r"(a[2]), "r"(a[3]), "r"(b[0]), "r"(b[1]));
}

__device__ __forceinline__ void ldsm_x4(uint32_t* r, uint32_t addr) {
    asm volatile("ldmatrix.sync.aligned.m8n8.x4.shared.b16 {%0,%1,%2,%3}, [%4];"
                 : "=r"(r[0]), "=r"(r[1]), "=r"(r[2]), "=r"(r[3])
                 : "r"(addr));
}

__device__ __forceinline__ uint4 cvt4(float4 v) {
    return make_uint4(f2tf32(v.x), f2tf32(v.y), f2tf32(v.z), f2tf32(v.w));
}

__device__ __forceinline__
void gemm_tf32_tile(const float* __restrict__ A, int lda,
                    const float* __restrict__ Bm, int ldb,
                    float* __restrict__ C, int ldc, int K,
                    int bm, int bn)
{
    __shared__ __align__(16) uint32_t a_s[TBM * TAPAD];   // [m][k]
    __shared__ __align__(16) uint32_t b_s[TBK * TBPAD];   // [k][n]

    const int tid = threadIdx.x;
    const int warp = tid >> 5, lane = tid & 31;
    const int wm = (warp >> 2) * 64;
    const int wn = (warp & 3) * 32;

    float acc[4][4][4];
#pragma unroll
    for (int i = 0; i < 4; i++)
#pragma unroll
        for (int j = 0; j < 4; j++)
#pragma unroll
            for (int k = 0; k < 4; k++) acc[i][j][k] = 0.f;

    const int lq = lane >> 2;
    const int lr = lane & 3;

    const uint32_t s_a0 = (uint32_t)__cvta_generic_to_shared(a_s);
    const uint32_t a_lm_base =
        s_a0 + (((wm + (lane & 7) + ((lane >> 3) & 1) * 8) * TAPAD + (lane >> 4) * 4) << 2);

    for (int kt = 0; kt < K; kt += TBK) {
#pragma unroll
        for (int u = 0; u < 4; u++) {
            int id = tid + u * 256;
            int r  = id >> 3;
            int kc = (id & 7) << 2;
            float4 v = *(const float4*)(A + (size_t)(bm + r) * lda + kt + kc);
            *(uint4*)(a_s + r * TAPAD + kc) = cvt4(v);
        }
#pragma unroll
        for (int u = 0; u < 4; u++) {
            int id = tid + u * 256;
            int r  = id >> 5;
            int nc = (id & 31) << 2;
            float4 v = *(const float4*)(Bm + (size_t)(kt + r) * ldb + bn + nc);
            *(uint4*)(b_s + r * TBPAD + nc) = cvt4(v);
        }
        __syncthreads();

#pragma unroll
        for (int kk = 0; kk < TBK; kk += 8) {
            uint32_t a[4][4], b[4][2];
#pragma unroll
            for (int mt = 0; mt < 4; mt++)
                ldsm_x4(a[mt], a_lm_base + ((mt * 16 * TAPAD + kk) << 2));
#pragma unroll
            for (int nt = 0; nt < 4; nt++) {
                int cc = wn + nt * 8 + lq;
                b[nt][0] = b_s[(kk + lr) * TBPAD + cc];
                b[nt][1] = b_s[(kk + lr + 4) * TBPAD + cc];
            }
#pragma unroll
            for (int mt = 0; mt < 4; mt++)
#pragma unroll
                for (int nt = 0; nt < 4; nt++)
                    mma_tf32(acc[mt][nt], a[mt], b[nt]);
        }
        __syncthreads();
    }

#pragma unroll
    for (int mt = 0; mt < 4; mt++) {
#pragma unroll
        for (int nt = 0; nt < 4; nt++) {
            int row = bm + wm + mt * 16 + lq;
            int col = bn + wn + nt * 8 + 2 * lr;
            *(float2*)(C + (size_t)row * ldc + col) =
                make_float2(acc[mt][nt][0], acc[mt][nt][1]);
            *(float2*)(C + (size_t)(row + 8) * ldc + col) =
                make_float2(acc[mt][nt][2], acc[mt][nt][3]);
        }
    }
}

__global__ __launch_bounds__(256, 2)
void gemm_tf32(const float* __restrict__ A, int lda,
               const float* __restrict__ Bm, int ldb,
               float* __restrict__ C, int ldc, int K)
{
    gemm_tf32_tile(A, lda, Bm, ldb, C, ldc, K, blockIdx.y * TBM, blockIdx.x * TBN);
}

// Fused fold GEMMs: x<8 -> FQ = GEq@QWP, x>=8 -> FK = GEk@KWP.
__global__ __launch_bounds__(256, 2)
void fold_fused(const float* __restrict__ geo)
{
    const float* A;
    const float* Bm;
    float* C;
    int ldb, ldc, bn;
    if (blockIdx.x < 8) {
        A = geo;            Bm = g_scratch + OFF_QWP; C = g_scratch + OFF_FQ;
        ldb = 1024; ldc = 1024; bn = blockIdx.x * TBN;
    } else {
        A = geo + 1024;     Bm = g_scratch + OFF_KWP; C = g_scratch + OFF_FK;
        ldb = 256;  ldc = 256;  bn = (blockIdx.x - 8) * TBN;
    }
    gemm_tf32_tile(A, 2048, Bm, ldb, C, ldc, 1024, blockIdx.y * TBM, bn);
}

// =====================================================================
// 3xtf32 split GEMM (fp32-class accuracy), ldmatrix A-reads, STS.128.
// =====================================================================
#define X3_ASZ (TBM * TAPAD)
#define X3_BSZ (TBK * TBPAD)
#define SMEM_X3 ((2 * X3_ASZ + 2 * X3_BSZ) * 4)

__global__ __launch_bounds__(256)
void gemm_tf32x3(const float* __restrict__ A, int lda,
                 const float* __restrict__ Bm, int ldb,
                 float* __restrict__ C, int ldc, int K)
{
    extern __shared__ uint32_t smu[];
    uint32_t* Ah = smu;
    uint32_t* Al = smu + X3_ASZ;
    uint32_t* Bh = smu + 2 * X3_ASZ;
    uint32_t* Bl = smu + 2 * X3_ASZ + X3_BSZ;

    const int tid = threadIdx.x;
    const int warp = tid >> 5, lane = tid & 31;
    const int wm = (warp >> 2) * 64;
    const int wn = (warp & 3) * 32;
    const int bm = blockIdx.y * TBM;
    const int bn = blockIdx.x * TBN;

    float acc[4][4][4];
#pragma unroll
    for (int i = 0; i < 4; i++)
#pragma unroll
        for (int j = 0; j < 4; j++)
#pragma unroll
            for (int k = 0; k < 4; k++) acc[i][j][k] = 0.f;

    const int lq = lane >> 2;
    const int lr = lane & 3;

    const uint32_t s_ah0 = (uint32_t)__cvta_generic_to_shared(Ah);
    const uint32_t lm_off =
        (((wm + (lane & 7) + ((lane >> 3) & 1) * 8) * TAPAD + (lane >> 4) * 4) << 2);
    const uint32_t ah_base = s_ah0 + lm_off;
    const uint32_t al_base = ah_base + (X3_ASZ << 2);

    for (int kt = 0; kt < K; kt += TBK) {
#pragma unroll
        for (int u = 0; u < 4; u++) {
            int id = tid + u * 256;
            int r  = id >> 3;
            int kc = (id & 7) << 2;
            float4 v = *(const float4*)(A + (size_t)(bm + r) * lda + kt + kc);
            uint4 hv = cvt4(v);
            uint4 lv = make_uint4(
                f2tf32(v.x - __uint_as_float(hv.x)),
                f2tf32(v.y - __uint_as_float(hv.y)),
                f2tf32(v.z - __uint_as_float(hv.z)),
                f2tf32(v.w - __uint_as_float(hv.w)));
            *(uint4*)(Ah + r * TAPAD + kc) = hv;
            *(uint4*)(Al + r * TAPAD + kc) = lv;
        }
#pragma unroll
        for (int u = 0; u < 4; u++) {
            int id = tid + u * 256;
            int r  = id >> 5;
            int nc = (id & 31) << 2;
            float4 v = *(const float4*)(Bm + (size_t)(kt + r) * ldb + bn + nc);
            uint4 hv = cvt4(v);
            uint4 lv = make_uint4(
                f2tf32(v.x - __uint_as_float(hv.x)),
                f2tf32(v.y - __uint_as_float(hv.y)),
                f2tf32(v.z - __uint_as_float(hv.z)),
                f2tf32(v.w - __uint_as_float(hv.w)));
            *(uint4*)(Bh + r * TBPAD + nc) = hv;
            *(uint4*)(Bl + r * TBPAD + nc) = lv;
        }
        __syncthreads();

#pragma unroll
        for (int kk = 0; kk < TBK; kk += 8) {
            uint32_t ah[4][4], al[4][4], bh[4][2], bl[4][2];
#pragma unroll
            for (int mt = 0; mt < 4; mt++) {
                uint32_t off = (mt * 16 * TAPAD + kk) << 2;
                ldsm_x4(ah[mt], ah_base + off);
                ldsm_x4(al[mt], al_base + off);
            }
#pragma unroll
            for (int nt = 0; nt < 4; nt++) {
                int cc = wn + nt * 8 + lq;
                bh[nt][0] = Bh[(kk + lr) * TBPAD + cc];
                bh[nt][1] = Bh[(kk + lr + 4) * TBPAD + cc];
                bl[nt][0] = Bl[(kk + lr) * TBPAD + cc];
                bl[nt][1] = Bl[(kk + lr + 4) * TBPAD + cc];
            }
#pragma unroll
            for (int mt = 0; mt < 4; mt++)
#pragma unroll
                for (int nt = 0; nt < 4; nt++) {
                    mma_tf32(acc[mt][nt], al[mt], bh[nt]);
                    mma_tf32(acc[mt][nt], ah[mt], bl[nt]);
                    mma_tf32(acc[mt][nt], ah[mt], bh[nt]);
                }
        }
        __syncthreads();
    }

#pragma unroll
    for (int mt = 0; mt < 4; mt++) {
#pragma unroll
        for (int nt = 0; nt < 4; nt++) {
            int row = bm + wm + mt * 16 + lq;
            int col = bn + wn + nt * 8 + 2 * lr;
            *(float2*)(C + (size_t)row * ldc + col) =
                make_float2(acc[mt][nt][0], acc[mt][nt][1]);
            *(float2*)(C + (size_t)(row + 8) * ldc + col) =
                make_float2(acc[mt][nt][2], acc[mt][nt][3]);
        }
    }
}

// =====================================================================
// Weight folds (small)
// =====================================================================
__global__ void fold_small(const float* __restrict__ Aq, const float* __restrict__ Bq,
                           const float* __restrict__ Ak, const float* __restrict__ Bk)
{
    int ij = blockIdx.x * blockDim.x + threadIdx.x;
    int i = ij >> 6, j = ij & 63;
    float sq = 0.f, sk = 0.f;
#pragma unroll
    for (int r = 0; r < 16; r++) {
        sq += Aq[i * 16 + r] * Bq[r * 64 + j];
        sk += Ak[i * 16 + r] * Bk[r * 64 + j];
    }
    g_scratch[OFF_WQ + ij] = sq;
    g_scratch[OFF_WK + ij] = sk;
}

__global__ void fold_qw(const float* __restrict__ qw, const float* __restrict__ kw,
                        const float* __restrict__ rand_gate)
{
    __shared__ float qr[1024];
    __shared__ float kr[256];
    __shared__ float wq_s[4096];
    __shared__ float wk_s[4096];
    int d = blockIdx.x;
    int tid = threadIdx.x;
    for (int i = tid; i < 4096; i += 256) { wq_s[i] = g_scratch[OFF_WQ + i]; wk_s[i] = g_scratch[OFF_WK + i]; }
    for (int i = tid; i < 1024; i += 256) qr[i] = qw[(size_t)d * 1024 + i];
    if (tid < 256) kr[tid] = kw[(size_t)d * 256 + tid];
    __syncthreads();
    for (int c = tid; c < 1024; c += 256) {
        int h = c >> 6, j = c & 63;
        float s = 0.f;
#pragma unroll
        for (int i = 0; i < 64; i++) s += qr[h * 64 + i] * wq_s[i * 64 + j];
        g_scratch[OFF_QWP + (size_t)d * 1024 + c] = s;
    }
    {
        int c = tid;
        int g = c >> 6, j = c & 63;
        float s = 0.f;
#pragma unroll
        for (int i = 0; i < 64; i++) s += kr[g * 64 + i] * wk_s[i * 64 + j];
        g_scratch[OFF_KWP + (size_t)d * 256 + c] = s * tanhf(1.f + rand_gate[j]);
    }
}

// FBASE = GEq @ base_w (fp32 exact — sign-critical)
__global__ void fold_base(const float* __restrict__ ge_out_w,
                          const float* __restrict__ base_w)
{
    int i = blockIdx.x;
    int tid = threadIdx.x;
    __shared__ float red[256];
    const float* a = ge_out_w + (size_t)i * 2048;
    int h = tid & 7, ck = tid >> 3;
    float p = 0.f;
#pragma unroll
    for (int dd = 0; dd < 32; dd++)
        p += a[ck * 32 + dd] * base_w[(ck * 32 + dd) * 8 + h];
    red[tid] = p;
    __syncthreads();
    if (tid < 8) {
        float s = 0.f;
        for (int c2 = 0; c2 < 32; c2++) s += red[c2 * 8 + tid];
        g_scratch[OFF_FBASE + (size_t)i * 8 + tid] = s;
    }
}

// =====================================================================
// conv + SiLU*SiLU gating (precision-critical -> expf)
// =====================================================================
__global__ void conv_silu(const float* __restrict__ dw_w, const float* __restrict__ dw_b)
{
    int gid = blockIdx.x * 256 + threadIdx.x;
    int d   = gid & 1023;
    int row = gid >> 10;
    int n   = row & (NSEQ - 1);
    const float* zr = g_scratch + OFF_ZFULL + (size_t)row * 2048;
    float z0 = (n > 0)        ? zr[-2048 + d] : 0.f;
    float z1 = zr[d];
    float z2 = (n < NSEQ - 1) ? zr[2048 + d] : 0.f;
    float c = z0 * dw_w[d * 3 + 0] + z1 * dw_w[d * 3 + 1] + z2 * dw_w[d * 3 + 2] + dw_b[d];
    float g = zr[1024 + d];
    float sc = c / (1.f + expf(-c));
    float sg = g / (1.f + expf(-g));
    g_scratch[OFF_ZM + (size_t)row * 1024 + d] = sc * sg;
}

// =====================================================================
// Haar mix over sequence pairs
// =====================================================================
__global__ void haar_kernel()
{
    int gid = blockIdx.x * 256 + threadIdx.x;
    int ch = gid & 255;
    int t  = gid >> 8;
    int c  = t & 2047;
    int b  = t >> 11;
    const float* kr = g_scratch + OFF_KRAW;
    float x0 = kr[((size_t)(b * NSEQ + 2 * c)) * 256 + ch];
    float x1 = kr[((size_t)(b * NSEQ + 2 * c + 1)) * 256 + ch];
    float* kh = g_scratch + OFF_KH;
    kh[((size_t)(b * NSEQ + c)) * 256 + ch]        = 0.5f * (x0 + x1);
    kh[((size_t)(b * NSEQ + 2048 + c)) * 256 + ch] = 0.5f * (x0 - x1);
}

// =====================================================================
// LSH hash: base = zm @ FBASE, sign->salt XOR. fp32 exact.
// =====================================================================
__global__ void hash_kernel(const float* __restrict__ rot,
                            const int* __restrict__ salts)
{
    int m = blockIdx.x;
    int tid = threadIdx.x;
    __shared__ float red[256];
    __shared__ float base_s[8];
    const float* zm = g_scratch + OFF_ZM + (size_t)m * 1024;
    const float* fb = g_scratch + OFF_FBASE;
    int h = tid & 7, ck = tid >> 3;
    float p = 0.f;
    const float* zp = zm + ck * 32;
#pragma unroll
    for (int dd = 0; dd < 32; dd++) p += zp[dd] * fb[(ck * 32 + dd) * 8 + h];
    red[tid] = p;
    __syncthreads();
    if (tid < 8) {
        float s = 0.f;
        for (int c2 = 0; c2 < 32; c2++) s += red[c2 * 8 + tid];
        base_s[tid] = s;
    }
    __syncthreads();
    if (tid == 0) {
        int code = 0;
#pragma unroll
        for (int r = 0; r < 4; r++) {
            int ph = 0;
#pragma unroll
            for (int kk = 0; kk < 8; kk++) {
                float sim = 0.f;
#pragma unroll
                for (int hh = 0; hh < 8; hh++) sim += base_s[hh] * rot[r * 64 + hh * 8 + kk];
                if (sim >= 0.f) ph ^= salts[r * 8 + kk];
            }
            code ^= ph;
        }
        g_bucket[m] = code & (NBK - 1);
    }
}

// =====================================================================
// Parallel stable counting sort per batch: 256 threads x 16-elem
// segments; per-(bucket,thread) histogram + scan preserves stability.
// =====================================================================
__global__ void sort_kernel()
{
    int b = blockIdx.x;
    __shared__ int cnt[NBK][257];
    __shared__ int bbase[NBK];
    int tid = threadIdx.x;
#pragma unroll
    for (int bb = 0; bb < NBK; bb++) cnt[bb][tid] = 0;
    __syncthreads();
    const int* bk = g_bucket + b * NSEQ;
    int seg = tid * 16;
    int loc[16];
#pragma unroll
    for (int i = 0; i < 16; i++) {
        loc[i] = bk[seg + i];
        cnt[loc[i]][tid] += 1;
    }
    __syncthreads();
    if (tid < NBK) {
        int s = 0;
        for (int t = 0; t < 256; t++) { int v = cnt[tid][t]; cnt[tid][t] = s; s += v; }
        cnt[tid][256] = s;
    }
    __syncthreads();
    if (tid == 0) {
        int s = 0;
        for (int bb = 0; bb < NBK; bb++) { bbase[bb] = s; s += cnt[bb][256]; }
    }
    __syncthreads();
#pragma unroll
    for (int i = 0; i < 16; i++) {
        int bb = loc[i];
        int pos = bbase[bb] + cnt[bb][tid];
        cnt[bb][tid] = pos + 1 - bbase[bb];
        g_order[b * NSEQ + pos] = seg + i;
    }
}

// =====================================================================
// Tensor-core bucketed attention. One CTA per (bucket, head, batch).
// 8 warps; warp w owns rows w*16..w*16+15 -> softmax is warp-local.
// QK^T and PV via tf32 mma m16n8k8 + ldmatrix A-frags.
// smem: qs[128][72] | ks[64][136] | vs[128][72]; ps[128][132] aliases qs+ks.
// =====================================================================
#define AQ_PAD 72
#define AK_PAD 136
#define AV_PAD 72
#define AP_PAD 132
#define ATTN_SMEM ((128*AQ_PAD + 64*AK_PAD + 128*AV_PAD) * 4)

__global__ __launch_bounds__(256, 2)
void attn_tc()
{
    extern __shared__ __align__(16) uint32_t smw[];
    uint32_t* qs = smw;
    uint32_t* ks = smw + 128 * AQ_PAD;
    uint32_t* vs = smw + 128 * AQ_PAD + 64 * AK_PAD;
    uint32_t* ps = smw;   // aliases qs+ks after QK phase (16896 <= 17920)
    __shared__ int idx_s[128];

    const int c = blockIdx.x, h = blockIdx.y, b = blockIdx.z;
    const int kvh = h >> 2;
    const int tid = threadIdx.x;
    const int warp = tid >> 5, lane = tid & 31;
    const int lq = lane >> 2, lr = lane & 3;
    const int m0 = warp * 16;

    if (tid < 128) idx_s[tid] = g_order[b * NSEQ + c * BUCK + tid];
    __syncthreads();

    const float* gq = g_scratch + OFF_Q;
    const float* gk = g_scratch + OFF_KH;
    const float* gv = g_scratch + OFF_V;

    for (int e = tid; e < 128 * 16; e += 256) {
        int row = e >> 4;
        int c4  = (e & 15) << 2;
        size_t grow = (size_t)(b * NSEQ + idx_s[row]);
        float4 qv = *(const float4*)(gq + grow * 1024 + h * 64 + c4);
        *(uint4*)(qs + row * AQ_PAD + c4) = cvt4(qv);
        float4 kv = *(const float4*)(gk + grow * 256 + kvh * 64 + c4);
        ks[(c4 + 0) * AK_PAD + row] = f2tf32(kv.x);
        ks[(c4 + 1) * AK_PAD + row] = f2tf32(kv.y);
        ks[(c4 + 2) * AK_PAD + row] = f2tf32(kv.z);
        ks[(c4 + 3) * AK_PAD + row] = f2tf32(kv.w);
        float4 vv = *(const float4*)(gv + grow * 256 + kvh * 64 + c4);
        *(uint4*)(vs + row * AV_PAD + c4) = cvt4(vv);
    }
    __syncthreads();

    // ---- QK^T: S[m0..m0+15][0..127] ----
    float acc[16][4];
#pragma unroll
    for (int nt = 0; nt < 16; nt++)
#pragma unroll
        for (int k2 = 0; k2 < 4; k2++) acc[nt][k2] = 0.f;

    const uint32_t lm_row = (uint32_t)(m0 + (lane & 7) + ((lane >> 3) & 1) * 8);
    const uint32_t q_base = (uint32_t)__cvta_generic_to_shared(qs)
                          + ((lm_row * AQ_PAD + (lane >> 4) * 4) << 2);
#pragma unroll
    for (int kk = 0; kk < 64; kk += 8) {
        uint32_t a[4];
        ldsm_x4(a, q_base + (kk << 2));
#pragma unroll
        for (int nt = 0; nt < 16; nt++) {
            uint32_t bf[2];
            bf[0] = ks[(kk + lr) * AK_PAD + nt * 8 + lq];
            bf[1] = ks[(kk + lr + 4) * AK_PAD + nt * 8 + lq];
            mma_tf32(acc[nt], a, bf);
        }
    }

    // ---- warp-local softmax (rows m0+lq and m0+lq+8) ----
    float mx0 = -1e30f, mx1 = -1e30f;
#pragma unroll
    for (int nt = 0; nt < 16; nt++) {
        mx0 = fmaxf(mx0, fmaxf(acc[nt][0], acc[nt][1]));
        mx1 = fmaxf(mx1, fmaxf(acc[nt][2], acc[nt][3]));
    }
    mx0 = fmaxf(mx0, __shfl_xor_sync(0xffffffffu, mx0, 1));
    mx0 = fmaxf(mx0, __shfl_xor_sync(0xffffffffu, mx0, 2));
    mx1 = fmaxf(mx1, __shfl_xor_sync(0xffffffffu, mx1, 1));
    mx1 = fmaxf(mx1, __shfl_xor_sync(0xffffffffu, mx1, 2));
    float s0 = 0.f, s1 = 0.f;
#pragma unroll
    for (int nt = 0; nt < 16; nt++) {
        acc[nt][0] = __expf((acc[nt][0] - mx0) * 0.125f);
        acc[nt][1] = __expf((acc[nt][1] - mx0) * 0.125f);
        acc[nt][2] = __expf((acc[nt][2] - mx1) * 0.125f);
        acc[nt][3] = __expf((acc[nt][3] - mx1) * 0.125f);
        s0 += acc[nt][0] + acc[nt][1];
        s1 += acc[nt][2] + acc[nt][3];
    }
    s0 += __shfl_xor_sync(0xffffffffu, s0, 1);
    s0 += __shfl_xor_sync(0xffffffffu, s0, 2);
    s1 += __shfl_xor_sync(0xffffffffu, s1, 1);
    s1 += __shfl_xor_sync(0xffffffffu, s1, 2);
    const float r0 = 1.f / s0, r1 = 1.f / s1;

    __syncthreads();   // all warps done reading qs/ks -> reuse as ps

    // store P (tf32) in a-operand layout [m][k]
#pragma unroll
    for (int nt = 0; nt < 16; nt++) {
        *(uint2*)(ps + (m0 + lq) * AP_PAD + nt * 8 + 2 * lr) =
            make_uint2(f2tf32(acc[nt][0] * r0), f2tf32(acc[nt][1] * r0));
        *(uint2*)(ps + (m0 + lq + 8) * AP_PAD + nt * 8 + 2 * lr) =
            make_uint2(f2tf32(acc[nt][2] * r1), f2tf32(acc[nt][3] * r1));
    }
    __syncwarp();      // warp reads only its own rows via ldmatrix

    // ---- PV: O[m0..m0+15][0..63] ----
    float o[8][4];
#pragma unroll
    for (int nt = 0; nt < 8; nt++)
#pragma unroll
        for (int k2 = 0; k2 < 4; k2++) o[nt][k2] = 0.f;

    const uint32_t p_base = (uint32_t)__cvta_generic_to_shared(ps)
                          + ((lm_row * AP_PAD + (lane >> 4) * 4) << 2);
#pragma unroll
    for (int kk = 0; kk < 128; kk += 8) {
        uint32_t a[4];
        ldsm_x4(a, p_base + (kk << 2));
#pragma unroll
        for (int nt = 0; nt < 8; nt++) {
            uint32_t bf[2];
            bf[0] = vs[(kk + lr) * AV_PAD + nt * 8 + lq];
            bf[1] = vs[(kk + lr + 4) * AV_PAD + nt * 8 + lq];
            mma_tf32(o[nt], a, bf);
        }
    }

    // scatter back to original token order
    float* ga = g_scratch + OFF_ATT;
    size_t g0 = (size_t)(b * NSEQ + idx_s[m0 + lq]);
    size_t g1 = (size_t)(b * NSEQ + idx_s[m0 + lq + 8]);
#pragma unroll
    for (int nt = 0; nt < 8; nt++) {
        *(float2*)(ga + g0 * 1024 + h * 64 + nt * 8 + 2 * lr) =
            make_float2(o[nt][0], o[nt][1]);
        *(float2*)(ga + g1 * 1024 + h * 64 + nt * 8 + 2 * lr) =
            make_float2(o[nt][2], o[nt][3]);
    }
}

// =====================================================================
// Host launcher
// =====================================================================
extern "C" void kernel_launch(void* const* d_in, const int* in_sizes, int n_in,
                              void* d_out, int out_size)
{
    const float* x         = (const float*)d_in[0];
    const float* ge_inp_w  = (const float*)d_in[1];
    const float* dw_w      = (const float*)d_in[2];
    const float* dw_b      = (const float*)d_in[3];
    const float* ge_out_w  = (const float*)d_in[4];
    const float* q_w       = (const float*)d_in[5];
    const float* k_w       = (const float*)d_in[6];
    const float* v_w       = (const float*)d_in[7];
    const float* Aq        = (const float*)d_in[8];
    const float* Bq        = (const float*)d_in[9];
    const float* Ak        = (const float*)d_in[10];
    const float* Bk        = (const float*)d_in[11];
    const float* rand_gate = (const float*)d_in[12];
    const float* base_w    = (const float*)d_in[13];
    const float* rot       = (const float*)d_in[14];
    const float* o_w       = (const float*)d_in[16];
    const int*   salts     = (const int*)d_in[17];
    float* out = (float*)d_out;

    float* sc = nullptr;
    cudaGetSymbolAddress((void**)&sc, g_scratch);

    cudaFuncSetAttribute(attn_tc, cudaFuncAttributeMaxDynamicSharedMemorySize, ATTN_SMEM);
    cudaFuncSetAttribute(gemm_tf32x3, cudaFuncAttributeMaxDynamicSharedMemorySize, SMEM_X3);

    // ---- weight folds ----
    fold_small<<<16, 256>>>(Aq, Bq, Ak, Bk);
    fold_qw<<<1024, 256>>>(q_w, k_w, rand_gate);
    fold_fused<<<dim3(10, 8), 256>>>(ge_out_w);
    fold_base<<<1024, 256>>>(ge_out_w, base_w);

    // ---- activations ----
    gemm_tf32x3<<<dim3(16, 64), 256, SMEM_X3>>>(x, 1024, ge_inp_w, 2048, sc + OFF_ZFULL, 2048, 1024);
    conv_silu<<<(MROWS * 1024) / 256, 256>>>(dw_w, dw_b);

    hash_kernel<<<MROWS, 256>>>(rot, salts);
    sort_kernel<<<BB, 256>>>();

    // smooth projections (tf32)
    gemm_tf32<<<dim3(8, 64), 256>>>(sc + OFF_ZM, 1024, sc + OFF_FQ, 1024, sc + OFF_Q, 1024, 1024);
    gemm_tf32<<<dim3(2, 64), 256>>>(sc + OFF_ZM, 1024, sc + OFF_FK, 256, sc + OFF_KRAW, 256, 1024);
    gemm_tf32<<<dim3(2, 64), 256>>>(x, 1024, v_w, 256, sc + OFF_V, 256, 1024);

    haar_kernel<<<(BB * 2048 * 256) / 256, 256>>>();

    // tensor-core bucketed attention
    attn_tc<<<dim3(NBK, HH, BB), 256, ATTN_SMEM>>>();

    // out = att @ o_w (tf32)
    gemm_tf32<<<dim3(8, 64), 256>>>(sc + OFF_ATT, 1024, o_w, 1024, out, 1024, 1024);
}

// round 9
// speedup vs baseline: 2.8363x; 1.0080x over previous
#include <cuda_runtime.h>
#include <cstdint>
#include <cstddef>

// ---------------- problem constants ----------------
#define BB    2
#define NSEQ  4096
#define DMOD  1024
#define HH    16
#define HKV   4
#define DHD   64
#define MROWS (BB*NSEQ)          // 8192
#define NBK   32
#define BUCK  128

// ---------------- scratch layout (floats / u32 bit patterns) ----------------
#define OFF_ZFULL 0ull                          // 8192*2048
#define OFF_ZM    (OFF_ZFULL + 16777216ull)     // 8192*1024
#define OFF_Q     (OFF_ZM    + 8388608ull)      // 8192*1024
#define OFF_KRAW  (OFF_Q     + 8388608ull)      // 8192*256
#define OFF_KH    (OFF_KRAW  + 2097152ull)      // 8192*256
#define OFF_V     (OFF_KH    + 2097152ull)      // 8192*256
#define OFF_ATT   (OFF_V     + 2097152ull)      // 8192*1024
#define OFF_QWP   (OFF_ATT   + 8388608ull)      // 1024*1024
#define OFF_KWP   (OFF_QWP   + 1048576ull)      // 1024*256
#define OFF_FQ    (OFF_KWP   + 262144ull)       // 1024*1024
#define OFF_FK    (OFF_FQ    + 1048576ull)      // 1024*256
#define OFF_FBASE (OFF_FK    + 262144ull)       // 1024*8
#define OFF_WQ    (OFF_FBASE + 8192ull)         // 64*64
#define OFF_WK    (OFF_WQ    + 4096ull)         // 64*64
#define OFF_XH    (OFF_WK    + 4096ull)         // 8192*1024 (tf32-hi of x)
#define OFF_XL    (OFF_XH    + 8388608ull)      // 8192*1024 (tf32-lo of x)
#define OFF_GWH   (OFF_XL    + 8388608ull)      // 1024*2048 (tf32-hi of ge_inp_w)
#define OFF_GWL   (OFF_GWH   + 2097152ull)      // 1024*2048 (tf32-lo)
#define SCRATCH_TOTAL (OFF_GWL + 2097152ull)

__device__ __align__(256) float g_scratch[SCRATCH_TOTAL];
__device__ int g_bucket[MROWS];
__device__ int g_order[MROWS];

// =====================================================================
// Shared tf32 helpers
// =====================================================================
#define TBM 128
#define TBN 128
#define TBK 32
#define TAPAD 36
#define TBPAD 132

__device__ __forceinline__ uint32_t f2tf32(float f) {
    uint32_t r;
    asm("cvt.rna.tf32.f32 %0, %1;" : "=r"(r) : "f"(f));
    return r;
}

__device__ __forceinline__ void mma_tf32(float* c, const uint32_t* a, const uint32_t* b) {
    asm volatile(
        "mma.sync.aligned.m16n8k8.row.col.f32.tf32.tf32.f32 "
        "{%0,%1,%2,%3}, {%4,%5,%6,%7}, {%8,%9}, {%0,%1,%2,%3};"
        : "+f"(c[0]), "+f"(c[1]), "+f"(c[2]), "+f"(c[3])
        : "r"(a[0]), "r"(a[1]), "r"(a[2]), "r"(a[3]), "r"(b[0]), "r"(b[1]));
}

__device__ __forceinline__ void ldsm_x4(uint32_t* r, uint32_t addr) {
    asm volatile("ldmatrix.sync.aligned.m8n8.x4.shared.b16 {%0,%1,%2,%3}, [%4];"
                 : "=r"(r[0]), "=r"(r[1]), "=r"(r[2]), "=r"(r[3])
                 : "r"(addr));
}

__device__ __forceinline__ uint4 cvt4(float4 v) {
    return make_uint4(f2tf32(v.x), f2tf32(v.y), f2tf32(v.z), f2tf32(v.w));
}

__device__ __forceinline__ void cpa16(uint32_t dst, const void* src) {
    asm volatile("cp.async.cg.shared.global [%0], [%1], 16;" :: "r"(dst), "l"(src));
}

// =====================================================================
// Plain tf32 GEMM tile (proven R7 path: cvt-in-writer, STS.128, ldmatrix)
// =====================================================================
__device__ __forceinline__
void gemm_tf32_tile(const float* __restrict__ A, int lda,
                    const float* __restrict__ Bm, int ldb,
                    float* __restrict__ C, int ldc, int K,
                    int bm, int bn)
{
    __shared__ __align__(16) uint32_t a_s[TBM * TAPAD];   // [m][k]
    __shared__ __align__(16) uint32_t b_s[TBK * TBPAD];   // [k][n]

    const int tid = threadIdx.x;
    const int warp = tid >> 5, lane = tid & 31;
    const int wm = (warp >> 2) * 64;
    const int wn = (warp & 3) * 32;

    float acc[4][4][4];
#pragma unroll
    for (int i = 0; i < 4; i++)
#pragma unroll
        for (int j = 0; j < 4; j++)
#pragma unroll
            for (int k = 0; k < 4; k++) acc[i][j][k] = 0.f;

    const int lq = lane >> 2;
    const int lr = lane & 3;

    const uint32_t s_a0 = (uint32_t)__cvta_generic_to_shared(a_s);
    const uint32_t a_lm_base =
        s_a0 + (((wm + (lane & 7) + ((lane >> 3) & 1) * 8) * TAPAD + (lane >> 4) * 4) << 2);

    for (int kt = 0; kt < K; kt += TBK) {
#pragma unroll
        for (int u = 0; u < 4; u++) {
            int id = tid + u * 256;
            int r  = id >> 3;
            int kc = (id & 7) << 2;
            float4 v = *(const float4*)(A + (size_t)(bm + r) * lda + kt + kc);
            *(uint4*)(a_s + r * TAPAD + kc) = cvt4(v);
        }
#pragma unroll
        for (int u = 0; u < 4; u++) {
            int id = tid + u * 256;
            int r  = id >> 5;
            int nc = (id & 31) << 2;
            float4 v = *(const float4*)(Bm + (size_t)(kt + r) * ldb + bn + nc);
            *(uint4*)(b_s + r * TBPAD + nc) = cvt4(v);
        }
        __syncthreads();

#pragma unroll
        for (int kk = 0; kk < TBK; kk += 8) {
            uint32_t a[4][4], b[4][2];
#pragma unroll
            for (int mt = 0; mt < 4; mt++)
                ldsm_x4(a[mt], a_lm_base + ((mt * 16 * TAPAD + kk) << 2));
#pragma unroll
            for (int nt = 0; nt < 4; nt++) {
                int cc = wn + nt * 8 + lq;
                b[nt][0] = b_s[(kk + lr) * TBPAD + cc];
                b[nt][1] = b_s[(kk + lr + 4) * TBPAD + cc];
            }
#pragma unroll
            for (int mt = 0; mt < 4; mt++)
#pragma unroll
                for (int nt = 0; nt < 4; nt++)
                    mma_tf32(acc[mt][nt], a[mt], b[nt]);
        }
        __syncthreads();
    }

#pragma unroll
    for (int mt = 0; mt < 4; mt++) {
#pragma unroll
        for (int nt = 0; nt < 4; nt++) {
            int row = bm + wm + mt * 16 + lq;
            int col = bn + wn + nt * 8 + 2 * lr;
            *(float2*)(C + (size_t)row * ldc + col) =
                make_float2(acc[mt][nt][0], acc[mt][nt][1]);
            *(float2*)(C + (size_t)(row + 8) * ldc + col) =
                make_float2(acc[mt][nt][2], acc[mt][nt][3]);
        }
    }
}

__global__ __launch_bounds__(256, 2)
void gemm_tf32(const float* __restrict__ A, int lda,
               const float* __restrict__ Bm, int ldb,
               float* __restrict__ C, int ldc, int K)
{
    gemm_tf32_tile(A, lda, Bm, ldb, C, ldc, K, blockIdx.y * TBM, blockIdx.x * TBN);
}

// Fused fold GEMMs: x<8 -> FQ = GEq@QWP, x>=8 -> FK = GEk@KWP.
__global__ __launch_bounds__(256, 2)
void fold_fused(const float* __restrict__ geo)
{
    const float* A;
    const float* Bm;
    float* C;
    int ldb, ldc, bn;
    if (blockIdx.x < 8) {
        A = geo;            Bm = g_scratch + OFF_QWP; C = g_scratch + OFF_FQ;
        ldb = 1024; ldc = 1024; bn = blockIdx.x * TBN;
    } else {
        A = geo + 1024;     Bm = g_scratch + OFF_KWP; C = g_scratch + OFF_FK;
        ldb = 256;  ldc = 256;  bn = (blockIdx.x - 8) * TBN;
    }
    gemm_tf32_tile(A, 2048, Bm, ldb, C, ldc, 1024, blockIdx.y * TBM, bn);
}

// Fused smooth projections: x<8 -> q = zm@FQ; 8,9 -> kraw = zm@FK; 10,11 -> v = x@v_w.
__global__ __launch_bounds__(256, 2)
void proj_fused(const float* __restrict__ x, const float* __restrict__ v_w)
{
    const float* A;
    const float* Bm;
    float* C;
    int ldb, ldc, bn;
    int bx = blockIdx.x;
    if (bx < 8) {
        A = g_scratch + OFF_ZM; Bm = g_scratch + OFF_FQ; C = g_scratch + OFF_Q;
        ldb = 1024; ldc = 1024; bn = bx * TBN;
    } else if (bx < 10) {
        A = g_scratch + OFF_ZM; Bm = g_scratch + OFF_FK; C = g_scratch + OFF_KRAW;
        ldb = 256;  ldc = 256;  bn = (bx - 8) * TBN;
    } else {
        A = x;                  Bm = v_w;               C = g_scratch + OFF_V;
        ldb = 256;  ldc = 256;  bn = (bx - 10) * TBN;
    }
    gemm_tf32_tile(A, 1024, Bm, ldb, C, ldc, 1024, blockIdx.y * TBM, bn);
}

// =====================================================================
// Pre-split: hi = rna_tf32(v), lo = rna_tf32(v - hi), stored as u32 bits.
// =====================================================================
__global__ void presplit(const float* __restrict__ src,
                         uint32_t* __restrict__ hi, uint32_t* __restrict__ lo)
{
    int g = (blockIdx.x * 256 + threadIdx.x) * 4;
    float4 v = *(const float4*)(src + g);
    uint4 h = cvt4(v);
    uint4 l = make_uint4(
        f2tf32(v.x - __uint_as_float(h.x)),
        f2tf32(v.y - __uint_as_float(h.y)),
        f2tf32(v.z - __uint_as_float(h.z)),
        f2tf32(v.w - __uint_as_float(h.w)));
    *(uint4*)(hi + g) = h;
    *(uint4*)(lo + g) = l;
}

// =====================================================================
// 3xtf32 GEMM, cp.async double-buffered, pre-split operands.
// zfull = x @ ge_inp_w : A [8192,1024] lda=1024, B [1024,2048] ldb=2048,
// C ldc=2048, K=1024. Stage = [Ah|Al|Bh|Bl] = 17664 u32; 2 stages.
// Compute loop identical to the proven R7 x3 inner loop.
// =====================================================================
#define X3P_STAGE 17664
#define SMEM_X3P (2 * X3P_STAGE * 4)   // 141312 B

__global__ __launch_bounds__(256)
void gemm_x3p(const uint32_t* __restrict__ Ahg, const uint32_t* __restrict__ Alg,
              const uint32_t* __restrict__ Bhg, const uint32_t* __restrict__ Blg,
              float* __restrict__ C)
{
    extern __shared__ uint32_t smu[];
    const int tid = threadIdx.x;
    const int warp = tid >> 5, lane = tid & 31;
    const int wm = (warp >> 2) * 64, wn = (warp & 3) * 32;
    const int bm = blockIdx.y * TBM, bn = blockIdx.x * TBN;
    const int lq = lane >> 2, lr = lane & 3;

    const uint32_t smem_base = (uint32_t)__cvta_generic_to_shared(smu);
    const uint32_t lm_off =
        (((wm + (lane & 7) + ((lane >> 3) & 1) * 8) * TAPAD + (lane >> 4) * 4) << 2);

    float acc[4][4][4];
#pragma unroll
    for (int i = 0; i < 4; i++)
#pragma unroll
        for (int j = 0; j < 4; j++)
#pragma unroll
            for (int k = 0; k < 4; k++) acc[i][j][k] = 0.f;

    auto issue_tile = [&](int kt, int stage) {
        uint32_t sb = smem_base + stage * (X3P_STAGE * 4);
#pragma unroll
        for (int u = 0; u < 4; u++) {
            int id = tid + u * 256;
            int r  = id >> 3;
            int kc = (id & 7) << 2;
            size_t asrc = (size_t)(bm + r) * 1024 + kt + kc;
            uint32_t ad = sb + ((r * TAPAD + kc) << 2);
            cpa16(ad, Ahg + asrc);
            cpa16(ad + (4608 << 2), Alg + asrc);
            int rb = id >> 5;
            int nc = (id & 31) << 2;
            size_t bsrc = (size_t)(kt + rb) * 2048 + bn + nc;
            uint32_t bd = sb + ((9216 + rb * TBPAD + nc) << 2);
            cpa16(bd, Bhg + bsrc);
            cpa16(bd + (4224 << 2), Blg + bsrc);
        }
        asm volatile("cp.async.commit_group;" ::: "memory");
    };

    const int nk = 1024 / TBK;   // 32
    issue_tile(0, 0);

    for (int t = 0; t < nk; t++) {
        if (t + 1 < nk) {
            issue_tile((t + 1) * TBK, (t + 1) & 1);
            asm volatile("cp.async.wait_group 1;" ::: "memory");
        } else {
            asm volatile("cp.async.wait_group 0;" ::: "memory");
        }
        __syncthreads();

        const uint32_t* st = smu + (t & 1) * X3P_STAGE;
        const uint32_t* Bh = st + 9216;
        const uint32_t* Bl = st + 9216 + 4224;
        const uint32_t ah_base = smem_base + (t & 1) * (X3P_STAGE * 4) + lm_off;
        const uint32_t al_base = ah_base + (4608 << 2);

#pragma unroll
        for (int kk = 0; kk < TBK; kk += 8) {
            uint32_t ah[4][4], al[4][4], bh[4][2], bl[4][2];
#pragma unroll
            for (int mt = 0; mt < 4; mt++) {
                uint32_t off = (mt * 16 * TAPAD + kk) << 2;
                ldsm_x4(ah[mt], ah_base + off);
                ldsm_x4(al[mt], al_base + off);
            }
#pragma unroll
            for (int nt = 0; nt < 4; nt++) {
                int cc = wn + nt * 8 + lq;
                bh[nt][0] = Bh[(kk + lr) * TBPAD + cc];
                bh[nt][1] = Bh[(kk + lr + 4) * TBPAD + cc];
                bl[nt][0] = Bl[(kk + lr) * TBPAD + cc];
                bl[nt][1] = Bl[(kk + lr + 4) * TBPAD + cc];
            }
#pragma unroll
            for (int mt = 0; mt < 4; mt++)
#pragma unroll
                for (int nt = 0; nt < 4; nt++) {
                    mma_tf32(acc[mt][nt], al[mt], bh[nt]);
                    mma_tf32(acc[mt][nt], ah[mt], bl[nt]);
                    mma_tf32(acc[mt][nt], ah[mt], bh[nt]);
                }
        }
        __syncthreads();
    }

#pragma unroll
    for (int mt = 0; mt < 4; mt++) {
#pragma unroll
        for (int nt = 0; nt < 4; nt++) {
            int row = bm + wm + mt * 16 + lq;
            int col = bn + wn + nt * 8 + 2 * lr;
            *(float2*)(C + (size_t)row * 2048 + col) =
                make_float2(acc[mt][nt][0], acc[mt][nt][1]);
            *(float2*)(C + (size_t)(row + 8) * 2048 + col) =
                make_float2(acc[mt][nt][2], acc[mt][nt][3]);
        }
    }
}

// =====================================================================
// Weight folds (small)
// =====================================================================
__global__ void fold_small(const float* __restrict__ Aq, const float* __restrict__ Bq,
                           const float* __restrict__ Ak, const float* __restrict__ Bk)
{
    int ij = blockIdx.x * blockDim.x + threadIdx.x;
    int i = ij >> 6, j = ij & 63;
    float sq = 0.f, sk = 0.f;
#pragma unroll
    for (int r = 0; r < 16; r++) {
        sq += Aq[i * 16 + r] * Bq[r * 64 + j];
        sk += Ak[i * 16 + r] * Bk[r * 64 + j];
    }
    g_scratch[OFF_WQ + ij] = sq;
    g_scratch[OFF_WK + ij] = sk;
}

__global__ void fold_qw(const float* __restrict__ qw, const float* __restrict__ kw,
                        const float* __restrict__ rand_gate)
{
    __shared__ float qr[1024];
    __shared__ float kr[256];
    __shared__ float wq_s[4096];
    __shared__ float wk_s[4096];
    int d = blockIdx.x;
    int tid = threadIdx.x;
    for (int i = tid; i < 4096; i += 256) { wq_s[i] = g_scratch[OFF_WQ + i]; wk_s[i] = g_scratch[OFF_WK + i]; }
    for (int i = tid; i < 1024; i += 256) qr[i] = qw[(size_t)d * 1024 + i];
    if (tid < 256) kr[tid] = kw[(size_t)d * 256 + tid];
    __syncthreads();
    for (int c = tid; c < 1024; c += 256) {
        int h = c >> 6, j = c & 63;
        float s = 0.f;
#pragma unroll
        for (int i = 0; i < 64; i++) s += qr[h * 64 + i] * wq_s[i * 64 + j];
        g_scratch[OFF_QWP + (size_t)d * 1024 + c] = s;
    }
    {
        int c = tid;
        int g = c >> 6, j = c & 63;
        float s = 0.f;
#pragma unroll
        for (int i = 0; i < 64; i++) s += kr[g * 64 + i] * wk_s[i * 64 + j];
        g_scratch[OFF_KWP + (size_t)d * 256 + c] = s * tanhf(1.f + rand_gate[j]);
    }
}

// FBASE = GEq @ base_w (fp32 exact — sign-critical); float4 A loads.
__global__ void fold_base(const float* __restrict__ ge_out_w,
                          const float* __restrict__ base_w)
{
    int i = blockIdx.x;
    int tid = threadIdx.x;
    __shared__ float red[256];
    const float* a = ge_out_w + (size_t)i * 2048;
    int h = tid & 7, ck = tid >> 3;
    const float4* a4 = (const float4*)(a + ck * 32);
    float p = 0.f;
#pragma unroll
    for (int q4 = 0; q4 < 8; q4++) {
        float4 v = a4[q4];
        const float* bw = base_w + (ck * 32 + q4 * 4) * 8 + h;
        p += v.x * bw[0] + v.y * bw[8] + v.z * bw[16] + v.w * bw[24];
    }
    red[tid] = p;
    __syncthreads();
    if (tid < 8) {
        float s = 0.f;
        for (int c2 = 0; c2 < 32; c2++) s += red[c2 * 8 + tid];
        g_scratch[OFF_FBASE + (size_t)i * 8 + tid] = s;
    }
}

// =====================================================================
// conv + SiLU*SiLU gating (precision-critical -> expf)
// =====================================================================
__global__ void conv_silu(const float* __restrict__ dw_w, const float* __restrict__ dw_b)
{
    int gid = blockIdx.x * 256 + threadIdx.x;
    int d   = gid & 1023;
    int row = gid >> 10;
    int n   = row & (NSEQ - 1);
    const float* zr = g_scratch + OFF_ZFULL + (size_t)row * 2048;
    float z0 = (n > 0)        ? zr[-2048 + d] : 0.f;
    float z1 = zr[d];
    float z2 = (n < NSEQ - 1) ? zr[2048 + d] : 0.f;
    float c = z0 * dw_w[d * 3 + 0] + z1 * dw_w[d * 3 + 1] + z2 * dw_w[d * 3 + 2] + dw_b[d];
    float g = zr[1024 + d];
    float sc = c / (1.f + expf(-c));
    float sg = g / (1.f + expf(-g));
    g_scratch[OFF_ZM + (size_t)row * 1024 + d] = sc * sg;
}

// =====================================================================
// Haar mix over sequence pairs
// =====================================================================
__global__ void haar_kernel()
{
    int gid = blockIdx.x * 256 + threadIdx.x;
    int ch = gid & 255;
    int t  = gid >> 8;
    int c  = t & 2047;
    int b  = t >> 11;
    const float* kr = g_scratch + OFF_KRAW;
    float x0 = kr[((size_t)(b * NSEQ + 2 * c)) * 256 + ch];
    float x1 = kr[((size_t)(b * NSEQ + 2 * c + 1)) * 256 + ch];
    float* kh = g_scratch + OFF_KH;
    kh[((size_t)(b * NSEQ + c)) * 256 + ch]        = 0.5f * (x0 + x1);
    kh[((size_t)(b * NSEQ + 2048 + c)) * 256 + ch] = 0.5f * (x0 - x1);
}

// =====================================================================
// LSH hash: base = zm @ FBASE, sign->salt XOR. fp32 exact.
// =====================================================================
__global__ void hash_kernel(const float* __restrict__ rot,
                            const int* __restrict__ salts)
{
    int m = blockIdx.x;
    int tid = threadIdx.x;
    __shared__ float red[256];
    __shared__ float base_s[8];
    const float* zm = g_scratch + OFF_ZM + (size_t)m * 1024;
    const float* fb = g_scratch + OFF_FBASE;
    int h = tid & 7, ck = tid >> 3;
    float p = 0.f;
    const float* zp = zm + ck * 32;
#pragma unroll
    for (int dd = 0; dd < 32; dd++) p += zp[dd] * fb[(ck * 32 + dd) * 8 + h];
    red[tid] = p;
    __syncthreads();
    if (tid < 8) {
        float s = 0.f;
        for (int c2 = 0; c2 < 32; c2++) s += red[c2 * 8 + tid];
        base_s[tid] = s;
    }
    __syncthreads();
    if (tid == 0) {
        int code = 0;
#pragma unroll
        for (int r = 0; r < 4; r++) {
            int ph = 0;
#pragma unroll
            for (int kk = 0; kk < 8; kk++) {
                float sim = 0.f;
#pragma unroll
                for (int hh = 0; hh < 8; hh++) sim += base_s[hh] * rot[r * 64 + hh * 8 + kk];
                if (sim >= 0.f) ph ^= salts[r * 8 + kk];
            }
            code ^= ph;
        }
        g_bucket[m] = code & (NBK - 1);
    }
}

// =====================================================================
// Parallel stable counting sort per batch
// =====================================================================
__global__ void sort_kernel()
{
    int b = blockIdx.x;
    __shared__ int cnt[NBK][257];
    __shared__ int bbase[NBK];
    int tid = threadIdx.x;
#pragma unroll
    for (int bb = 0; bb < NBK; bb++) cnt[bb][tid] = 0;
    __syncthreads();
    const int* bk = g_bucket + b * NSEQ;
    int seg = tid * 16;
    int loc[16];
#pragma unroll
    for (int i = 0; i < 16; i++) {
        loc[i] = bk[seg + i];
        cnt[loc[i]][tid] += 1;
    }
    __syncthreads();
    if (tid < NBK) {
        int s = 0;
        for (int t = 0; t < 256; t++) { int v = cnt[tid][t]; cnt[tid][t] = s; s += v; }
        cnt[tid][256] = s;
    }
    __syncthreads();
    if (tid == 0) {
        int s = 0;
        for (int bb = 0; bb < NBK; bb++) { bbase[bb] = s; s += cnt[bb][256]; }
    }
    __syncthreads();
#pragma unroll
    for (int i = 0; i < 16; i++) {
        int bb = loc[i];
        int pos = bbase[bb] + cnt[bb][tid];
        cnt[bb][tid] = pos + 1 - bbase[bb];
        g_order[b * NSEQ + pos] = seg + i;
    }
}

// =====================================================================
// Tensor-core bucketed attention (proven R7)
// =====================================================================
#define AQ_PAD 72
#define AK_PAD 136
#define AV_PAD 72
#define AP_PAD 132
#define ATTN_SMEM ((128*AQ_PAD + 64*AK_PAD + 128*AV_PAD) * 4)

__global__ __launch_bounds__(256, 2)
void attn_tc()
{
    extern __shared__ __align__(16) uint32_t smw[];
    uint32_t* qs = smw;
    uint32_t* ks = smw + 128 * AQ_PAD;
    uint32_t* vs = smw + 128 * AQ_PAD + 64 * AK_PAD;
    uint32_t* ps = smw;
    __shared__ int idx_s[128];

    const int c = blockIdx.x, h = blockIdx.y, b = blockIdx.z;
    const int kvh = h >> 2;
    const int tid = threadIdx.x;
    const int warp = tid >> 5, lane = tid & 31;
    const int lq = lane >> 2, lr = lane & 3;
    const int m0 = warp * 16;

    if (tid < 128) idx_s[tid] = g_order[b * NSEQ + c * BUCK + tid];
    __syncthreads();

    const float* gq = g_scratch + OFF_Q;
    const float* gk = g_scratch + OFF_KH;
    const float* gv = g_scratch + OFF_V;

    for (int e = tid; e < 128 * 16; e += 256) {
        int row = e >> 4;
        int c4  = (e & 15) << 2;
        size_t grow = (size_t)(b * NSEQ + idx_s[row]);
        float4 qv = *(const float4*)(gq + grow * 1024 + h * 64 + c4);
        *(uint4*)(qs + row * AQ_PAD + c4) = cvt4(qv);
        float4 kv = *(const float4*)(gk + grow * 256 + kvh * 64 + c4);
        ks[(c4 + 0) * AK_PAD + row] = f2tf32(kv.x);
        ks[(c4 + 1) * AK_PAD + row] = f2tf32(kv.y);
        ks[(c4 + 2) * AK_PAD + row] = f2tf32(kv.z);
        ks[(c4 + 3) * AK_PAD + row] = f2tf32(kv.w);
        float4 vv = *(const float4*)(gv + grow * 256 + kvh * 64 + c4);
        *(uint4*)(vs + row * AV_PAD + c4) = cvt4(vv);
    }
    __syncthreads();

    float acc[16][4];
#pragma unroll
    for (int nt = 0; nt < 16; nt++)
#pragma unroll
        for (int k2 = 0; k2 < 4; k2++) acc[nt][k2] = 0.f;

    const uint32_t lm_row = (uint32_t)(m0 + (lane & 7) + ((lane >> 3) & 1) * 8);
    const uint32_t q_base = (uint32_t)__cvta_generic_to_shared(qs)
                          + ((lm_row * AQ_PAD + (lane >> 4) * 4) << 2);
#pragma unroll
    for (int kk = 0; kk < 64; kk += 8) {
        uint32_t a[4];
        ldsm_x4(a, q_base + (kk << 2));
#pragma unroll
        for (int nt = 0; nt < 16; nt++) {
            uint32_t bf[2];
            bf[0] = ks[(kk + lr) * AK_PAD + nt * 8 + lq];
            bf[1] = ks[(kk + lr + 4) * AK_PAD + nt * 8 + lq];
            mma_tf32(acc[nt], a, bf);
        }
    }

    float mx0 = -1e30f, mx1 = -1e30f;
#pragma unroll
    for (int nt = 0; nt < 16; nt++) {
        mx0 = fmaxf(mx0, fmaxf(acc[nt][0], acc[nt][1]));
        mx1 = fmaxf(mx1, fmaxf(acc[nt][2], acc[nt][3]));
    }
    mx0 = fmaxf(mx0, __shfl_xor_sync(0xffffffffu, mx0, 1));
    mx0 = fmaxf(mx0, __shfl_xor_sync(0xffffffffu, mx0, 2));
    mx1 = fmaxf(mx1, __shfl_xor_sync(0xffffffffu, mx1, 1));
    mx1 = fmaxf(mx1, __shfl_xor_sync(0xffffffffu, mx1, 2));
    float s0 = 0.f, s1 = 0.f;
#pragma unroll
    for (int nt = 0; nt < 16; nt++) {
        acc[nt][0] = __expf((acc[nt][0] - mx0) * 0.125f);
        acc[nt][1] = __expf((acc[nt][1] - mx0) * 0.125f);
        acc[nt][2] = __expf((acc[nt][2] - mx1) * 0.125f);
        acc[nt][3] = __expf((acc[nt][3] - mx1) * 0.125f);
        s0 += acc[nt][0] + acc[nt][1];
        s1 += acc[nt][2] + acc[nt][3];
    }
    s0 += __shfl_xor_sync(0xffffffffu, s0, 1);
    s0 += __shfl_xor_sync(0xffffffffu, s0, 2);
    s1 += __shfl_xor_sync(0xffffffffu, s1, 1);
    s1 += __shfl_xor_sync(0xffffffffu, s1, 2);
    const float r0 = 1.f / s0, r1 = 1.f / s1;

    __syncthreads();

#pragma unroll
    for (int nt = 0; nt < 16; nt++) {
        *(uint2*)(ps + (m0 + lq) * AP_PAD + nt * 8 + 2 * lr) =
            make_uint2(f2tf32(acc[nt][0] * r0), f2tf32(acc[nt][1] * r0));
        *(uint2*)(ps + (m0 + lq + 8) * AP_PAD + nt * 8 + 2 * lr) =
            make_uint2(f2tf32(acc[nt][2] * r1), f2tf32(acc[nt][3] * r1));
    }
    __syncwarp();

    float o[8][4];
#pragma unroll
    for (int nt = 0; nt < 8; nt++)
#pragma unroll
        for (int k2 = 0; k2 < 4; k2++) o[nt][k2] = 0.f;

    const uint32_t p_base = (uint32_t)__cvta_generic_to_shared(ps)
                          + ((lm_row * AP_PAD + (lane >> 4) * 4) << 2);
#pragma unroll
    for (int kk = 0; kk < 128; kk += 8) {
        uint32_t a[4];
        ldsm_x4(a, p_base + (kk << 2));
#pragma unroll
        for (int nt = 0; nt < 8; nt++) {
            uint32_t bf[2];
            bf[0] = vs[(kk + lr) * AV_PAD + nt * 8 + lq];
            bf[1] = vs[(kk + lr + 4) * AV_PAD + nt * 8 + lq];
            mma_tf32(o[nt], a, bf);
        }
    }

    float* ga = g_scratch + OFF_ATT;
    size_t g0 = (size_t)(b * NSEQ + idx_s[m0 + lq]);
    size_t g1 = (size_t)(b * NSEQ + idx_s[m0 + lq + 8]);
#pragma unroll
    for (int nt = 0; nt < 8; nt++) {
        *(float2*)(ga + g0 * 1024 + h * 64 + nt * 8 + 2 * lr) =
            make_float2(o[nt][0], o[nt][1]);
        *(float2*)(ga + g1 * 1024 + h * 64 + nt * 8 + 2 * lr) =
            make_float2(o[nt][2], o[nt][3]);
    }
}

// =====================================================================
// Host launcher
// =====================================================================
extern "C" void kernel_launch(void* const* d_in, const int* in_sizes, int n_in,
                              void* d_out, int out_size)
{
    const float* x         = (const float*)d_in[0];
    const float* ge_inp_w  = (const float*)d_in[1];
    const float* dw_w      = (const float*)d_in[2];
    const float* dw_b      = (const float*)d_in[3];
    const float* ge_out_w  = (const float*)d_in[4];
    const float* q_w       = (const float*)d_in[5];
    const float* k_w       = (const float*)d_in[6];
    const float* v_w       = (const float*)d_in[7];
    const float* Aq        = (const float*)d_in[8];
    const float* Bq        = (const float*)d_in[9];
    const float* Ak        = (const float*)d_in[10];
    const float* Bk        = (const float*)d_in[11];
    const float* rand_gate = (const float*)d_in[12];
    const float* base_w    = (const float*)d_in[13];
    const float* rot       = (const float*)d_in[14];
    const float* o_w       = (const float*)d_in[16];
    const int*   salts     = (const int*)d_in[17];
    float* out = (float*)d_out;

    float* sc = nullptr;
    cudaGetSymbolAddress((void**)&sc, g_scratch);
    uint32_t* xh  = (uint32_t*)(sc + OFF_XH);
    uint32_t* xl  = (uint32_t*)(sc + OFF_XL);
    uint32_t* gwh = (uint32_t*)(sc + OFF_GWH);
    uint32_t* gwl = (uint32_t*)(sc + OFF_GWL);

    cudaFuncSetAttribute(attn_tc, cudaFuncAttributeMaxDynamicSharedMemorySize, ATTN_SMEM);
    cudaFuncSetAttribute(gemm_x3p, cudaFuncAttributeMaxDynamicSharedMemorySize, SMEM_X3P);

    // ---- pre-split x3 operands ----
    presplit<<<8192, 256>>>(x, xh, xl);
    presplit<<<2048, 256>>>(ge_inp_w, gwh, gwl);

    // ---- weight folds ----
    fold_small<<<16, 256>>>(Aq, Bq, Ak, Bk);
    fold_qw<<<1024, 256>>>(q_w, k_w, rand_gate);
    fold_fused<<<dim3(10, 8), 256>>>(ge_out_w);
    fold_base<<<1024, 256>>>(ge_out_w, base_w);

    // ---- activations ----
    // zfull = x @ ge_inp_w  (3xtf32, cp.async pipelined)
    gemm_x3p<<<dim3(16, 64), 256, SMEM_X3P>>>(xh, xl, gwh, gwl, sc + OFF_ZFULL);
    conv_silu<<<(MROWS * 1024) / 256, 256>>>(dw_w, dw_b);

    hash_kernel<<<MROWS, 256>>>(rot, salts);
    sort_kernel<<<BB, 256>>>();

    // smooth projections fused (q, kraw, v)
    proj_fused<<<dim3(12, 64), 256>>>(x, v_w);

    haar_kernel<<<(BB * 2048 * 256) / 256, 256>>>();

    attn_tc<<<dim3(NBK, HH, BB), 256, ATTN_SMEM>>>();

    // out = att @ o_w (tf32)
    gemm_tf32<<<dim3(8, 64), 256>>>(sc + OFF_ATT, 1024, o_w, 1024, out, 1024, 1024);
}

// round 12
// speedup vs baseline: 2.8824x; 1.0162x over previous
#include <cuda_runtime.h>
#include <cstdint>
#include <cstddef>

// ---------------- problem constants ----------------
#define BB    2
#define NSEQ  4096
#define DMOD  1024
#define HH    16
#define HKV   4
#define DHD   64
#define MROWS (BB*NSEQ)          // 8192
#define NBK   32
#define BUCK  128

// ---------------- scratch layout (floats / u32 bit patterns) ----------------
#define OFF_ZFULL 0ull                          // 8192*2048
#define OFF_ZM    (OFF_ZFULL + 16777216ull)     // 8192*1024
#define OFF_Q     (OFF_ZM    + 8388608ull)      // 8192*1024
#define OFF_KRAW  (OFF_Q     + 8388608ull)      // 8192*256
#define OFF_KH    (OFF_KRAW  + 2097152ull)      // 8192*256
#define OFF_V     (OFF_KH    + 2097152ull)      // 8192*256
#define OFF_ATT   (OFF_V     + 2097152ull)      // 8192*1024
#define OFF_QWP   (OFF_ATT   + 8388608ull)      // 1024*1024
#define OFF_KWP   (OFF_QWP   + 1048576ull)      // 1024*256
#define OFF_FQ    (OFF_KWP   + 262144ull)       // 1024*1024
#define OFF_FK    (OFF_FQ    + 1048576ull)      // 1024*256
#define OFF_FBASE (OFF_FK    + 262144ull)       // 1024*8
#define OFF_XH    (OFF_FBASE + 8192ull)         // 8192*1024 (tf32-hi of x)
#define OFF_XL    (OFF_XH    + 8388608ull)      // 8192*1024 (tf32-lo of x)
#define OFF_GWH   (OFF_XL    + 8388608ull)      // 1024*2048 (tf32-hi of ge_inp_w)
#define OFF_GWL   (OFF_GWH   + 2097152ull)      // 1024*2048 (tf32-lo)
#define SCRATCH_TOTAL (OFF_GWL + 2097152ull)

__device__ __align__(256) float g_scratch[SCRATCH_TOTAL];
__device__ int g_bucket[MROWS];
__device__ int g_order[MROWS];

// =====================================================================
// Shared tf32 helpers
// =====================================================================
#define TBM 128
#define TBN 128
#define TBK 32
#define TAPAD 36
#define TBPAD 132

__device__ __forceinline__ uint32_t f2tf32(float f) {
    uint32_t r;
    asm("cvt.rna.tf32.f32 %0, %1;" : "=r"(r) : "f"(f));
    return r;
}

__device__ __forceinline__ void mma_tf32(float* c, const uint32_t* a, const uint32_t* b) {
    asm volatile(
        "mma.sync.aligned.m16n8k8.row.col.f32.tf32.tf32.f32 "
        "{%0,%1,%2,%3}, {%4,%5,%6,%7}, {%8,%9}, {%0,%1,%2,%3};"
        : "+f"(c[0]), "+f"(c[1]), "+f"(c[2]), "+f"(c[3])
        : "r"(a[0]), "r"(a[1]), "r"(a[2]), "r"(a[3]), "r"(b[0]), "r"(b[1]));
}

__device__ __forceinline__ void ldsm_x4(uint32_t* r, uint32_t addr) {
    asm volatile("ldmatrix.sync.aligned.m8n8.x4.shared.b16 {%0,%1,%2,%3}, [%4];"
                 : "=r"(r[0]), "=r"(r[1]), "=r"(r[2]), "=r"(r[3])
                 : "r"(addr));
}

__device__ __forceinline__ uint4 cvt4(float4 v) {
    return make_uint4(f2tf32(v.x), f2tf32(v.y), f2tf32(v.z), f2tf32(v.w));
}

__device__ __forceinline__ void cpa16(uint32_t dst, const void* src) {
    asm volatile("cp.async.cg.shared.global [%0], [%1], 16;" :: "r"(dst), "l"(src));
}

// =====================================================================
// Plain tf32 GEMM tile (proven: cvt-in-writer, STS.128, ldmatrix A-reads)
// =====================================================================
__device__ __forceinline__
void gemm_tf32_tile(const float* __restrict__ A, int lda,
                    const float* __restrict__ Bm, int ldb,
                    float* __restrict__ C, int ldc, int K,
                    int bm, int bn)
{
    __shared__ __align__(16) uint32_t a_s[TBM * TAPAD];   // [m][k]
    __shared__ __align__(16) uint32_t b_s[TBK * TBPAD];   // [k][n]

    const int tid = threadIdx.x;
    const int warp = tid >> 5, lane = tid & 31;
    const int wm = (warp >> 2) * 64;
    const int wn = (warp & 3) * 32;

    float acc[4][4][4];
#pragma unroll
    for (int i = 0; i < 4; i++)
#pragma unroll
        for (int j = 0; j < 4; j++)
#pragma unroll
            for (int k = 0; k < 4; k++) acc[i][j][k] = 0.f;

    const int lq = lane >> 2;
    const int lr = lane & 3;

    const uint32_t s_a0 = (uint32_t)__cvta_generic_to_shared(a_s);
    const uint32_t a_lm_base =
        s_a0 + (((wm + (lane & 7) + ((lane >> 3) & 1) * 8) * TAPAD + (lane >> 4) * 4) << 2);

    for (int kt = 0; kt < K; kt += TBK) {
#pragma unroll
        for (int u = 0; u < 4; u++) {
            int id = tid + u * 256;
            int r  = id >> 3;
            int kc = (id & 7) << 2;
            float4 v = *(const float4*)(A + (size_t)(bm + r) * lda + kt + kc);
            *(uint4*)(a_s + r * TAPAD + kc) = cvt4(v);
        }
#pragma unroll
        for (int u = 0; u < 4; u++) {
            int id = tid + u * 256;
            int r  = id >> 5;
            int nc = (id & 31) << 2;
            float4 v = *(const float4*)(Bm + (size_t)(kt + r) * ldb + bn + nc);
            *(uint4*)(b_s + r * TBPAD + nc) = cvt4(v);
        }
        __syncthreads();

#pragma unroll
        for (int kk = 0; kk < TBK; kk += 8) {
            uint32_t a[4][4], b[4][2];
#pragma unroll
            for (int mt = 0; mt < 4; mt++)
                ldsm_x4(a[mt], a_lm_base + ((mt * 16 * TAPAD + kk) << 2));
#pragma unroll
            for (int nt = 0; nt < 4; nt++) {
                int cc = wn + nt * 8 + lq;
                b[nt][0] = b_s[(kk + lr) * TBPAD + cc];
                b[nt][1] = b_s[(kk + lr + 4) * TBPAD + cc];
            }
#pragma unroll
            for (int mt = 0; mt < 4; mt++)
#pragma unroll
                for (int nt = 0; nt < 4; nt++)
                    mma_tf32(acc[mt][nt], a[mt], b[nt]);
        }
        __syncthreads();
    }

#pragma unroll
    for (int mt = 0; mt < 4; mt++) {
#pragma unroll
        for (int nt = 0; nt < 4; nt++) {
            int row = bm + wm + mt * 16 + lq;
            int col = bn + wn + nt * 8 + 2 * lr;
            *(float2*)(C + (size_t)row * ldc + col) =
                make_float2(acc[mt][nt][0], acc[mt][nt][1]);
            *(float2*)(C + (size_t)(row + 8) * ldc + col) =
                make_float2(acc[mt][nt][2], acc[mt][nt][3]);
        }
    }
}

__global__ __launch_bounds__(256, 2)
void gemm_tf32(const float* __restrict__ A, int lda,
               const float* __restrict__ Bm, int ldb,
               float* __restrict__ C, int ldc, int K)
{
    gemm_tf32_tile(A, lda, Bm, ldb, C, ldc, K, blockIdx.y * TBM, blockIdx.x * TBN);
}

// Fused smooth projections: x<8 -> q = zm@FQ; 8,9 -> kraw = zm@FK; 10,11 -> v = x@v_w.
__global__ __launch_bounds__(256, 2)
void proj_fused(const float* __restrict__ x, const float* __restrict__ v_w)
{
    const float* A;
    const float* Bm;
    float* C;
    int ldb, ldc, bn;
    int bx = blockIdx.x;
    if (bx < 8) {
        A = g_scratch + OFF_ZM; Bm = g_scratch + OFF_FQ; C = g_scratch + OFF_Q;
        ldb = 1024; ldc = 1024; bn = bx * TBN;
    } else if (bx < 10) {
        A = g_scratch + OFF_ZM; Bm = g_scratch + OFF_FK; C = g_scratch + OFF_KRAW;
        ldb = 256;  ldc = 256;  bn = (bx - 8) * TBN;
    } else {
        A = x;                  Bm = v_w;               C = g_scratch + OFF_V;
        ldb = 256;  ldc = 256;  bn = (bx - 10) * TBN;
    }
    gemm_tf32_tile(A, 1024, Bm, ldb, C, ldc, 1024, blockIdx.y * TBM, bn);
}

// =====================================================================
// Pre-split: hi = rna_tf32(v), lo = rna_tf32(v - hi), stored as u32 bits.
// =====================================================================
__global__ void presplit(const float* __restrict__ src,
                         uint32_t* __restrict__ hi, uint32_t* __restrict__ lo)
{
    int g = (blockIdx.x * 256 + threadIdx.x) * 4;
    float4 v = *(const float4*)(src + g);
    uint4 h = cvt4(v);
    uint4 l = make_uint4(
        f2tf32(v.x - __uint_as_float(h.x)),
        f2tf32(v.y - __uint_as_float(h.y)),
        f2tf32(v.z - __uint_as_float(h.z)),
        f2tf32(v.w - __uint_as_float(h.w)));
    *(uint4*)(hi + g) = h;
    *(uint4*)(lo + g) = l;
}

// =====================================================================
// fold_qw merged with fold_small: each block recomputes Wq=Aq@Bq,
// Wk=Ak@Bk (64x64, same FP order as before) into smem, then folds.
// =====================================================================
__global__ void fold_qw2(const float* __restrict__ qw, const float* __restrict__ kw,
                         const float* __restrict__ Aq, const float* __restrict__ Bq,
                         const float* __restrict__ Ak, const float* __restrict__ Bk,
                         const float* __restrict__ rand_gate)
{
    __shared__ float qr[1024];
    __shared__ float kr[256];
    __shared__ float wq_s[4096];
    __shared__ float wk_s[4096];
    int d = blockIdx.x;
    int tid = threadIdx.x;
#pragma unroll
    for (int t = 0; t < 16; t++) {
        int ij = tid + t * 256;
        int i = ij >> 6, j = ij & 63;
        float sq = 0.f, sk = 0.f;
#pragma unroll
        for (int r = 0; r < 16; r++) {
            sq += Aq[i * 16 + r] * Bq[r * 64 + j];
            sk += Ak[i * 16 + r] * Bk[r * 64 + j];
        }
        wq_s[ij] = sq;
        wk_s[ij] = sk;
    }
    for (int i = tid; i < 1024; i += 256) qr[i] = qw[(size_t)d * 1024 + i];
    if (tid < 256) kr[tid] = kw[(size_t)d * 256 + tid];
    __syncthreads();
    for (int c = tid; c < 1024; c += 256) {
        int h = c >> 6, j = c & 63;
        float s = 0.f;
#pragma unroll
        for (int i = 0; i < 64; i++) s += qr[h * 64 + i] * wq_s[i * 64 + j];
        g_scratch[OFF_QWP + (size_t)d * 1024 + c] = s;
    }
    {
        int c = tid;
        int g = c >> 6, j = c & 63;
        float s = 0.f;
#pragma unroll
        for (int i = 0; i < 64; i++) s += kr[g * 64 + i] * wk_s[i * 64 + j];
        g_scratch[OFF_KWP + (size_t)d * 256 + c] = s * tanhf(1.f + rand_gate[j]);
    }
}

// =====================================================================
// fold_base body (fp32 exact — sign-critical), one row per call.
// =====================================================================
__device__ __forceinline__
void fold_base_row(const float* __restrict__ ge_out_w,
                   const float* __restrict__ base_w, int i, float* red)
{
    int tid = threadIdx.x;
    const float* a = ge_out_w + (size_t)i * 2048;
    int h = tid & 7, ck = tid >> 3;
    const float4* a4 = (const float4*)(a + ck * 32);
    float p = 0.f;
#pragma unroll
    for (int q4 = 0; q4 < 8; q4++) {
        float4 v = a4[q4];
        const float* bw = base_w + (ck * 32 + q4 * 4) * 8 + h;
        p += v.x * bw[0] + v.y * bw[8] + v.z * bw[16] + v.w * bw[24];
    }
    red[tid] = p;
    __syncthreads();
    if (tid < 8) {
        float s = 0.f;
        for (int c2 = 0; c2 < 32; c2++) s += red[c2 * 8 + tid];
        g_scratch[OFF_FBASE + (size_t)i * 8 + tid] = s;
    }
    __syncthreads();
}

// =====================================================================
// Fused big kernel: z=0 plane -> zfull 3xtf32 cp.async GEMM (unchanged),
// z=1 plane -> fold GEMMs (FQ/FK) + fold_base, hidden under zfull waves.
// =====================================================================
#define X3P_STAGE 17664
#define SMEM_X3P (2 * X3P_STAGE * 4)   // 141312 B dynamic (+ ~35KB static tile smem)

__global__ __launch_bounds__(256)
void zfull_folds(const uint32_t* __restrict__ Ahg, const uint32_t* __restrict__ Alg,
                 const uint32_t* __restrict__ Bhg, const uint32_t* __restrict__ Blg,
                 float* __restrict__ C,
                 const float* __restrict__ geo, const float* __restrict__ base_w)
{
    extern __shared__ uint32_t smu[];

    if (blockIdx.z == 1) {
        int f = blockIdx.y * 16 + blockIdx.x;     // 0..1023
        if (f < 64) {
            gemm_tf32_tile(geo, 2048, g_scratch + OFF_QWP, 1024,
                           g_scratch + OFF_FQ, 1024, 1024, (f >> 3) * TBM, (f & 7) * TBN);
        } else if (f < 80) {
            int g = f - 64;
            gemm_tf32_tile(geo + 1024, 2048, g_scratch + OFF_KWP, 256,
                           g_scratch + OFF_FK, 256, 1024, (g >> 1) * TBM, (g & 1) * TBN);
        } else if (f < 592) {
            __shared__ float red[256];
            int i0 = (f - 80) * 2;
            fold_base_row(geo, base_w, i0, red);
            fold_base_row(geo, base_w, i0 + 1, red);
        }
        return;
    }

    // ---- z == 0: zfull 3xtf32 (proven R9 path) ----
    const int tid = threadIdx.x;
    const int warp = tid >> 5, lane = tid & 31;
    const int wm = (warp >> 2) * 64, wn = (warp & 3) * 32;
    const int bm = blockIdx.y * TBM, bn = blockIdx.x * TBN;
    const int lq = lane >> 2, lr = lane & 3;

    const uint32_t smem_base = (uint32_t)__cvta_generic_to_shared(smu);
    const uint32_t lm_off =
        (((wm + (lane & 7) + ((lane >> 3) & 1) * 8) * TAPAD + (lane >> 4) * 4) << 2);

    float acc[4][4][4];
#pragma unroll
    for (int i = 0; i < 4; i++)
#pragma unroll
        for (int j = 0; j < 4; j++)
#pragma unroll
            for (int k = 0; k < 4; k++) acc[i][j][k] = 0.f;

    auto issue_tile = [&](int kt, int stage) {
        uint32_t sb = smem_base + stage * (X3P_STAGE * 4);
#pragma unroll
        for (int u = 0; u < 4; u++) {
            int id = tid + u * 256;
            int r  = id >> 3;
            int kc = (id & 7) << 2;
            size_t asrc = (size_t)(bm + r) * 1024 + kt + kc;
            uint32_t ad = sb + ((r * TAPAD + kc) << 2);
            cpa16(ad, Ahg + asrc);
            cpa16(ad + (4608 << 2), Alg + asrc);
            int rb = id >> 5;
            int nc = (id & 31) << 2;
            size_t bsrc = (size_t)(kt + rb) * 2048 + bn + nc;
            uint32_t bd = sb + ((9216 + rb * TBPAD + nc) << 2);
            cpa16(bd, Bhg + bsrc);
            cpa16(bd + (4224 << 2), Blg + bsrc);
        }
        asm volatile("cp.async.commit_group;" ::: "memory");
    };

    const int nk = 1024 / TBK;   // 32
    issue_tile(0, 0);

    for (int t = 0; t < nk; t++) {
        if (t + 1 < nk) {
            issue_tile((t + 1) * TBK, (t + 1) & 1);
            asm volatile("cp.async.wait_group 1;" ::: "memory");
        } else {
            asm volatile("cp.async.wait_group 0;" ::: "memory");
        }
        __syncthreads();

        const uint32_t* st = smu + (t & 1) * X3P_STAGE;
        const uint32_t* Bh = st + 9216;
        const uint32_t* Bl = st + 9216 + 4224;
        const uint32_t ah_base = smem_base + (t & 1) * (X3P_STAGE * 4) + lm_off;
        const uint32_t al_base = ah_base + (4608 << 2);

#pragma unroll
        for (int kk = 0; kk < TBK; kk += 8) {
            uint32_t ah[4][4], al[4][4], bh[4][2], bl[4][2];
#pragma unroll
            for (int mt = 0; mt < 4; mt++) {
                uint32_t off = (mt * 16 * TAPAD + kk) << 2;
                ldsm_x4(ah[mt], ah_base + off);
                ldsm_x4(al[mt], al_base + off);
            }
#pragma unroll
            for (int nt = 0; nt < 4; nt++) {
                int cc = wn + nt * 8 + lq;
                bh[nt][0] = Bh[(kk + lr) * TBPAD + cc];
                bh[nt][1] = Bh[(kk + lr + 4) * TBPAD + cc];
                bl[nt][0] = Bl[(kk + lr) * TBPAD + cc];
                bl[nt][1] = Bl[(kk + lr + 4) * TBPAD + cc];
            }
#pragma unroll
            for (int mt = 0; mt < 4; mt++)
#pragma unroll
                for (int nt = 0; nt < 4; nt++) {
                    mma_tf32(acc[mt][nt], al[mt], bh[nt]);
                    mma_tf32(acc[mt][nt], ah[mt], bl[nt]);
                    mma_tf32(acc[mt][nt], ah[mt], bh[nt]);
                }
        }
        __syncthreads();
    }

#pragma unroll
    for (int mt = 0; mt < 4; mt++) {
#pragma unroll
        for (int nt = 0; nt < 4; nt++) {
            int row = bm + wm + mt * 16 + lq;
            int col = bn + wn + nt * 8 + 2 * lr;
            *(float2*)(C + (size_t)row * 2048 + col) =
                make_float2(acc[mt][nt][0], acc[mt][nt][1]);
            *(float2*)(C + (size_t)(row + 8) * 2048 + col) =
                make_float2(acc[mt][nt][2], acc[mt][nt][3]);
        }
    }
}

// =====================================================================
// Fused conv + SiLU*SiLU + LSH hash: one block per token row.
// conv math per-element identical to before; hash identical, reading
// zm from smem instead of gmem (zm still written to gmem for proj).
// =====================================================================
__global__ __launch_bounds__(256)
void conv_hash(const float* __restrict__ dw_w, const float* __restrict__ dw_b,
               const float* __restrict__ rot, const int* __restrict__ salts)
{
    __shared__ float zm_s[1024];
    __shared__ float red[256];
    __shared__ float base_s[8];
    int row = blockIdx.x;
    int n = row & (NSEQ - 1);
    int tid = threadIdx.x;
    const float* zr = g_scratch + OFF_ZFULL + (size_t)row * 2048;
    float* zmg = g_scratch + OFF_ZM + (size_t)row * 1024;

#pragma unroll
    for (int t = 0; t < 4; t++) {
        int d = tid + t * 256;
        float z0 = (n > 0)        ? zr[-2048 + d] : 0.f;
        float z1 = zr[d];
        float z2 = (n < NSEQ - 1) ? zr[2048 + d] : 0.f;
        float c = z0 * dw_w[d * 3 + 0] + z1 * dw_w[d * 3 + 1] + z2 * dw_w[d * 3 + 2] + dw_b[d];
        float g = zr[1024 + d];
        float sc = c / (1.f + expf(-c));
        float sg = g / (1.f + expf(-g));
        float v = sc * sg;
        zm_s[d] = v;
        zmg[d] = v;
    }
    __syncthreads();

    const float* fb = g_scratch + OFF_FBASE;
    int h = tid & 7, ck = tid >> 3;
    float p = 0.f;
    const float* zp = zm_s + ck * 32;
#pragma unroll
    for (int dd = 0; dd < 32; dd++) p += zp[dd] * fb[(ck * 32 + dd) * 8 + h];
    red[tid] = p;
    __syncthreads();
    if (tid < 8) {
        float s = 0.f;
        for (int c2 = 0; c2 < 32; c2++) s += red[c2 * 8 + tid];
        base_s[tid] = s;
    }
    __syncthreads();
    if (tid == 0) {
        int code = 0;
#pragma unroll
        for (int r = 0; r < 4; r++) {
            int ph = 0;
#pragma unroll
            for (int kk = 0; kk < 8; kk++) {
                float sim = 0.f;
#pragma unroll
                for (int hh = 0; hh < 8; hh++) sim += base_s[hh] * rot[r * 64 + hh * 8 + kk];
                if (sim >= 0.f) ph ^= salts[r * 8 + kk];
            }
            code ^= ph;
        }
        g_bucket[row] = code & (NBK - 1);
    }
}

// =====================================================================
// Haar mix over sequence pairs
// =====================================================================
__global__ void haar_kernel()
{
    int gid = blockIdx.x * 256 + threadIdx.x;
    int ch = gid & 255;
    int t  = gid >> 8;
    int c  = t & 2047;
    int b  = t >> 11;
    const float* kr = g_scratch + OFF_KRAW;
    float x0 = kr[((size_t)(b * NSEQ + 2 * c)) * 256 + ch];
    float x1 = kr[((size_t)(b * NSEQ + 2 * c + 1)) * 256 + ch];
    float* kh = g_scratch + OFF_KH;
    kh[((size_t)(b * NSEQ + c)) * 256 + ch]        = 0.5f * (x0 + x1);
    kh[((size_t)(b * NSEQ + 2048 + c)) * 256 + ch] = 0.5f * (x0 - x1);
}

// =====================================================================
// Parallel stable counting sort per batch
// =====================================================================
__global__ void sort_kernel()
{
    int b = blockIdx.x;
    __shared__ int cnt[NBK][257];
    __shared__ int bbase[NBK];
    int tid = threadIdx.x;
#pragma unroll
    for (int bb = 0; bb < NBK; bb++) cnt[bb][tid] = 0;
    __syncthreads();
    const int* bk = g_bucket + b * NSEQ;
    int seg = tid * 16;
    int loc[16];
#pragma unroll
    for (int i = 0; i < 16; i++) {
        loc[i] = bk[seg + i];
        cnt[loc[i]][tid] += 1;
    }
    __syncthreads();
    if (tid < NBK) {
        int s = 0;
        for (int t = 0; t < 256; t++) { int v = cnt[tid][t]; cnt[tid][t] = s; s += v; }
        cnt[tid][256] = s;
    }
    __syncthreads();
    if (tid == 0) {
        int s = 0;
        for (int bb = 0; bb < NBK; bb++) { bbase[bb] = s; s += cnt[bb][256]; }
    }
    __syncthreads();
#pragma unroll
    for (int i = 0; i < 16; i++) {
        int bb = loc[i];
        int pos = bbase[bb] + cnt[bb][tid];
        cnt[bb][tid] = pos + 1 - bbase[bb];
        g_order[b * NSEQ + pos] = seg + i;
    }
}

// =====================================================================
// Tensor-core bucketed attention (proven R7)
// =====================================================================
#define AQ_PAD 72
#define AK_PAD 136
#define AV_PAD 72
#define AP_PAD 132
#define ATTN_SMEM ((128*AQ_PAD + 64*AK_PAD + 128*AV_PAD) * 4)

__global__ __launch_bounds__(256, 2)
void attn_tc()
{
    extern __shared__ __align__(16) uint32_t smw[];
    uint32_t* qs = smw;
    uint32_t* ks = smw + 128 * AQ_PAD;
    uint32_t* vs = smw + 128 * AQ_PAD + 64 * AK_PAD;
    uint32_t* ps = smw;
    __shared__ int idx_s[128];

    const int c = blockIdx.x, h = blockIdx.y, b = blockIdx.z;
    const int kvh = h >> 2;
    const int tid = threadIdx.x;
    const int warp = tid >> 5, lane = tid & 31;
    const int lq = lane >> 2, lr = lane & 3;
    const int m0 = warp * 16;

    if (tid < 128) idx_s[tid] = g_order[b * NSEQ + c * BUCK + tid];
    __syncthreads();

    const float* gq = g_scratch + OFF_Q;
    const float* gk = g_scratch + OFF_KH;
    const float* gv = g_scratch + OFF_V;

    for (int e = tid; e < 128 * 16; e += 256) {
        int row = e >> 4;
        int c4  = (e & 15) << 2;
        size_t grow = (size_t)(b * NSEQ + idx_s[row]);
        float4 qv = *(const float4*)(gq + grow * 1024 + h * 64 + c4);
        *(uint4*)(qs + row * AQ_PAD + c4) = cvt4(qv);
        float4 kv = *(const float4*)(gk + grow * 256 + kvh * 64 + c4);
        ks[(c4 + 0) * AK_PAD + row] = f2tf32(kv.x);
        ks[(c4 + 1) * AK_PAD + row] = f2tf32(kv.y);
        ks[(c4 + 2) * AK_PAD + row] = f2tf32(kv.z);
        ks[(c4 + 3) * AK_PAD + row] = f2tf32(kv.w);
        float4 vv = *(const float4*)(gv + grow * 256 + kvh * 64 + c4);
        *(uint4*)(vs + row * AV_PAD + c4) = cvt4(vv);
    }
    __syncthreads();

    float acc[16][4];
#pragma unroll
    for (int nt = 0; nt < 16; nt++)
#pragma unroll
        for (int k2 = 0; k2 < 4; k2++) acc[nt][k2] = 0.f;

    const uint32_t lm_row = (uint32_t)(m0 + (lane & 7) + ((lane >> 3) & 1) * 8);
    const uint32_t q_base = (uint32_t)__cvta_generic_to_shared(qs)
                          + ((lm_row * AQ_PAD + (lane >> 4) * 4) << 2);
#pragma unroll
    for (int kk = 0; kk < 64; kk += 8) {
        uint32_t a[4];
        ldsm_x4(a, q_base + (kk << 2));
#pragma unroll
        for (int nt = 0; nt < 16; nt++) {
            uint32_t bf[2];
            bf[0] = ks[(kk + lr) * AK_PAD + nt * 8 + lq];
            bf[1] = ks[(kk + lr + 4) * AK_PAD + nt * 8 + lq];
            mma_tf32(acc[nt], a, bf);
        }
    }

    float mx0 = -1e30f, mx1 = -1e30f;
#pragma unroll
    for (int nt = 0; nt < 16; nt++) {
        mx0 = fmaxf(mx0, fmaxf(acc[nt][0], acc[nt][1]));
        mx1 = fmaxf(mx1, fmaxf(acc[nt][2], acc[nt][3]));
    }
    mx0 = fmaxf(mx0, __shfl_xor_sync(0xffffffffu, mx0, 1));
    mx0 = fmaxf(mx0, __shfl_xor_sync(0xffffffffu, mx0, 2));
    mx1 = fmaxf(mx1, __shfl_xor_sync(0xffffffffu, mx1, 1));
    mx1 = fmaxf(mx1, __shfl_xor_sync(0xffffffffu, mx1, 2));
    float s0 = 0.f, s1 = 0.f;
#pragma unroll
    for (int nt = 0; nt < 16; nt++) {
        acc[nt][0] = __expf((acc[nt][0] - mx0) * 0.125f);
        acc[nt][1] = __expf((acc[nt][1] - mx0) * 0.125f);
        acc[nt][2] = __expf((acc[nt][2] - mx1) * 0.125f);
        acc[nt][3] = __expf((acc[nt][3] - mx1) * 0.125f);
        s0 += acc[nt][0] + acc[nt][1];
        s1 += acc[nt][2] + acc[nt][3];
    }
    s0 += __shfl_xor_sync(0xffffffffu, s0, 1);
    s0 += __shfl_xor_sync(0xffffffffu, s0, 2);
    s1 += __shfl_xor_sync(0xffffffffu, s1, 1);
    s1 += __shfl_xor_sync(0xffffffffu, s1, 2);
    const float r0 = 1.f / s0, r1 = 1.f / s1;

    __syncthreads();

#pragma unroll
    for (int nt = 0; nt < 16; nt++) {
        *(uint2*)(ps + (m0 + lq) * AP_PAD + nt * 8 + 2 * lr) =
            make_uint2(f2tf32(acc[nt][0] * r0), f2tf32(acc[nt][1] * r0));
        *(uint2*)(ps + (m0 + lq + 8) * AP_PAD + nt * 8 + 2 * lr) =
            make_uint2(f2tf32(acc[nt][2] * r1), f2tf32(acc[nt][3] * r1));
    }
    __syncwarp();

    float o[8][4];
#pragma unroll
    for (int nt = 0; nt < 8; nt++)
#pragma unroll
        for (int k2 = 0; k2 < 4; k2++) o[nt][k2] = 0.f;

    const uint32_t p_base = (uint32_t)__cvta_generic_to_shared(ps)
                          + ((lm_row * AP_PAD + (lane >> 4) * 4) << 2);
#pragma unroll
    for (int kk = 0; kk < 128; kk += 8) {
        uint32_t a[4];
        ldsm_x4(a, p_base + (kk << 2));
#pragma unroll
        for (int nt = 0; nt < 8; nt++) {
            uint32_t bf[2];
            bf[0] = vs[(kk + lr) * AV_PAD + nt * 8 + lq];
            bf[1] = vs[(kk + lr + 4) * AV_PAD + nt * 8 + lq];
            mma_tf32(o[nt], a, bf);
        }
    }

    float* ga = g_scratch + OFF_ATT;
    size_t g0 = (size_t)(b * NSEQ + idx_s[m0 + lq]);
    size_t g1 = (size_t)(b * NSEQ + idx_s[m0 + lq + 8]);
#pragma unroll
    for (int nt = 0; nt < 8; nt++) {
        *(float2*)(ga + g0 * 1024 + h * 64 + nt * 8 + 2 * lr) =
            make_float2(o[nt][0], o[nt][1]);
        *(float2*)(ga + g1 * 1024 + h * 64 + nt * 8 + 2 * lr) =
            make_float2(o[nt][2], o[nt][3]);
    }
}

// =====================================================================
// Host launcher
// =====================================================================
extern "C" void kernel_launch(void* const* d_in, const int* in_sizes, int n_in,
                              void* d_out, int out_size)
{
    const float* x         = (const float*)d_in[0];
    const float* ge_inp_w  = (const float*)d_in[1];
    const float* dw_w      = (const float*)d_in[2];
    const float* dw_b      = (const float*)d_in[3];
    const float* ge_out_w  = (const float*)d_in[4];
    const float* q_w       = (const float*)d_in[5];
    const float* k_w       = (const float*)d_in[6];
    const float* v_w       = (const float*)d_in[7];
    const float* Aq        = (const float*)d_in[8];
    const float* Bq        = (const float*)d_in[9];
    const float* Ak        = (const float*)d_in[10];
    const float* Bk        = (const float*)d_in[11];
    const float* rand_gate = (const float*)d_in[12];
    const float* base_w    = (const float*)d_in[13];
    const float* rot       = (const float*)d_in[14];
    const float* o_w       = (const float*)d_in[16];
    const int*   salts     = (const int*)d_in[17];
    float* out = (float*)d_out;

    float* sc = nullptr;
    cudaGetSymbolAddress((void**)&sc, g_scratch);
    uint32_t* xh  = (uint32_t*)(sc + OFF_XH);
    uint32_t* xl  = (uint32_t*)(sc + OFF_XL);
    uint32_t* gwh = (uint32_t*)(sc + OFF_GWH);
    uint32_t* gwl = (uint32_t*)(sc + OFF_GWL);

    cudaFuncSetAttribute(attn_tc, cudaFuncAttributeMaxDynamicSharedMemorySize, ATTN_SMEM);
    cudaFuncSetAttribute(zfull_folds, cudaFuncAttributeMaxDynamicSharedMemorySize, SMEM_X3P);

    // pre-split x3 operands + per-channel fold (both needed by the big fused kernel)
    presplit<<<8192, 256>>>(x, xh, xl);
    presplit<<<2048, 256>>>(ge_inp_w, gwh, gwl);
    fold_qw2<<<1024, 256>>>(q_w, k_w, Aq, Bq, Ak, Bk, rand_gate);

    // zfull (3xtf32) with fold GEMMs + FBASE hidden in the z=1 plane
    zfull_folds<<<dim3(16, 64, 2), 256, SMEM_X3P>>>(xh, xl, gwh, gwl,
                                                    sc + OFF_ZFULL, ge_out_w, base_w);

    // conv + silu + hash fused (needs zfull + FBASE)
    conv_hash<<<MROWS, 256>>>(dw_w, dw_b, rot, salts);
    sort_kernel<<<BB, 256>>>();

    // smooth projections fused (q, kraw, v)
    proj_fused<<<dim3(12, 64), 256>>>(x, v_w);

    haar_kernel<<<(BB * 2048 * 256) / 256, 256>>>();

    attn_tc<<<dim3(NBK, HH, BB), 256, ATTN_SMEM>>>();

    // out = att @ o_w (tf32)
    gemm_tf32<<<dim3(8, 64), 256>>>(sc + OFF_ATT, 1024, o_w, 1024, out, 1024, 1024);
}

// round 13
// speedup vs baseline: 2.8930x; 1.0037x over previous
#include <cuda_runtime.h>
#include <cstdint>
#include <cstddef>

// ---------------- problem constants ----------------
#define BB    2
#define NSEQ  4096
#define DMOD  1024
#define HH    16
#define HKV   4
#define DHD   64
#define MROWS (BB*NSEQ)          // 8192
#define NBK   32
#define BUCK  128

// ---------------- scratch layout (floats / u32 bit patterns) ----------------
#define OFF_ZFULL 0ull                          // 8192*2048
#define OFF_ZM    (OFF_ZFULL + 16777216ull)     // 8192*1024
#define OFF_Q     (OFF_ZM    + 8388608ull)      // 8192*1024
#define OFF_KRAW  (OFF_Q     + 8388608ull)      // 8192*256
#define OFF_KH    (OFF_KRAW  + 2097152ull)      // 8192*256
#define OFF_V     (OFF_KH    + 2097152ull)      // 8192*256
#define OFF_ATT   (OFF_V     + 2097152ull)      // 8192*1024
#define OFF_QWP   (OFF_ATT   + 8388608ull)      // 1024*1024
#define OFF_KWP   (OFF_QWP   + 1048576ull)      // 1024*256
#define OFF_FQ    (OFF_KWP   + 262144ull)       // 1024*1024
#define OFF_FK    (OFF_FQ    + 1048576ull)      // 1024*256
#define OFF_FBASE (OFF_FK    + 262144ull)       // 1024*8
#define OFF_XH    (OFF_FBASE + 8192ull)         // 8192*1024 (tf32-hi of x)
#define OFF_XL    (OFF_XH    + 8388608ull)      // 8192*1024 (tf32-lo of x)
#define OFF_GWH   (OFF_XL    + 8388608ull)      // 1024*2048 (tf32-hi of ge_inp_w)
#define OFF_GWL   (OFF_GWH   + 2097152ull)      // 1024*2048 (tf32-lo)
#define SCRATCH_TOTAL (OFF_GWL + 2097152ull)

__device__ __align__(256) float g_scratch[SCRATCH_TOTAL];
__device__ int g_bucket[MROWS];
__device__ int g_order[MROWS];

// =====================================================================
// Shared tf32 helpers
// =====================================================================
#define TBM 128
#define TBN 128
#define TBK 32
#define TAPAD 36
#define TBPAD 132

__device__ __forceinline__ uint32_t f2tf32(float f) {
    uint32_t r;
    asm("cvt.rna.tf32.f32 %0, %1;" : "=r"(r) : "f"(f));
    return r;
}

__device__ __forceinline__ void mma_tf32(float* c, const uint32_t* a, const uint32_t* b) {
    asm volatile(
        "mma.sync.aligned.m16n8k8.row.col.f32.tf32.tf32.f32 "
        "{%0,%1,%2,%3}, {%4,%5,%6,%7}, {%8,%9}, {%0,%1,%2,%3};"
        : "+f"(c[0]), "+f"(c[1]), "+f"(c[2]), "+f"(c[3])
        : "r"(a[0]), "r"(a[1]), "r"(a[2]), "r"(a[3]), "r"(b[0]), "r"(b[1]));
}

__device__ __forceinline__ void ldsm_x4(uint32_t* r, uint32_t addr) {
    asm volatile("ldmatrix.sync.aligned.m8n8.x4.shared.b16 {%0,%1,%2,%3}, [%4];"
                 : "=r"(r[0]), "=r"(r[1]), "=r"(r[2]), "=r"(r[3])
                 : "r"(addr));
}

__device__ __forceinline__ uint4 cvt4(float4 v) {
    return make_uint4(f2tf32(v.x), f2tf32(v.y), f2tf32(v.z), f2tf32(v.w));
}

__device__ __forceinline__ void cpa16(uint32_t dst, const void* src) {
    asm volatile("cp.async.cg.shared.global [%0], [%1], 16;" :: "r"(dst), "l"(src));
}

// =====================================================================
// Plain tf32 GEMM tile (proven path), smem provided by caller.
// a_s: TBM*TAPAD u32, b_s: TBK*TBPAD u32.
// =====================================================================
__device__ __forceinline__
void gemm_tf32_tile(const float* __restrict__ A, int lda,
                    const float* __restrict__ Bm, int ldb,
                    float* __restrict__ C, int ldc, int K,
                    int bm, int bn,
                    uint32_t* a_s, uint32_t* b_s)
{
    const int tid = threadIdx.x;
    const int warp = tid >> 5, lane = tid & 31;
    const int wm = (warp >> 2) * 64;
    const int wn = (warp & 3) * 32;

    float acc[4][4][4];
#pragma unroll
    for (int i = 0; i < 4; i++)
#pragma unroll
        for (int j = 0; j < 4; j++)
#pragma unroll
            for (int k = 0; k < 4; k++) acc[i][j][k] = 0.f;

    const int lq = lane >> 2;
    const int lr = lane & 3;

    const uint32_t s_a0 = (uint32_t)__cvta_generic_to_shared(a_s);
    const uint32_t a_lm_base =
        s_a0 + (((wm + (lane & 7) + ((lane >> 3) & 1) * 8) * TAPAD + (lane >> 4) * 4) << 2);

    for (int kt = 0; kt < K; kt += TBK) {
#pragma unroll
        for (int u = 0; u < 4; u++) {
            int id = tid + u * 256;
            int r  = id >> 3;
            int kc = (id & 7) << 2;
            float4 v = *(const float4*)(A + (size_t)(bm + r) * lda + kt + kc);
            *(uint4*)(a_s + r * TAPAD + kc) = cvt4(v);
        }
#pragma unroll
        for (int u = 0; u < 4; u++) {
            int id = tid + u * 256;
            int r  = id >> 5;
            int nc = (id & 31) << 2;
            float4 v = *(const float4*)(Bm + (size_t)(kt + r) * ldb + bn + nc);
            *(uint4*)(b_s + r * TBPAD + nc) = cvt4(v);
        }
        __syncthreads();

#pragma unroll
        for (int kk = 0; kk < TBK; kk += 8) {
            uint32_t a[4][4], b[4][2];
#pragma unroll
            for (int mt = 0; mt < 4; mt++)
                ldsm_x4(a[mt], a_lm_base + ((mt * 16 * TAPAD + kk) << 2));
#pragma unroll
            for (int nt = 0; nt < 4; nt++) {
                int cc = wn + nt * 8 + lq;
                b[nt][0] = b_s[(kk + lr) * TBPAD + cc];
                b[nt][1] = b_s[(kk + lr + 4) * TBPAD + cc];
            }
#pragma unroll
            for (int mt = 0; mt < 4; mt++)
#pragma unroll
                for (int nt = 0; nt < 4; nt++)
                    mma_tf32(acc[mt][nt], a[mt], b[nt]);
        }
        __syncthreads();
    }

#pragma unroll
    for (int mt = 0; mt < 4; mt++) {
#pragma unroll
        for (int nt = 0; nt < 4; nt++) {
            int row = bm + wm + mt * 16 + lq;
            int col = bn + wn + nt * 8 + 2 * lr;
            *(float2*)(C + (size_t)row * ldc + col) =
                make_float2(acc[mt][nt][0], acc[mt][nt][1]);
            *(float2*)(C + (size_t)(row + 8) * ldc + col) =
                make_float2(acc[mt][nt][2], acc[mt][nt][3]);
        }
    }
}

__global__ __launch_bounds__(256, 2)
void gemm_tf32(const float* __restrict__ A, int lda,
               const float* __restrict__ Bm, int ldb,
               float* __restrict__ C, int ldc, int K)
{
    __shared__ __align__(16) uint32_t a_s[TBM * TAPAD];
    __shared__ __align__(16) uint32_t b_s[TBK * TBPAD];
    gemm_tf32_tile(A, lda, Bm, ldb, C, ldc, K, blockIdx.y * TBM, blockIdx.x * TBN, a_s, b_s);
}

// Fused smooth projections: x<8 -> q = zm@FQ; 8,9 -> kraw = zm@FK; 10,11 -> v = x@v_w.
__global__ __launch_bounds__(256, 2)
void proj_fused(const float* __restrict__ x, const float* __restrict__ v_w)
{
    __shared__ __align__(16) uint32_t a_s[TBM * TAPAD];
    __shared__ __align__(16) uint32_t b_s[TBK * TBPAD];
    const float* A;
    const float* Bm;
    float* C;
    int ldb, ldc, bn;
    int bx = blockIdx.x;
    if (bx < 8) {
        A = g_scratch + OFF_ZM; Bm = g_scratch + OFF_FQ; C = g_scratch + OFF_Q;
        ldb = 1024; ldc = 1024; bn = bx * TBN;
    } else if (bx < 10) {
        A = g_scratch + OFF_ZM; Bm = g_scratch + OFF_FK; C = g_scratch + OFF_KRAW;
        ldb = 256;  ldc = 256;  bn = (bx - 8) * TBN;
    } else {
        A = x;                  Bm = v_w;               C = g_scratch + OFF_V;
        ldb = 256;  ldc = 256;  bn = (bx - 10) * TBN;
    }
    gemm_tf32_tile(A, 1024, Bm, ldb, C, ldc, 1024, blockIdx.y * TBM, bn, a_s, b_s);
}

// =====================================================================
// Pre-split: hi = rna_tf32(v), lo = rna_tf32(v - hi), stored as u32 bits.
// =====================================================================
__global__ void presplit(const float* __restrict__ src,
                         uint32_t* __restrict__ hi, uint32_t* __restrict__ lo)
{
    int g = (blockIdx.x * 256 + threadIdx.x) * 4;
    float4 v = *(const float4*)(src + g);
    uint4 h = cvt4(v);
    uint4 l = make_uint4(
        f2tf32(v.x - __uint_as_float(h.x)),
        f2tf32(v.y - __uint_as_float(h.y)),
        f2tf32(v.z - __uint_as_float(h.z)),
        f2tf32(v.w - __uint_as_float(h.w)));
    *(uint4*)(hi + g) = h;
    *(uint4*)(lo + g) = l;
}

// =====================================================================
// fold_qw merged with fold_small
// =====================================================================
__global__ void fold_qw2(const float* __restrict__ qw, const float* __restrict__ kw,
                         const float* __restrict__ Aq, const float* __restrict__ Bq,
                         const float* __restrict__ Ak, const float* __restrict__ Bk,
                         const float* __restrict__ rand_gate)
{
    __shared__ float qr[1024];
    __shared__ float kr[256];
    __shared__ float wq_s[4096];
    __shared__ float wk_s[4096];
    int d = blockIdx.x;
    int tid = threadIdx.x;
#pragma unroll
    for (int t = 0; t < 16; t++) {
        int ij = tid + t * 256;
        int i = ij >> 6, j = ij & 63;
        float sq = 0.f, sk = 0.f;
#pragma unroll
        for (int r = 0; r < 16; r++) {
            sq += Aq[i * 16 + r] * Bq[r * 64 + j];
            sk += Ak[i * 16 + r] * Bk[r * 64 + j];
        }
        wq_s[ij] = sq;
        wk_s[ij] = sk;
    }
    for (int i = tid; i < 1024; i += 256) qr[i] = qw[(size_t)d * 1024 + i];
    if (tid < 256) kr[tid] = kw[(size_t)d * 256 + tid];
    __syncthreads();
    for (int c = tid; c < 1024; c += 256) {
        int h = c >> 6, j = c & 63;
        float s = 0.f;
#pragma unroll
        for (int i = 0; i < 64; i++) s += qr[h * 64 + i] * wq_s[i * 64 + j];
        g_scratch[OFF_QWP + (size_t)d * 1024 + c] = s;
    }
    {
        int c = tid;
        int g = c >> 6, j = c & 63;
        float s = 0.f;
#pragma unroll
        for (int i = 0; i < 64; i++) s += kr[g * 64 + i] * wk_s[i * 64 + j];
        g_scratch[OFF_KWP + (size_t)d * 256 + c] = s * tanhf(1.f + rand_gate[j]);
    }
}

// =====================================================================
// fold_base body (fp32 exact — sign-critical), one row per call.
// =====================================================================
__device__ __forceinline__
void fold_base_row(const float* __restrict__ ge_out_w,
                   const float* __restrict__ base_w, int i, float* red)
{
    int tid = threadIdx.x;
    const float* a = ge_out_w + (size_t)i * 2048;
    int h = tid & 7, ck = tid >> 3;
    const float4* a4 = (const float4*)(a + ck * 32);
    float p = 0.f;
#pragma unroll
    for (int q4 = 0; q4 < 8; q4++) {
        float4 v = a4[q4];
        const float* bw = base_w + (ck * 32 + q4 * 4) * 8 + h;
        p += v.x * bw[0] + v.y * bw[8] + v.z * bw[16] + v.w * bw[24];
    }
    red[tid] = p;
    __syncthreads();
    if (tid < 8) {
        float s = 0.f;
        for (int c2 = 0; c2 < 32; c2++) s += red[c2 * 8 + tid];
        g_scratch[OFF_FBASE + (size_t)i * 8 + tid] = s;
    }
    __syncthreads();
}

// =====================================================================
// Fused big kernel, occ-2 version.
// z=0: zfull 3xtf32 cp.async GEMM with 128x64 tiles (2 CTAs/SM).
// z=1: fold GEMMs (FQ/FK) + fold_base using the dynamic smem buffer.
// Stage: Ah[0,4608) Al[4608,9216) Bh[9216,11392) Bl[11392,13568).
// =====================================================================
#define XBN 64
#define XBPAD 68
#define X3_STAGE 13568
#define SMEM_X3 (2 * X3_STAGE * 4)   // 108544 B -> 2 CTAs/SM

__global__ __launch_bounds__(256, 2)
void zfull_folds(const uint32_t* __restrict__ Ahg, const uint32_t* __restrict__ Alg,
                 const uint32_t* __restrict__ Bhg, const uint32_t* __restrict__ Blg,
                 float* __restrict__ C,
                 const float* __restrict__ geo, const float* __restrict__ base_w)
{
    extern __shared__ __align__(16) uint32_t smu[];

    if (blockIdx.z == 1) {
        int f = blockIdx.y * 32 + blockIdx.x;     // 0..2047
        if (f < 64) {
            gemm_tf32_tile(geo, 2048, g_scratch + OFF_QWP, 1024,
                           g_scratch + OFF_FQ, 1024, 1024, (f >> 3) * TBM, (f & 7) * TBN,
                           smu, smu + TBM * TAPAD);
        } else if (f < 80) {
            int g = f - 64;
            gemm_tf32_tile(geo + 1024, 2048, g_scratch + OFF_KWP, 256,
                           g_scratch + OFF_FK, 256, 1024, (g >> 1) * TBM, (g & 1) * TBN,
                           smu, smu + TBM * TAPAD);
        } else if (f < 592) {
            __shared__ float red[256];
            int i0 = (f - 80) * 2;
            fold_base_row(geo, base_w, i0, red);
            fold_base_row(geo, base_w, i0 + 1, red);
        }
        return;
    }

    // ---- z == 0: zfull 3xtf32, 128x64 tile ----
    const int tid = threadIdx.x;
    const int warp = tid >> 5, lane = tid & 31;
    const int wm = (warp >> 2) * 64, wn = (warp & 3) * 16;
    const int bm = blockIdx.y * TBM, bn = blockIdx.x * XBN;
    const int lq = lane >> 2, lr = lane & 3;

    const uint32_t smem_base = (uint32_t)__cvta_generic_to_shared(smu);
    const uint32_t lm_off =
        (((wm + (lane & 7) + ((lane >> 3) & 1) * 8) * TAPAD + (lane >> 4) * 4) << 2);

    float acc[4][2][4];
#pragma unroll
    for (int i = 0; i < 4; i++)
#pragma unroll
        for (int j = 0; j < 2; j++)
#pragma unroll
            for (int k = 0; k < 4; k++) acc[i][j][k] = 0.f;

    auto issue_tile = [&](int kt, int stage) {
        uint32_t sb = smem_base + stage * (X3_STAGE * 4);
#pragma unroll
        for (int u = 0; u < 4; u++) {
            int id = tid + u * 256;
            int r  = id >> 3;
            int kc = (id & 7) << 2;
            size_t asrc = (size_t)(bm + r) * 1024 + kt + kc;
            uint32_t ad = sb + ((r * TAPAD + kc) << 2);
            cpa16(ad, Ahg + asrc);
            cpa16(ad + (4608 << 2), Alg + asrc);
            if (id < 512) {
                int rb = id >> 4;
                int nc = (id & 15) << 2;
                size_t bsrc = (size_t)(kt + rb) * 2048 + bn + nc;
                uint32_t bd = sb + ((9216 + rb * XBPAD + nc) << 2);
                cpa16(bd, Bhg + bsrc);
                cpa16(bd + (2176 << 2), Blg + bsrc);
            }
        }
        asm volatile("cp.async.commit_group;" ::: "memory");
    };

    const int nk = 1024 / TBK;   // 32
    issue_tile(0, 0);

    for (int t = 0; t < nk; t++) {
        if (t + 1 < nk) {
            issue_tile((t + 1) * TBK, (t + 1) & 1);
            asm volatile("cp.async.wait_group 1;" ::: "memory");
        } else {
            asm volatile("cp.async.wait_group 0;" ::: "memory");
        }
        __syncthreads();

        const uint32_t* st = smu + (t & 1) * X3_STAGE;
        const uint32_t* Bh = st + 9216;
        const uint32_t* Bl = st + 9216 + 2176;
        const uint32_t ah_base = smem_base + (t & 1) * (X3_STAGE * 4) + lm_off;
        const uint32_t al_base = ah_base + (4608 << 2);

#pragma unroll
        for (int kk = 0; kk < TBK; kk += 8) {
            uint32_t ah[4][4], al[4][4], bh[2][2], bl[2][2];
#pragma unroll
            for (int mt = 0; mt < 4; mt++) {
                uint32_t off = (mt * 16 * TAPAD + kk) << 2;
                ldsm_x4(ah[mt], ah_base + off);
                ldsm_x4(al[mt], al_base + off);
            }
#pragma unroll
            for (int nt = 0; nt < 2; nt++) {
                int cc = wn + nt * 8 + lq;
                bh[nt][0] = Bh[(kk + lr) * XBPAD + cc];
                bh[nt][1] = Bh[(kk + lr + 4) * XBPAD + cc];
                bl[nt][0] = Bl[(kk + lr) * XBPAD + cc];
                bl[nt][1] = Bl[(kk + lr + 4) * XBPAD + cc];
            }
#pragma unroll
            for (int mt = 0; mt < 4; mt++)
#pragma unroll
                for (int nt = 0; nt < 2; nt++) {
                    mma_tf32(acc[mt][nt], al[mt], bh[nt]);
                    mma_tf32(acc[mt][nt], ah[mt], bl[nt]);
                    mma_tf32(acc[mt][nt], ah[mt], bh[nt]);
                }
        }
        __syncthreads();
    }

#pragma unroll
    for (int mt = 0; mt < 4; mt++) {
#pragma unroll
        for (int nt = 0; nt < 2; nt++) {
            int row = bm + wm + mt * 16 + lq;
            int col = bn + wn + nt * 8 + 2 * lr;
            *(float2*)(C + (size_t)row * 2048 + col) =
                make_float2(acc[mt][nt][0], acc[mt][nt][1]);
            *(float2*)(C + (size_t)(row + 8) * 2048 + col) =
                make_float2(acc[mt][nt][2], acc[mt][nt][3]);
        }
    }
}

// =====================================================================
// Fused conv + SiLU*SiLU + LSH hash: one block per token row.
// =====================================================================
__global__ __launch_bounds__(256)
void conv_hash(const float* __restrict__ dw_w, const float* __restrict__ dw_b,
               const float* __restrict__ rot, const int* __restrict__ salts)
{
    __shared__ float zm_s[1024];
    __shared__ float red[256];
    __shared__ float base_s[8];
    int row = blockIdx.x;
    int n = row & (NSEQ - 1);
    int tid = threadIdx.x;
    const float* zr = g_scratch + OFF_ZFULL + (size_t)row * 2048;
    float* zmg = g_scratch + OFF_ZM + (size_t)row * 1024;

#pragma unroll
    for (int t = 0; t < 4; t++) {
        int d = tid + t * 256;
        float z0 = (n > 0)        ? zr[-2048 + d] : 0.f;
        float z1 = zr[d];
        float z2 = (n < NSEQ - 1) ? zr[2048 + d] : 0.f;
        float c = z0 * dw_w[d * 3 + 0] + z1 * dw_w[d * 3 + 1] + z2 * dw_w[d * 3 + 2] + dw_b[d];
        float g = zr[1024 + d];
        float sc = c / (1.f + expf(-c));
        float sg = g / (1.f + expf(-g));
        float v = sc * sg;
        zm_s[d] = v;
        zmg[d] = v;
    }
    __syncthreads();

    const float* fb = g_scratch + OFF_FBASE;
    int h = tid & 7, ck = tid >> 3;
    float p = 0.f;
    const float* zp = zm_s + ck * 32;
#pragma unroll
    for (int dd = 0; dd < 32; dd++) p += zp[dd] * fb[(ck * 32 + dd) * 8 + h];
    red[tid] = p;
    __syncthreads();
    if (tid < 8) {
        float s = 0.f;
        for (int c2 = 0; c2 < 32; c2++) s += red[c2 * 8 + tid];
        base_s[tid] = s;
    }
    __syncthreads();
    if (tid == 0) {
        int code = 0;
#pragma unroll
        for (int r = 0; r < 4; r++) {
            int ph = 0;
#pragma unroll
            for (int kk = 0; kk < 8; kk++) {
                float sim = 0.f;
#pragma unroll
                for (int hh = 0; hh < 8; hh++) sim += base_s[hh] * rot[r * 64 + hh * 8 + kk];
                if (sim >= 0.f) ph ^= salts[r * 8 + kk];
            }
            code ^= ph;
        }
        g_bucket[row] = code & (NBK - 1);
    }
}

// =====================================================================
// Haar mix over sequence pairs
// =====================================================================
__global__ void haar_kernel()
{
    int gid = blockIdx.x * 256 + threadIdx.x;
    int ch = gid & 255;
    int t  = gid >> 8;
    int c  = t & 2047;
    int b  = t >> 11;
    const float* kr = g_scratch + OFF_KRAW;
    float x0 = kr[((size_t)(b * NSEQ + 2 * c)) * 256 + ch];
    float x1 = kr[((size_t)(b * NSEQ + 2 * c + 1)) * 256 + ch];
    float* kh = g_scratch + OFF_KH;
    kh[((size_t)(b * NSEQ + c)) * 256 + ch]        = 0.5f * (x0 + x1);
    kh[((size_t)(b * NSEQ + 2048 + c)) * 256 + ch] = 0.5f * (x0 - x1);
}

// =====================================================================
// Parallel stable counting sort per batch
// =====================================================================
__global__ void sort_kernel()
{
    int b = blockIdx.x;
    __shared__ int cnt[NBK][257];
    __shared__ int bbase[NBK];
    int tid = threadIdx.x;
#pragma unroll
    for (int bb = 0; bb < NBK; bb++) cnt[bb][tid] = 0;
    __syncthreads();
    const int* bk = g_bucket + b * NSEQ;
    int seg = tid * 16;
    int loc[16];
#pragma unroll
    for (int i = 0; i < 16; i++) {
        loc[i] = bk[seg + i];
        cnt[loc[i]][tid] += 1;
    }
    __syncthreads();
    if (tid < NBK) {
        int s = 0;
        for (int t = 0; t < 256; t++) { int v = cnt[tid][t]; cnt[tid][t] = s; s += v; }
        cnt[tid][256] = s;
    }
    __syncthreads();
    if (tid == 0) {
        int s = 0;
        for (int bb = 0; bb < NBK; bb++) { bbase[bb] = s; s += cnt[bb][256]; }
    }
    __syncthreads();
#pragma unroll
    for (int i = 0; i < 16; i++) {
        int bb = loc[i];
        int pos = bbase[bb] + cnt[bb][tid];
        cnt[bb][tid] = pos + 1 - bbase[bb];
        g_order[b * NSEQ + pos] = seg + i;
    }
}

// =====================================================================
// Tensor-core bucketed attention (proven R7)
// =====================================================================
#define AQ_PAD 72
#define AK_PAD 136
#define AV_PAD 72
#define AP_PAD 132
#define ATTN_SMEM ((128*AQ_PAD + 64*AK_PAD + 128*AV_PAD) * 4)

__global__ __launch_bounds__(256, 2)
void attn_tc()
{
    extern __shared__ __align__(16) uint32_t smw[];
    uint32_t* qs = smw;
    uint32_t* ks = smw + 128 * AQ_PAD;
    uint32_t* vs = smw + 128 * AQ_PAD + 64 * AK_PAD;
    uint32_t* ps = smw;
    __shared__ int idx_s[128];

    const int c = blockIdx.x, h = blockIdx.y, b = blockIdx.z;
    const int kvh = h >> 2;
    const int tid = threadIdx.x;
    const int warp = tid >> 5, lane = tid & 31;
    const int lq = lane >> 2, lr = lane & 3;
    const int m0 = warp * 16;

    if (tid < 128) idx_s[tid] = g_order[b * NSEQ + c * BUCK + tid];
    __syncthreads();

    const float* gq = g_scratch + OFF_Q;
    const float* gk = g_scratch + OFF_KH;
    const float* gv = g_scratch + OFF_V;

    for (int e = tid; e < 128 * 16; e += 256) {
        int row = e >> 4;
        int c4  = (e & 15) << 2;
        size_t grow = (size_t)(b * NSEQ + idx_s[row]);
        float4 qv = *(const float4*)(gq + grow * 1024 + h * 64 + c4);
        *(uint4*)(qs + row * AQ_PAD + c4) = cvt4(qv);
        float4 kv = *(const float4*)(gk + grow * 256 + kvh * 64 + c4);
        ks[(c4 + 0) * AK_PAD + row] = f2tf32(kv.x);
        ks[(c4 + 1) * AK_PAD + row] = f2tf32(kv.y);
        ks[(c4 + 2) * AK_PAD + row] = f2tf32(kv.z);
        ks[(c4 + 3) * AK_PAD + row] = f2tf32(kv.w);
        float4 vv = *(const float4*)(gv + grow * 256 + kvh * 64 + c4);
        *(uint4*)(vs + row * AV_PAD + c4) = cvt4(vv);
    }
    __syncthreads();

    float acc[16][4];
#pragma unroll
    for (int nt = 0; nt < 16; nt++)
#pragma unroll
        for (int k2 = 0; k2 < 4; k2++) acc[nt][k2] = 0.f;

    const uint32_t lm_row = (uint32_t)(m0 + (lane & 7) + ((lane >> 3) & 1) * 8);
    const uint32_t q_base = (uint32_t)__cvta_generic_to_shared(qs)
                          + ((lm_row * AQ_PAD + (lane >> 4) * 4) << 2);
#pragma unroll
    for (int kk = 0; kk < 64; kk += 8) {
        uint32_t a[4];
        ldsm_x4(a, q_base + (kk << 2));
#pragma unroll
        for (int nt = 0; nt < 16; nt++) {
            uint32_t bf[2];
            bf[0] = ks[(kk + lr) * AK_PAD + nt * 8 + lq];
            bf[1] = ks[(kk + lr + 4) * AK_PAD + nt * 8 + lq];
            mma_tf32(acc[nt], a, bf);
        }
    }

    float mx0 = -1e30f, mx1 = -1e30f;
#pragma unroll
    for (int nt = 0; nt < 16; nt++) {
        mx0 = fmaxf(mx0, fmaxf(acc[nt][0], acc[nt][1]));
        mx1 = fmaxf(mx1, fmaxf(acc[nt][2], acc[nt][3]));
    }
    mx0 = fmaxf(mx0, __shfl_xor_sync(0xffffffffu, mx0, 1));
    mx0 = fmaxf(mx0, __shfl_xor_sync(0xffffffffu, mx0, 2));
    mx1 = fmaxf(mx1, __shfl_xor_sync(0xffffffffu, mx1, 1));
    mx1 = fmaxf(mx1, __shfl_xor_sync(0xffffffffu, mx1, 2));
    float s0 = 0.f, s1 = 0.f;
#pragma unroll
    for (int nt = 0; nt < 16; nt++) {
        acc[nt][0] = __expf((acc[nt][0] - mx0) * 0.125f);
        acc[nt][1] = __expf((acc[nt][1] - mx0) * 0.125f);
        acc[nt][2] = __expf((acc[nt][2] - mx1) * 0.125f);
        acc[nt][3] = __expf((acc[nt][3] - mx1) * 0.125f);
        s0 += acc[nt][0] + acc[nt][1];
        s1 += acc[nt][2] + acc[nt][3];
    }
    s0 += __shfl_xor_sync(0xffffffffu, s0, 1);
    s0 += __shfl_xor_sync(0xffffffffu, s0, 2);
    s1 += __shfl_xor_sync(0xffffffffu, s1, 1);
    s1 += __shfl_xor_sync(0xffffffffu, s1, 2);
    const float r0 = 1.f / s0, r1 = 1.f / s1;

    __syncthreads();

#pragma unroll
    for (int nt = 0; nt < 16; nt++) {
        *(uint2*)(ps + (m0 + lq) * AP_PAD + nt * 8 + 2 * lr) =
            make_uint2(f2tf32(acc[nt][0] * r0), f2tf32(acc[nt][1] * r0));
        *(uint2*)(ps + (m0 + lq + 8) * AP_PAD + nt * 8 + 2 * lr) =
            make_uint2(f2tf32(acc[nt][2] * r1), f2tf32(acc[nt][3] * r1));
    }
    __syncwarp();

    float o[8][4];
#pragma unroll
    for (int nt = 0; nt < 8; nt++)
#pragma unroll
        for (int k2 = 0; k2 < 4; k2++) o[nt][k2] = 0.f;

    const uint32_t p_base = (uint32_t)__cvta_generic_to_shared(ps)
                          + ((lm_row * AP_PAD + (lane >> 4) * 4) << 2);
#pragma unroll
    for (int kk = 0; kk < 128; kk += 8) {
        uint32_t a[4];
        ldsm_x4(a, p_base + (kk << 2));
#pragma unroll
        for (int nt = 0; nt < 8; nt++) {
            uint32_t bf[2];
            bf[0] = vs[(kk + lr) * AV_PAD + nt * 8 + lq];
            bf[1] = vs[(kk + lr + 4) * AV_PAD + nt * 8 + lq];
            mma_tf32(o[nt], a, bf);
        }
    }

    float* ga = g_scratch + OFF_ATT;
    size_t g0 = (size_t)(b * NSEQ + idx_s[m0 + lq]);
    size_t g1 = (size_t)(b * NSEQ + idx_s[m0 + lq + 8]);
#pragma unroll
    for (int nt = 0; nt < 8; nt++) {
        *(float2*)(ga + g0 * 1024 + h * 64 + nt * 8 + 2 * lr) =
            make_float2(o[nt][0], o[nt][1]);
        *(float2*)(ga + g1 * 1024 + h * 64 + nt * 8 + 2 * lr) =
            make_float2(o[nt][2], o[nt][3]);
    }
}

// =====================================================================
// Host launcher
// =====================================================================
extern "C" void kernel_launch(void* const* d_in, const int* in_sizes, int n_in,
                              void* d_out, int out_size)
{
    const float* x         = (const float*)d_in[0];
    const float* ge_inp_w  = (const float*)d_in[1];
    const float* dw_w      = (const float*)d_in[2];
    const float* dw_b      = (const float*)d_in[3];
    const float* ge_out_w  = (const float*)d_in[4];
    const float* q_w       = (const float*)d_in[5];
    const float* k_w       = (const float*)d_in[6];
    const float* v_w       = (const float*)d_in[7];
    const float* Aq        = (const float*)d_in[8];
    const float* Bq        = (const float*)d_in[9];
    const float* Ak        = (const float*)d_in[10];
    const float* Bk        = (const float*)d_in[11];
    const float* rand_gate = (const float*)d_in[12];
    const float* base_w    = (const float*)d_in[13];
    const float* rot       = (const float*)d_in[14];
    const float* o_w       = (const float*)d_in[16];
    const int*   salts     = (const int*)d_in[17];
    float* out = (float*)d_out;

    float* sc = nullptr;
    cudaGetSymbolAddress((void**)&sc, g_scratch);
    uint32_t* xh  = (uint32_t*)(sc + OFF_XH);
    uint32_t* xl  = (uint32_t*)(sc + OFF_XL);
    uint32_t* gwh = (uint32_t*)(sc + OFF_GWH);
    uint32_t* gwl = (uint32_t*)(sc + OFF_GWL);

    cudaFuncSetAttribute(attn_tc, cudaFuncAttributeMaxDynamicSharedMemorySize, ATTN_SMEM);
    cudaFuncSetAttribute(zfull_folds, cudaFuncAttributeMaxDynamicSharedMemorySize, SMEM_X3);

    // pre-split x3 operands + per-channel fold
    presplit<<<8192, 256>>>(x, xh, xl);
    presplit<<<2048, 256>>>(ge_inp_w, gwh, gwl);
    fold_qw2<<<1024, 256>>>(q_w, k_w, Aq, Bq, Ak, Bk, rand_gate);

    // zfull (3xtf32, 128x64 tiles, occ 2) with folds in the z=1 plane
    zfull_folds<<<dim3(32, 64, 2), 256, SMEM_X3>>>(xh, xl, gwh, gwl,
                                                   sc + OFF_ZFULL, ge_out_w, base_w);

    // conv + silu + hash fused
    conv_hash<<<MROWS, 256>>>(dw_w, dw_b, rot, salts);
    sort_kernel<<<BB, 256>>>();

    // smooth projections fused (q, kraw, v)
    proj_fused<<<dim3(12, 64), 256>>>(x, v_w);

    haar_kernel<<<(BB * 2048 * 256) / 256, 256>>>();

    attn_tc<<<dim3(NBK, HH, BB), 256, ATTN_SMEM>>>();

    // out = att @ o_w (tf32)
    gemm_tf32<<<dim3(8, 64), 256>>>(sc + OFF_ATT, 1024, o_w, 1024, out, 1024, 1024);
}

// round 15
// speedup vs baseline: 3.0181x; 1.0432x over previous
#include <cuda_runtime.h>
#include <cstdint>
#include <cstddef>

// ---------------- problem constants ----------------
#define BB    2
#define NSEQ  4096
#define DMOD  1024
#define HH    16
#define HKV   4
#define DHD   64
#define MROWS (BB*NSEQ)          // 8192
#define NBK   32
#define BUCK  128

// ---------------- scratch layout (floats / u32 bit patterns) ----------------
#define OFF_ZFULL 0ull                          // 8192*2048
#define OFF_ZM    (OFF_ZFULL + 16777216ull)     // 8192*1024
#define OFF_Q     (OFF_ZM    + 8388608ull)      // 8192*1024
#define OFF_KRAW  (OFF_Q     + 8388608ull)      // 8192*256
#define OFF_KH    (OFF_KRAW  + 2097152ull)      // 8192*256
#define OFF_V     (OFF_KH    + 2097152ull)      // 8192*256
#define OFF_ATT   (OFF_V     + 2097152ull)      // 8192*1024
#define OFF_QWP   (OFF_ATT   + 8388608ull)      // 1024*1024
#define OFF_KWP   (OFF_QWP   + 1048576ull)      // 1024*256
#define OFF_FQ    (OFF_KWP   + 262144ull)       // 1024*1024
#define OFF_FK    (OFF_FQ    + 1048576ull)      // 1024*256
#define OFF_FBASE (OFF_FK    + 262144ull)       // 1024*8
#define OFF_XH    (OFF_FBASE + 8192ull)         // 8192*1024 (tf32-hi of x)
#define OFF_XL    (OFF_XH    + 8388608ull)      // 8192*1024 (tf32-lo of x)
#define OFF_GWH   (OFF_XL    + 8388608ull)      // 1024*2048 (tf32-hi of ge_inp_w)
#define OFF_GWL   (OFF_GWH   + 2097152ull)      // 1024*2048 (tf32-lo)
#define SCRATCH_TOTAL (OFF_GWL + 2097152ull)

__device__ __align__(256) float g_scratch[SCRATCH_TOTAL];
__device__ int g_bucket[MROWS];
__device__ int g_order[MROWS];

// =====================================================================
// Shared tf32 helpers (mma.sync path, proven)
// =====================================================================
#define TBM 128
#define TBN 128
#define TBK 32
#define TAPAD 36
#define TBPAD 132

__device__ __forceinline__ uint32_t f2tf32(float f) {
    uint32_t r;
    asm("cvt.rna.tf32.f32 %0, %1;" : "=r"(r) : "f"(f));
    return r;
}

__device__ __forceinline__ void mma_tf32(float* c, const uint32_t* a, const uint32_t* b) {
    asm volatile(
        "mma.sync.aligned.m16n8k8.row.col.f32.tf32.tf32.f32 "
        "{%0,%1,%2,%3}, {%4,%5,%6,%7}, {%8,%9}, {%0,%1,%2,%3};"
        : "+f"(c[0]), "+f"(c[1]), "+f"(c[2]), "+f"(c[3])
        : "r"(a[0]), "r"(a[1]), "r"(a[2]), "r"(a[3]), "r"(b[0]), "r"(b[1]));
}

__device__ __forceinline__ void ldsm_x4(uint32_t* r, uint32_t addr) {
    asm volatile("ldmatrix.sync.aligned.m8n8.x4.shared.b16 {%0,%1,%2,%3}, [%4];"
                 : "=r"(r[0]), "=r"(r[1]), "=r"(r[2]), "=r"(r[3])
                 : "r"(addr));
}

__device__ __forceinline__ uint4 cvt4(float4 v) {
    return make_uint4(f2tf32(v.x), f2tf32(v.y), f2tf32(v.z), f2tf32(v.w));
}

__device__ __forceinline__ void cpa16(uint32_t dst, const void* src) {
    asm volatile("cp.async.cg.shared.global [%0], [%1], 16;" :: "r"(dst), "l"(src));
}

__device__ __forceinline__ uint32_t smem_u32(const void* p) {
    return (uint32_t)__cvta_generic_to_shared(p);
}

// =====================================================================
// Plain tf32 GEMM tile (proven mma.sync path), smem provided by caller.
// =====================================================================
__device__ __forceinline__
void gemm_tf32_tile(const float* __restrict__ A, int lda,
                    const float* __restrict__ Bm, int ldb,
                    float* __restrict__ C, int ldc, int K,
                    int bm, int bn,
                    uint32_t* a_s, uint32_t* b_s)
{
    const int tid = threadIdx.x;
    const int warp = tid >> 5, lane = tid & 31;
    const int wm = (warp >> 2) * 64;
    const int wn = (warp & 3) * 32;

    float acc[4][4][4];
#pragma unroll
    for (int i = 0; i < 4; i++)
#pragma unroll
        for (int j = 0; j < 4; j++)
#pragma unroll
            for (int k = 0; k < 4; k++) acc[i][j][k] = 0.f;

    const int lq = lane >> 2;
    const int lr = lane & 3;

    const uint32_t s_a0 = smem_u32(a_s);
    const uint32_t a_lm_base =
        s_a0 + (((wm + (lane & 7) + ((lane >> 3) & 1) * 8) * TAPAD + (lane >> 4) * 4) << 2);

    for (int kt = 0; kt < K; kt += TBK) {
#pragma unroll
        for (int u = 0; u < 4; u++) {
            int id = tid + u * 256;
            int r  = id >> 3;
            int kc = (id & 7) << 2;
            float4 v = *(const float4*)(A + (size_t)(bm + r) * lda + kt + kc);
            *(uint4*)(a_s + r * TAPAD + kc) = cvt4(v);
        }
#pragma unroll
        for (int u = 0; u < 4; u++) {
            int id = tid + u * 256;
            int r  = id >> 5;
            int nc = (id & 31) << 2;
            float4 v = *(const float4*)(Bm + (size_t)(kt + r) * ldb + bn + nc);
            *(uint4*)(b_s + r * TBPAD + nc) = cvt4(v);
        }
        __syncthreads();

#pragma unroll
        for (int kk = 0; kk < TBK; kk += 8) {
            uint32_t a[4][4], b[4][2];
#pragma unroll
            for (int mt = 0; mt < 4; mt++)
                ldsm_x4(a[mt], a_lm_base + ((mt * 16 * TAPAD + kk) << 2));
#pragma unroll
            for (int nt = 0; nt < 4; nt++) {
                int cc = wn + nt * 8 + lq;
                b[nt][0] = b_s[(kk + lr) * TBPAD + cc];
                b[nt][1] = b_s[(kk + lr + 4) * TBPAD + cc];
            }
#pragma unroll
            for (int mt = 0; mt < 4; mt++)
#pragma unroll
                for (int nt = 0; nt < 4; nt++)
                    mma_tf32(acc[mt][nt], a[mt], b[nt]);
        }
        __syncthreads();
    }

#pragma unroll
    for (int mt = 0; mt < 4; mt++) {
#pragma unroll
        for (int nt = 0; nt < 4; nt++) {
            int row = bm + wm + mt * 16 + lq;
            int col = bn + wn + nt * 8 + 2 * lr;
            *(float2*)(C + (size_t)row * ldc + col) =
                make_float2(acc[mt][nt][0], acc[mt][nt][1]);
            *(float2*)(C + (size_t)(row + 8) * ldc + col) =
                make_float2(acc[mt][nt][2], acc[mt][nt][3]);
        }
    }
}

__global__ __launch_bounds__(256, 2)
void gemm_tf32(const float* __restrict__ A, int lda,
               const float* __restrict__ Bm, int ldb,
               float* __restrict__ C, int ldc, int K)
{
    __shared__ __align__(16) uint32_t a_s[TBM * TAPAD];
    __shared__ __align__(16) uint32_t b_s[TBK * TBPAD];
    gemm_tf32_tile(A, lda, Bm, ldb, C, ldc, K, blockIdx.y * TBM, blockIdx.x * TBN, a_s, b_s);
}

// Fused smooth projections: x<8 -> q = zm@FQ; 8,9 -> kraw = zm@FK; 10,11 -> v = x@v_w.
__global__ __launch_bounds__(256, 2)
void proj_fused(const float* __restrict__ x, const float* __restrict__ v_w)
{
    __shared__ __align__(16) uint32_t a_s[TBM * TAPAD];
    __shared__ __align__(16) uint32_t b_s[TBK * TBPAD];
    const float* A;
    const float* Bm;
    float* C;
    int ldb, ldc, bn;
    int bx = blockIdx.x;
    if (bx < 8) {
        A = g_scratch + OFF_ZM; Bm = g_scratch + OFF_FQ; C = g_scratch + OFF_Q;
        ldb = 1024; ldc = 1024; bn = bx * TBN;
    } else if (bx < 10) {
        A = g_scratch + OFF_ZM; Bm = g_scratch + OFF_FK; C = g_scratch + OFF_KRAW;
        ldb = 256;  ldc = 256;  bn = (bx - 8) * TBN;
    } else {
        A = x;                  Bm = v_w;               C = g_scratch + OFF_V;
        ldb = 256;  ldc = 256;  bn = (bx - 10) * TBN;
    }
    gemm_tf32_tile(A, 1024, Bm, ldb, C, ldc, 1024, blockIdx.y * TBM, bn, a_s, b_s);
}

// =====================================================================
// Pre-split: hi = rna_tf32(v), lo = rna_tf32(v - hi), stored as u32 bits.
// =====================================================================
__global__ void presplit(const float* __restrict__ src,
                         uint32_t* __restrict__ hi, uint32_t* __restrict__ lo)
{
    int g = (blockIdx.x * 256 + threadIdx.x) * 4;
    float4 v = *(const float4*)(src + g);
    uint4 h = cvt4(v);
    uint4 l = make_uint4(
        f2tf32(v.x - __uint_as_float(h.x)),
        f2tf32(v.y - __uint_as_float(h.y)),
        f2tf32(v.z - __uint_as_float(h.z)),
        f2tf32(v.w - __uint_as_float(h.w)));
    *(uint4*)(hi + g) = h;
    *(uint4*)(lo + g) = l;
}

// =====================================================================
// fold_qw merged with fold_small
// =====================================================================
__global__ void fold_qw2(const float* __restrict__ qw, const float* __restrict__ kw,
                         const float* __restrict__ Aq, const float* __restrict__ Bq,
                         const float* __restrict__ Ak, const float* __restrict__ Bk,
                         const float* __restrict__ rand_gate)
{
    __shared__ float qr[1024];
    __shared__ float kr[256];
    __shared__ float wq_s[4096];
    __shared__ float wk_s[4096];
    int d = blockIdx.x;
    int tid = threadIdx.x;
#pragma unroll
    for (int t = 0; t < 16; t++) {
        int ij = tid + t * 256;
        int i = ij >> 6, j = ij & 63;
        float sq = 0.f, sk = 0.f;
#pragma unroll
        for (int r = 0; r < 16; r++) {
            sq += Aq[i * 16 + r] * Bq[r * 64 + j];
            sk += Ak[i * 16 + r] * Bk[r * 64 + j];
        }
        wq_s[ij] = sq;
        wk_s[ij] = sk;
    }
    for (int i = tid; i < 1024; i += 256) qr[i] = qw[(size_t)d * 1024 + i];
    if (tid < 256) kr[tid] = kw[(size_t)d * 256 + tid];
    __syncthreads();
    for (int c = tid; c < 1024; c += 256) {
        int h = c >> 6, j = c & 63;
        float s = 0.f;
#pragma unroll
        for (int i = 0; i < 64; i++) s += qr[h * 64 + i] * wq_s[i * 64 + j];
        g_scratch[OFF_QWP + (size_t)d * 1024 + c] = s;
    }
    {
        int c = tid;
        int g = c >> 6, j = c & 63;
        float s = 0.f;
#pragma unroll
        for (int i = 0; i < 64; i++) s += kr[g * 64 + i] * wk_s[i * 64 + j];
        g_scratch[OFF_KWP + (size_t)d * 256 + c] = s * tanhf(1.f + rand_gate[j]);
    }
}

// =====================================================================
// fold_base body (fp32 exact — sign-critical)
// =====================================================================
__device__ __forceinline__
void fold_base_row(const float* __restrict__ ge_out_w,
                   const float* __restrict__ base_w, int i, float* red)
{
    int tid = threadIdx.x;
    const float* a = ge_out_w + (size_t)i * 2048;
    int h = tid & 7, ck = tid >> 3;
    const float4* a4 = (const float4*)(a + ck * 32);
    float p = 0.f;
#pragma unroll
    for (int q4 = 0; q4 < 8; q4++) {
        float4 v = a4[q4];
        const float* bw = base_w + (ck * 32 + q4 * 4) * 8 + h;
        p += v.x * bw[0] + v.y * bw[8] + v.z * bw[16] + v.w * bw[24];
    }
    red[tid] = p;
    __syncthreads();
    if (tid < 8) {
        float s = 0.f;
        for (int c2 = 0; c2 < 32; c2++) s += red[c2 * 8 + tid];
        g_scratch[OFF_FBASE + (size_t)i * 8 + tid] = s;
    }
    __syncthreads();
}

// =====================================================================
// Fused big kernel — z=0: zfull 3xtf32 cp.async GEMM, 128x128 tiles,
// TBK=16 so 2 stages fit in 74.8 KB -> 2 CTAs/SM with double buffering.
// z=1: fold GEMMs + fold_base on the mma.sync path (dynamic smem reuse).
// Stage (u32): Ah[0,2560) Al[2560,5120) Bh[5120,7232) Bl[7232,9344).
// A rows pad 20 (80B stride: ldmatrix conflict-free), B rows pad 132.
// k-sequencing identical to R12/R13 -> bitwise-identical results.
// =====================================================================
#define XTBK 16
#define XTAP 20
#define XBPD 132
#define XA_SZ (128 * XTAP)          // 2560
#define XB_SZ (XTBK * XBPD)         // 2112
#define X_STAGE (2 * XA_SZ + 2 * XB_SZ)   // 9344 u32
#define SMEM_X (2 * X_STAGE * 4)    // 74752 B

__global__ __launch_bounds__(256, 2)
void zfull_folds(const uint32_t* __restrict__ Ahg, const uint32_t* __restrict__ Alg,
                 const uint32_t* __restrict__ Bhg, const uint32_t* __restrict__ Blg,
                 float* __restrict__ C,
                 const float* __restrict__ geo, const float* __restrict__ base_w)
{
    extern __shared__ __align__(16) uint32_t smu[];

    if (blockIdx.z == 1) {
        int f = blockIdx.y * 16 + blockIdx.x;     // 0..1023
        if (f < 64) {
            gemm_tf32_tile(geo, 2048, g_scratch + OFF_QWP, 1024,
                           g_scratch + OFF_FQ, 1024, 1024, (f >> 3) * TBM, (f & 7) * TBN,
                           smu, smu + TBM * TAPAD);
        } else if (f < 80) {
            int g = f - 64;
            gemm_tf32_tile(geo + 1024, 2048, g_scratch + OFF_KWP, 256,
                           g_scratch + OFF_FK, 256, 1024, (g >> 1) * TBM, (g & 1) * TBN,
                           smu, smu + TBM * TAPAD);
        } else if (f < 592) {
            __shared__ float red[256];
            int i0 = (f - 80) * 2;
            fold_base_row(geo, base_w, i0, red);
            fold_base_row(geo, base_w, i0 + 1, red);
        }
        return;
    }

    // ---- z == 0: zfull 3xtf32, 128x128 tile, TBK=16, occ 2 ----
    const int tid = threadIdx.x;
    const int warp = tid >> 5, lane = tid & 31;
    const int wm = (warp >> 2) * 64, wn = (warp & 3) * 32;
    const int bm = blockIdx.y * TBM, bn = blockIdx.x * TBN;
    const int lq = lane >> 2, lr = lane & 3;

    const uint32_t smem_base = smem_u32(smu);
    const uint32_t lm_off =
        (((wm + (lane & 7) + ((lane >> 3) & 1) * 8) * XTAP + (lane >> 4) * 4) << 2);

    float acc[4][4][4];
#pragma unroll
    for (int i = 0; i < 4; i++)
#pragma unroll
        for (int j = 0; j < 4; j++)
#pragma unroll
            for (int k = 0; k < 4; k++) acc[i][j][k] = 0.f;

    // per-chunk loader: A 512 granules (2/thread) x {h,l}, B 512 granules x {h,l}
    auto issue_chunk = [&](int kt, int stage) {
        uint32_t sb = smem_base + stage * (X_STAGE * 4);
#pragma unroll
        for (int u = 0; u < 2; u++) {
            int id = tid + u * 256;
            int r  = id >> 2;                  // 0..127
            int kc = (id & 3) << 2;            // 0,4,8,12
            size_t asrc = (size_t)(bm + r) * 1024 + kt + kc;
            uint32_t ad = sb + ((r * XTAP + kc) << 2);
            cpa16(ad, Ahg + asrc);
            cpa16(ad + (XA_SZ << 2), Alg + asrc);
            int rb = id >> 5;                  // 0..15
            int nc = (id & 31) << 2;           // 0..124
            size_t bsrc = (size_t)(kt + rb) * 2048 + bn + nc;
            uint32_t bd = sb + ((2 * XA_SZ + rb * XBPD + nc) << 2);
            cpa16(bd, Bhg + bsrc);
            cpa16(bd + (XB_SZ << 2), Blg + bsrc);
        }
        asm volatile("cp.async.commit_group;" ::: "memory");
    };

    const int nk = 1024 / XTBK;   // 64
    issue_chunk(0, 0);

    for (int t = 0; t < nk; t++) {
        if (t + 1 < nk) {
            issue_chunk((t + 1) * XTBK, (t + 1) & 1);
            asm volatile("cp.async.wait_group 1;" ::: "memory");
        } else {
            asm volatile("cp.async.wait_group 0;" ::: "memory");
        }
        __syncthreads();

        const uint32_t* st = smu + (t & 1) * X_STAGE;
        const uint32_t* Bh = st + 2 * XA_SZ;
        const uint32_t* Bl = st + 2 * XA_SZ + XB_SZ;
        const uint32_t ah_base = smem_base + (t & 1) * (X_STAGE * 4) + lm_off;
        const uint32_t al_base = ah_base + (XA_SZ << 2);

#pragma unroll
        for (int kk = 0; kk < XTBK; kk += 8) {
            uint32_t ah[4][4], al[4][4], bh[4][2], bl[4][2];
#pragma unroll
            for (int mt = 0; mt < 4; mt++) {
                uint32_t off = (mt * 16 * XTAP + kk) << 2;
                ldsm_x4(ah[mt], ah_base + off);
                ldsm_x4(al[mt], al_base + off);
            }
#pragma unroll
            for (int nt = 0; nt < 4; nt++) {
                int cc = wn + nt * 8 + lq;
                bh[nt][0] = Bh[(kk + lr) * XBPD + cc];
                bh[nt][1] = Bh[(kk + lr + 4) * XBPD + cc];
                bl[nt][0] = Bl[(kk + lr) * XBPD + cc];
                bl[nt][1] = Bl[(kk + lr + 4) * XBPD + cc];
            }
#pragma unroll
            for (int mt = 0; mt < 4; mt++)
#pragma unroll
                for (int nt = 0; nt < 4; nt++) {
                    mma_tf32(acc[mt][nt], al[mt], bh[nt]);
                    mma_tf32(acc[mt][nt], ah[mt], bl[nt]);
                    mma_tf32(acc[mt][nt], ah[mt], bh[nt]);
                }
        }
        __syncthreads();
    }

#pragma unroll
    for (int mt = 0; mt < 4; mt++) {
#pragma unroll
        for (int nt = 0; nt < 4; nt++) {
            int row = bm + wm + mt * 16 + lq;
            int col = bn + wn + nt * 8 + 2 * lr;
            *(float2*)(C + (size_t)row * 2048 + col) =
                make_float2(acc[mt][nt][0], acc[mt][nt][1]);
            *(float2*)(C + (size_t)(row + 8) * 2048 + col) =
                make_float2(acc[mt][nt][2], acc[mt][nt][3]);
        }
    }
}

// =====================================================================
// Fused conv + SiLU*SiLU + LSH hash: one block per token row.
// =====================================================================
__global__ __launch_bounds__(256)
void conv_hash(const float* __restrict__ dw_w, const float* __restrict__ dw_b,
               const float* __restrict__ rot, const int* __restrict__ salts)
{
    __shared__ float zm_s[1024];
    __shared__ float red[256];
    __shared__ float base_s[8];
    int row = blockIdx.x;
    int n = row & (NSEQ - 1);
    int tid = threadIdx.x;
    const float* zr = g_scratch + OFF_ZFULL + (size_t)row * 2048;
    float* zmg = g_scratch + OFF_ZM + (size_t)row * 1024;

#pragma unroll
    for (int t = 0; t < 4; t++) {
        int d = tid + t * 256;
        float z0 = (n > 0)        ? zr[-2048 + d] : 0.f;
        float z1 = zr[d];
        float z2 = (n < NSEQ - 1) ? zr[2048 + d] : 0.f;
        float c = z0 * dw_w[d * 3 + 0] + z1 * dw_w[d * 3 + 1] + z2 * dw_w[d * 3 + 2] + dw_b[d];
        float g = zr[1024 + d];
        float sc = c / (1.f + expf(-c));
        float sg = g / (1.f + expf(-g));
        float v = sc * sg;
        zm_s[d] = v;
        zmg[d] = v;
    }
    __syncthreads();

    const float* fb = g_scratch + OFF_FBASE;
    int h = tid & 7, ck = tid >> 3;
    float p = 0.f;
    const float* zp = zm_s + ck * 32;
#pragma unroll
    for (int dd = 0; dd < 32; dd++) p += zp[dd] * fb[(ck * 32 + dd) * 8 + h];
    red[tid] = p;
    __syncthreads();
    if (tid < 8) {
        float s = 0.f;
        for (int c2 = 0; c2 < 32; c2++) s += red[c2 * 8 + tid];
        base_s[tid] = s;
    }
    __syncthreads();
    if (tid == 0) {
        int code = 0;
#pragma unroll
        for (int r = 0; r < 4; r++) {
            int ph = 0;
#pragma unroll
            for (int kk = 0; kk < 8; kk++) {
                float sim = 0.f;
#pragma unroll
                for (int hh = 0; hh < 8; hh++) sim += base_s[hh] * rot[r * 64 + hh * 8 + kk];
                if (sim >= 0.f) ph ^= salts[r * 8 + kk];
            }
            code ^= ph;
        }
        g_bucket[row] = code & (NBK - 1);
    }
}

// =====================================================================
// Haar mix over sequence pairs
// =====================================================================
__global__ void haar_kernel()
{
    int gid = blockIdx.x * 256 + threadIdx.x;
    int ch = gid & 255;
    int t  = gid >> 8;
    int c  = t & 2047;
    int b  = t >> 11;
    const float* kr = g_scratch + OFF_KRAW;
    float x0 = kr[((size_t)(b * NSEQ + 2 * c)) * 256 + ch];
    float x1 = kr[((size_t)(b * NSEQ + 2 * c + 1)) * 256 + ch];
    float* kh = g_scratch + OFF_KH;
    kh[((size_t)(b * NSEQ + c)) * 256 + ch]        = 0.5f * (x0 + x1);
    kh[((size_t)(b * NSEQ + 2048 + c)) * 256 + ch] = 0.5f * (x0 - x1);
}

// =====================================================================
// Parallel stable counting sort per batch
// =====================================================================
__global__ void sort_kernel()
{
    int b = blockIdx.x;
    __shared__ int cnt[NBK][257];
    __shared__ int bbase[NBK];
    int tid = threadIdx.x;
#pragma unroll
    for (int bb = 0; bb < NBK; bb++) cnt[bb][tid] = 0;
    __syncthreads();
    const int* bk = g_bucket + b * NSEQ;
    int seg = tid * 16;
    int loc[16];
#pragma unroll
    for (int i = 0; i < 16; i++) {
        loc[i] = bk[seg + i];
        cnt[loc[i]][tid] += 1;
    }
    __syncthreads();
    if (tid < NBK) {
        int s = 0;
        for (int t = 0; t < 256; t++) { int v = cnt[tid][t]; cnt[tid][t] = s; s += v; }
        cnt[tid][256] = s;
    }
    __syncthreads();
    if (tid == 0) {
        int s = 0;
        for (int bb = 0; bb < NBK; bb++) { bbase[bb] = s; s += cnt[bb][256]; }
    }
    __syncthreads();
#pragma unroll
    for (int i = 0; i < 16; i++) {
        int bb = loc[i];
        int pos = bbase[bb] + cnt[bb][tid];
        cnt[bb][tid] = pos + 1 - bbase[bb];
        g_order[b * NSEQ + pos] = seg + i;
    }
}

// =====================================================================
// Tensor-core bucketed attention (proven R7)
// =====================================================================
#define AQ_PAD 72
#define AK_PAD 136
#define AV_PAD 72
#define AP_PAD 132
#define ATTN_SMEM ((128*AQ_PAD + 64*AK_PAD + 128*AV_PAD) * 4)

__global__ __launch_bounds__(256, 2)
void attn_tc()
{
    extern __shared__ __align__(16) uint32_t smw[];
    uint32_t* qs = smw;
    uint32_t* ks = smw + 128 * AQ_PAD;
    uint32_t* vs = smw + 128 * AQ_PAD + 64 * AK_PAD;
    uint32_t* ps = smw;
    __shared__ int idx_s[128];

    const int c = blockIdx.x, h = blockIdx.y, b = blockIdx.z;
    const int kvh = h >> 2;
    const int tid = threadIdx.x;
    const int warp = tid >> 5, lane = tid & 31;
    const int lq = lane >> 2, lr = lane & 3;
    const int m0 = warp * 16;

    if (tid < 128) idx_s[tid] = g_order[b * NSEQ + c * BUCK + tid];
    __syncthreads();

    const float* gq = g_scratch + OFF_Q;
    const float* gk = g_scratch + OFF_KH;
    const float* gv = g_scratch + OFF_V;

    for (int e = tid; e < 128 * 16; e += 256) {
        int row = e >> 4;
        int c4  = (e & 15) << 2;
        size_t grow = (size_t)(b * NSEQ + idx_s[row]);
        float4 qv = *(const float4*)(gq + grow * 1024 + h * 64 + c4);
        *(uint4*)(qs + row * AQ_PAD + c4) = cvt4(qv);
        float4 kv = *(const float4*)(gk + grow * 256 + kvh * 64 + c4);
        ks[(c4 + 0) * AK_PAD + row] = f2tf32(kv.x);
        ks[(c4 + 1) * AK_PAD + row] = f2tf32(kv.y);
        ks[(c4 + 2) * AK_PAD + row] = f2tf32(kv.z);
        ks[(c4 + 3) * AK_PAD + row] = f2tf32(kv.w);
        float4 vv = *(const float4*)(gv + grow * 256 + kvh * 64 + c4);
        *(uint4*)(vs + row * AV_PAD + c4) = cvt4(vv);
    }
    __syncthreads();

    float acc[16][4];
#pragma unroll
    for (int nt = 0; nt < 16; nt++)
#pragma unroll
        for (int k2 = 0; k2 < 4; k2++) acc[nt][k2] = 0.f;

    const uint32_t lm_row = (uint32_t)(m0 + (lane & 7) + ((lane >> 3) & 1) * 8);
    const uint32_t q_base = smem_u32(qs) + ((lm_row * AQ_PAD + (lane >> 4) * 4) << 2);
#pragma unroll
    for (int kk = 0; kk < 64; kk += 8) {
        uint32_t a[4];
        ldsm_x4(a, q_base + (kk << 2));
#pragma unroll
        for (int nt = 0; nt < 16; nt++) {
            uint32_t bf[2];
            bf[0] = ks[(kk + lr) * AK_PAD + nt * 8 + lq];
            bf[1] = ks[(kk + lr + 4) * AK_PAD + nt * 8 + lq];
            mma_tf32(acc[nt], a, bf);
        }
    }

    float mx0 = -1e30f, mx1 = -1e30f;
#pragma unroll
    for (int nt = 0; nt < 16; nt++) {
        mx0 = fmaxf(mx0, fmaxf(acc[nt][0], acc[nt][1]));
        mx1 = fmaxf(mx1, fmaxf(acc[nt][2], acc[nt][3]));
    }
    mx0 = fmaxf(mx0, __shfl_xor_sync(0xffffffffu, mx0, 1));
    mx0 = fmaxf(mx0, __shfl_xor_sync(0xffffffffu, mx0, 2));
    mx1 = fmaxf(mx1, __shfl_xor_sync(0xffffffffu, mx1, 1));
    mx1 = fmaxf(mx1, __shfl_xor_sync(0xffffffffu, mx1, 2));
    float s0 = 0.f, s1 = 0.f;
#pragma unroll
    for (int nt = 0; nt < 16; nt++) {
        acc[nt][0] = __expf((acc[nt][0] - mx0) * 0.125f);
        acc[nt][1] = __expf((acc[nt][1] - mx0) * 0.125f);
        acc[nt][2] = __expf((acc[nt][2] - mx1) * 0.125f);
        acc[nt][3] = __expf((acc[nt][3] - mx1) * 0.125f);
        s0 += acc[nt][0] + acc[nt][1];
        s1 += acc[nt][2] + acc[nt][3];
    }
    s0 += __shfl_xor_sync(0xffffffffu, s0, 1);
    s0 += __shfl_xor_sync(0xffffffffu, s0, 2);
    s1 += __shfl_xor_sync(0xffffffffu, s1, 1);
    s1 += __shfl_xor_sync(0xffffffffu, s1, 2);
    const float r0 = 1.f / s0, r1 = 1.f / s1;

    __syncthreads();

#pragma unroll
    for (int nt = 0; nt < 16; nt++) {
        *(uint2*)(ps + (m0 + lq) * AP_PAD + nt * 8 + 2 * lr) =
            make_uint2(f2tf32(acc[nt][0] * r0), f2tf32(acc[nt][1] * r0));
        *(uint2*)(ps + (m0 + lq + 8) * AP_PAD + nt * 8 + 2 * lr) =
            make_uint2(f2tf32(acc[nt][2] * r1), f2tf32(acc[nt][3] * r1));
    }
    __syncwarp();

    float o[8][4];
#pragma unroll
    for (int nt = 0; nt < 8; nt++)
#pragma unroll
        for (int k2 = 0; k2 < 4; k2++) o[nt][k2] = 0.f;

    const uint32_t p_base = smem_u32(ps) + ((lm_row * AP_PAD + (lane >> 4) * 4) << 2);
#pragma unroll
    for (int kk = 0; kk < 128; kk += 8) {
        uint32_t a[4];
        ldsm_x4(a, p_base + (kk << 2));
#pragma unroll
        for (int nt = 0; nt < 8; nt++) {
            uint32_t bf[2];
            bf[0] = vs[(kk + lr) * AV_PAD + nt * 8 + lq];
            bf[1] = vs[(kk + lr + 4) * AV_PAD + nt * 8 + lq];
            mma_tf32(o[nt], a, bf);
        }
    }

    float* ga = g_scratch + OFF_ATT;
    size_t g0 = (size_t)(b * NSEQ + idx_s[m0 + lq]);
    size_t g1 = (size_t)(b * NSEQ + idx_s[m0 + lq + 8]);
#pragma unroll
    for (int nt = 0; nt < 8; nt++) {
        *(float2*)(ga + g0 * 1024 + h * 64 + nt * 8 + 2 * lr) =
            make_float2(o[nt][0], o[nt][1]);
        *(float2*)(ga + g1 * 1024 + h * 64 + nt * 8 + 2 * lr) =
            make_float2(o[nt][2], o[nt][3]);
    }
}

// =====================================================================
// Host launcher
// =====================================================================
extern "C" void kernel_launch(void* const* d_in, const int* in_sizes, int n_in,
                              void* d_out, int out_size)
{
    const float* x         = (const float*)d_in[0];
    const float* ge_inp_w  = (const float*)d_in[1];
    const float* dw_w      = (const float*)d_in[2];
    const float* dw_b      = (const float*)d_in[3];
    const float* ge_out_w  = (const float*)d_in[4];
    const float* q_w       = (const float*)d_in[5];
    const float* k_w       = (const float*)d_in[6];
    const float* v_w       = (const float*)d_in[7];
    const float* Aq        = (const float*)d_in[8];
    const float* Bq        = (const float*)d_in[9];
    const float* Ak        = (const float*)d_in[10];
    const float* Bk        = (const float*)d_in[11];
    const float* rand_gate = (const float*)d_in[12];
    const float* base_w    = (const float*)d_in[13];
    const float* rot       = (const float*)d_in[14];
    const float* o_w       = (const float*)d_in[16];
    const int*   salts     = (const int*)d_in[17];
    float* out = (float*)d_out;

    float* sc = nullptr;
    cudaGetSymbolAddress((void**)&sc, g_scratch);
    uint32_t* xh  = (uint32_t*)(sc + OFF_XH);
    uint32_t* xl  = (uint32_t*)(sc + OFF_XL);
    uint32_t* gwh = (uint32_t*)(sc + OFF_GWH);
    uint32_t* gwl = (uint32_t*)(sc + OFF_GWL);

    cudaFuncSetAttribute(attn_tc, cudaFuncAttributeMaxDynamicSharedMemorySize, ATTN_SMEM);
    cudaFuncSetAttribute(zfull_folds, cudaFuncAttributeMaxDynamicSharedMemorySize, SMEM_X);

    // pre-split x3 operands + per-channel fold
    presplit<<<8192, 256>>>(x, xh, xl);
    presplit<<<2048, 256>>>(ge_inp_w, gwh, gwl);
    fold_qw2<<<1024, 256>>>(q_w, k_w, Aq, Bq, Ak, Bk, rand_gate);

    // zfull (3xtf32, 128x128 tiles, TBK=16, occ 2) with folds in the z=1 plane
    zfull_folds<<<dim3(16, 64, 2), 256, SMEM_X>>>(xh, xl, gwh, gwl,
                                                  sc + OFF_ZFULL, ge_out_w, base_w);

    // conv + silu + hash fused
    conv_hash<<<MROWS, 256>>>(dw_w, dw_b, rot, salts);
    sort_kernel<<<BB, 256>>>();

    // smooth projections fused (q, kraw, v)
    proj_fused<<<dim3(12, 64), 256>>>(x, v_w);

    haar_kernel<<<(BB * 2048 * 256) / 256, 256>>>();

    attn_tc<<<dim3(NBK, HH, BB), 256, ATTN_SMEM>>>();

    // out = att @ o_w (tf32 mma.sync)
    gemm_tf32<<<dim3(8, 64), 256>>>(sc + OFF_ATT, 1024, o_w, 1024, out, 1024, 1024);
}